// round 1
// baseline (speedup 1.0000x reference)
#include <cuda_runtime.h>
#include <math.h>

#define S_LEN  4096
#define DMODEL 1024
#define NHEADS 16
#define DK     64

// ---- scratch (allocation-free rule: __device__ globals) ----
__device__ float g_q[(size_t)S_LEN * DMODEL];
__device__ float g_k[(size_t)S_LEN * DMODEL];
__device__ float g_v[(size_t)S_LEN * DMODEL];
__device__ float g_ctx[(size_t)S_LEN * DMODEL];

// =====================================================================
// GEMM:  C[M,N] = A[M,K] @ B[K,N] + bias[N]      (all row-major fp32)
// 128x128 tile, BK=8, 256 threads, 8x8 per thread.
// =====================================================================
#define GBM 128
#define GBN 128
#define GBK 8

__global__ __launch_bounds__(256)
void gemm_bias_kernel(const float* __restrict__ A,
                      const float* __restrict__ B,
                      const float* __restrict__ bias,
                      float* __restrict__ C,
                      int M, int N, int K)
{
    __shared__ float As[GBK][GBM];   // A tile, transposed: As[k][m]
    __shared__ float Bs[GBK][GBN];   // B tile natural:     Bs[k][n]

    const int tid = threadIdx.x;
    const int tx  = tid & 15;        // n-dim thread coord (16)
    const int ty  = tid >> 4;        // m-dim thread coord (16)
    const int bm  = blockIdx.y * GBM;
    const int bn  = blockIdx.x * GBN;

    // A-tile load mapping: 128x8 = 1024 floats, float4 per thread
    const int arow = tid >> 1;            // 0..127
    const int acol = (tid & 1) << 2;      // 0 or 4
    // B-tile load mapping: 8x128 = 1024 floats, float4 per thread
    const int brow = tid >> 5;            // 0..7
    const int bcol = (tid & 31) << 2;     // 0..124

    const float* Ap = A + (size_t)(bm + arow) * K + acol;
    const float* Bp = B + (size_t)brow * N + bn + bcol;

    float acc[8][8];
    #pragma unroll
    for (int i = 0; i < 8; i++)
        #pragma unroll
        for (int j = 0; j < 8; j++) acc[i][j] = 0.f;

    for (int k0 = 0; k0 < K; k0 += GBK) {
        const float4 av = *(const float4*)(Ap + k0);
        const float4 bv = *(const float4*)(Bp + (size_t)k0 * N);
        As[acol + 0][arow] = av.x;
        As[acol + 1][arow] = av.y;
        As[acol + 2][arow] = av.z;
        As[acol + 3][arow] = av.w;
        *(float4*)&Bs[brow][bcol] = bv;
        __syncthreads();

        #pragma unroll
        for (int kk = 0; kk < GBK; kk++) {
            float a[8], b[8];
            *(float4*)&a[0] = *(const float4*)&As[kk][ty * 8];
            *(float4*)&a[4] = *(const float4*)&As[kk][ty * 8 + 4];
            *(float4*)&b[0] = *(const float4*)&Bs[kk][tx * 8];
            *(float4*)&b[4] = *(const float4*)&Bs[kk][tx * 8 + 4];
            #pragma unroll
            for (int i = 0; i < 8; i++)
                #pragma unroll
                for (int j = 0; j < 8; j++)
                    acc[i][j] = fmaf(a[i], b[j], acc[i][j]);
        }
        __syncthreads();
    }

    // epilogue: add bias, vectorized store
    #pragma unroll
    for (int i = 0; i < 8; i++) {
        const int m = bm + ty * 8 + i;
        float* crow = C + (size_t)m * N + bn + tx * 8;
        const float* brow_ = bias + bn + tx * 8;
        float4 c0, c1;
        c0.x = acc[i][0] + brow_[0];
        c0.y = acc[i][1] + brow_[1];
        c0.z = acc[i][2] + brow_[2];
        c0.w = acc[i][3] + brow_[3];
        c1.x = acc[i][4] + brow_[4];
        c1.y = acc[i][5] + brow_[5];
        c1.z = acc[i][6] + brow_[6];
        c1.w = acc[i][7] + brow_[7];
        *(float4*)(crow)     = c0;
        *(float4*)(crow + 4) = c1;
    }
}

// =====================================================================
// Flash attention (causal), fp32.
// One CTA = (head h, 128-query tile). 256 threads (16x16), iterates over
// key tiles of 128 up to the diagonal. Online softmax. P staged via smem.
//   smem: QsT[64][132] (Q^T), KsT[64][132] (K^T), Vs[128][68], Ps[128][130]
// =====================================================================
#define BQ  128
#define BKV 128
#define STQ 132
#define STK 132
#define STV 68
#define STP 130
#define ATT_SMEM_FLOATS (DK*STQ + DK*STK + BKV*STV + BQ*STP)
#define ATT_SMEM_BYTES  (ATT_SMEM_FLOATS * 4)

__global__ __launch_bounds__(256)
void attn_kernel()
{
    extern __shared__ float sm[];
    float* QsT = sm;
    float* KsT = QsT + DK * STQ;
    float* Vs  = KsT + DK * STK;
    float* Ps  = Vs  + BKV * STV;

    const int tid = threadIdx.x;
    const int tx  = tid & 15;
    const int ty  = tid >> 4;
    const int h   = blockIdx.y;
    // heaviest query tiles (largest qt) scheduled first
    const int qt  = (int)gridDim.x - 1 - (int)blockIdx.x;
    const int q0  = qt * BQ;
    const int hoff = h * DK;

    // ---- load Q tile, transposed into QsT[d][q] ----
    {
        const int lq  = tid >> 4;            // 0..15 (query within group)
        const int ld0 = (tid & 15) << 2;     // 0..60 (d, float4)
        #pragma unroll
        for (int it = 0; it < BQ / 16; it++) {
            const int q = lq + it * 16;
            const float4 v = *(const float4*)(g_q + (size_t)(q0 + q) * DMODEL + hoff + ld0);
            QsT[(ld0 + 0) * STQ + q] = v.x;
            QsT[(ld0 + 1) * STQ + q] = v.y;
            QsT[(ld0 + 2) * STQ + q] = v.z;
            QsT[(ld0 + 3) * STQ + q] = v.w;
        }
    }

    float m[8], l[8], o[8][4];
    #pragma unroll
    for (int i = 0; i < 8; i++) {
        m[i] = -1e30f;
        l[i] = 0.f;
        #pragma unroll
        for (int j = 0; j < 4; j++) o[i][j] = 0.f;
    }

    for (int kt = 0; kt <= qt; kt++) {
        const int k0 = kt * BKV;
        __syncthreads();   // protect KsT/Vs/Ps from prior iteration readers

        // ---- load K tile (transposed) + V tile (natural) ----
        {
            const int lr  = tid >> 4;
            const int ld0 = (tid & 15) << 2;
            #pragma unroll
            for (int it = 0; it < BKV / 16; it++) {
                const int kr = lr + it * 16;
                const float4 kv = *(const float4*)(g_k + (size_t)(k0 + kr) * DMODEL + hoff + ld0);
                KsT[(ld0 + 0) * STK + kr] = kv.x;
                KsT[(ld0 + 1) * STK + kr] = kv.y;
                KsT[(ld0 + 2) * STK + kr] = kv.z;
                KsT[(ld0 + 3) * STK + kr] = kv.w;
                const float4 vv = *(const float4*)(g_v + (size_t)(k0 + kr) * DMODEL + hoff + ld0);
                *(float4*)(Vs + kr * STV + ld0) = vv;
            }
        }
        __syncthreads();

        // ---- S = Q @ K^T  (per-thread 8x8 over [q, key]) ----
        float s[8][8];
        #pragma unroll
        for (int i = 0; i < 8; i++)
            #pragma unroll
            for (int j = 0; j < 8; j++) s[i][j] = 0.f;

        #pragma unroll 4
        for (int kk = 0; kk < DK; kk++) {
            float a[8], b[8];
            *(float4*)&a[0] = *(const float4*)(QsT + kk * STQ + ty * 8);
            *(float4*)&a[4] = *(const float4*)(QsT + kk * STQ + ty * 8 + 4);
            *(float4*)&b[0] = *(const float4*)(KsT + kk * STK + tx * 8);
            *(float4*)&b[4] = *(const float4*)(KsT + kk * STK + tx * 8 + 4);
            #pragma unroll
            for (int i = 0; i < 8; i++)
                #pragma unroll
                for (int j = 0; j < 8; j++)
                    s[i][j] = fmaf(a[i], b[j], s[i][j]);
        }

        // ---- scale (1/sqrt(64)) + causal mask on diagonal tile ----
        if (kt == qt) {
            #pragma unroll
            for (int i = 0; i < 8; i++) {
                const int qrow = ty * 8 + i;
                #pragma unroll
                for (int j = 0; j < 8; j++) {
                    const int kcol = tx * 8 + j;
                    s[i][j] = (kcol <= qrow) ? s[i][j] * 0.125f : -1e30f;
                }
            }
        } else {
            #pragma unroll
            for (int i = 0; i < 8; i++)
                #pragma unroll
                for (int j = 0; j < 8; j++) s[i][j] *= 0.125f;
        }

        // ---- online softmax (row spread across the 16 tx lanes = half-warp) ----
        #pragma unroll
        for (int i = 0; i < 8; i++) {
            float rmax = s[i][0];
            #pragma unroll
            for (int j = 1; j < 8; j++) rmax = fmaxf(rmax, s[i][j]);
            #pragma unroll
            for (int off = 8; off >= 1; off >>= 1)
                rmax = fmaxf(rmax, __shfl_xor_sync(0xffffffffu, rmax, off));

            const float mn    = fmaxf(m[i], rmax);
            const float alpha = __expf(m[i] - mn);
            float rsum = 0.f;
            #pragma unroll
            for (int j = 0; j < 8; j++) {
                const float p = __expf(s[i][j] - mn);
                s[i][j] = p;
                rsum += p;
            }
            #pragma unroll
            for (int off = 8; off >= 1; off >>= 1)
                rsum += __shfl_xor_sync(0xffffffffu, rsum, off);

            l[i] = l[i] * alpha + rsum;
            m[i] = mn;
            #pragma unroll
            for (int jd = 0; jd < 4; jd++) o[i][jd] *= alpha;
        }

        // ---- stage P into smem ----
        #pragma unroll
        for (int i = 0; i < 8; i++) {
            float* pr = Ps + (ty * 8 + i) * STP + tx * 8;
            #pragma unroll
            for (int j = 0; j < 8; j++) pr[j] = s[i][j];
        }
        __syncthreads();

        // ---- O += P @ V   (per-thread 8 rows x 4 d-cols; tx indexes d now) ----
        #pragma unroll 4
        for (int kk = 0; kk < BKV; kk++) {
            float a[8];
            #pragma unroll
            for (int i = 0; i < 8; i++) a[i] = Ps[(ty * 8 + i) * STP + kk];
            const float4 bv = *(const float4*)(Vs + kk * STV + tx * 4);
            #pragma unroll
            for (int i = 0; i < 8; i++) {
                o[i][0] = fmaf(a[i], bv.x, o[i][0]);
                o[i][1] = fmaf(a[i], bv.y, o[i][1]);
                o[i][2] = fmaf(a[i], bv.z, o[i][2]);
                o[i][3] = fmaf(a[i], bv.w, o[i][3]);
            }
        }
    }

    // ---- epilogue: normalize, write ctx[token][h*64 + d] ----
    #pragma unroll
    for (int i = 0; i < 8; i++) {
        const float inv = 1.f / l[i];
        float4 r;
        r.x = o[i][0] * inv;
        r.y = o[i][1] * inv;
        r.z = o[i][2] * inv;
        r.w = o[i][3] * inv;
        *(float4*)(g_ctx + (size_t)(q0 + ty * 8 + i) * DMODEL + hoff + tx * 4) = r;
    }
}

// =====================================================================
// Host launcher
// Inputs (metadata order): x, mask, Wq_w, Wq_b, Wk_w, Wk_b, Wv_w, Wv_b,
//                          Wo_w, Wo_b.  mask is implied causal -> unused.
// =====================================================================
extern "C" void kernel_launch(void* const* d_in, const int* in_sizes, int n_in,
                              void* d_out, int out_size)
{
    (void)in_sizes; (void)n_in; (void)out_size;
    const float* x  = (const float*)d_in[0];
    const float* Wq = (const float*)d_in[2];
    const float* bq = (const float*)d_in[3];
    const float* Wk = (const float*)d_in[4];
    const float* bk = (const float*)d_in[5];
    const float* Wv = (const float*)d_in[6];
    const float* bv = (const float*)d_in[7];
    const float* Wo = (const float*)d_in[8];
    const float* bo = (const float*)d_in[9];
    float* out = (float*)d_out;

    float *qp, *kp, *vp, *cp;
    cudaGetSymbolAddress((void**)&qp, g_q);
    cudaGetSymbolAddress((void**)&kp, g_k);
    cudaGetSymbolAddress((void**)&vp, g_v);
    cudaGetSymbolAddress((void**)&cp, g_ctx);

    const dim3 ggrid(DMODEL / GBN, S_LEN / GBM);

    gemm_bias_kernel<<<ggrid, 256>>>(x, Wq, bq, qp, S_LEN, DMODEL, DMODEL);
    gemm_bias_kernel<<<ggrid, 256>>>(x, Wk, bk, kp, S_LEN, DMODEL, DMODEL);
    gemm_bias_kernel<<<ggrid, 256>>>(x, Wv, bv, vp, S_LEN, DMODEL, DMODEL);

    cudaFuncSetAttribute(attn_kernel,
                         cudaFuncAttributeMaxDynamicSharedMemorySize,
                         ATT_SMEM_BYTES);
    attn_kernel<<<dim3(S_LEN / BQ, NHEADS), 256, ATT_SMEM_BYTES>>>();

    gemm_bias_kernel<<<ggrid, 256>>>(cp, Wo, bo, out, S_LEN, DMODEL, DMODEL);
}

// round 3
// speedup vs baseline: 1.3085x; 1.3085x over previous
#include <cuda_runtime.h>
#include <cuda_bf16.h>
#include <cstdint>
#include <math.h>

#define S_LEN  4096
#define DMODEL 1024
#define NHEADS 16
#define DK     64

// ======================= scratch (device globals) =======================
__device__ float g_q[(size_t)S_LEN * DMODEL];
__device__ float g_k[(size_t)S_LEN * DMODEL];
__device__ float g_v[(size_t)S_LEN * DMODEL];

__device__ __nv_bfloat16 g_xh[(size_t)S_LEN * DMODEL];
__device__ __nv_bfloat16 g_xl[(size_t)S_LEN * DMODEL];
__device__ __nv_bfloat16 g_ch[(size_t)S_LEN * DMODEL];
__device__ __nv_bfloat16 g_cl[(size_t)S_LEN * DMODEL];

__device__ __nv_bfloat16 g_wqh[(size_t)DMODEL * DMODEL];
__device__ __nv_bfloat16 g_wql[(size_t)DMODEL * DMODEL];
__device__ __nv_bfloat16 g_wkh[(size_t)DMODEL * DMODEL];
__device__ __nv_bfloat16 g_wkl[(size_t)DMODEL * DMODEL];
__device__ __nv_bfloat16 g_wvh[(size_t)DMODEL * DMODEL];
__device__ __nv_bfloat16 g_wvl[(size_t)DMODEL * DMODEL];
__device__ __nv_bfloat16 g_woh[(size_t)DMODEL * DMODEL];
__device__ __nv_bfloat16 g_wol[(size_t)DMODEL * DMODEL];

// ======================= helpers =======================
__device__ __forceinline__ uint32_t smem_u32(const void* p) {
    uint32_t a;
    asm("{ .reg .u64 t; cvta.to.shared.u64 t, %1; cvt.u32.u64 %0, t; }" : "=r"(a) : "l"(p));
    return a;
}

__device__ __forceinline__ void cp16(uint32_t saddr, const void* g) {
    asm volatile("cp.async.ca.shared.global [%0], [%1], 16;" :: "r"(saddr), "l"(g));
}
__device__ __forceinline__ void cp_commit() {
    asm volatile("cp.async.commit_group;");
}
__device__ __forceinline__ void cp_wait1() {
    asm volatile("cp.async.wait_group 1;");
}
__device__ __forceinline__ void cp_wait0() {
    asm volatile("cp.async.wait_group 0;");
}

__device__ __forceinline__ void ldsm_x4(uint32_t* r, uint32_t addr) {
    asm volatile("ldmatrix.sync.aligned.m8n8.x4.shared.b16 {%0,%1,%2,%3}, [%4];"
                 : "=r"(r[0]), "=r"(r[1]), "=r"(r[2]), "=r"(r[3]) : "r"(addr));
}

__device__ __forceinline__ void mma16816(float* c, const uint32_t* a, const uint32_t* b) {
    asm volatile(
        "mma.sync.aligned.m16n8k16.row.col.f32.bf16.bf16.f32 "
        "{%0,%1,%2,%3}, {%4,%5,%6,%7}, {%8,%9}, {%0,%1,%2,%3};"
        : "+f"(c[0]), "+f"(c[1]), "+f"(c[2]), "+f"(c[3])
        : "r"(a[0]), "r"(a[1]), "r"(a[2]), "r"(a[3]), "r"(b[0]), "r"(b[1]));
}

__device__ __forceinline__ void split_bf16(float v, __nv_bfloat16& h, __nv_bfloat16& l) {
    h = __float2bfloat16(v);
    l = __float2bfloat16(v - __bfloat162float(h));
}

// ======================= pre-pass kernels =======================
__global__ __launch_bounds__(256)
void split_x_kernel(const float* __restrict__ src,
                    __nv_bfloat16* __restrict__ hi, __nv_bfloat16* __restrict__ lo, int n4)
{
    for (int i = blockIdx.x * blockDim.x + threadIdx.x; i < n4; i += gridDim.x * blockDim.x) {
        float4 v = ((const float4*)src)[i];
        __nv_bfloat16 h0,h1,h2,h3,l0,l1,l2,l3;
        split_bf16(v.x,h0,l0); split_bf16(v.y,h1,l1); split_bf16(v.z,h2,l2); split_bf16(v.w,h3,l3);
        __nv_bfloat162* hp = (__nv_bfloat162*)(hi + (size_t)i*4);
        __nv_bfloat162* lp = (__nv_bfloat162*)(lo + (size_t)i*4);
        hp[0] = __nv_bfloat162(h0,h1); hp[1] = __nv_bfloat162(h2,h3);
        lp[0] = __nv_bfloat162(l0,l1); lp[1] = __nv_bfloat162(l2,l3);
    }
}

// W [K=1024, N=1024] fp32 -> Th/Tl [N,K] bf16  (transpose + split)
__global__ __launch_bounds__(256)
void transpose_split_kernel(const float* __restrict__ W,
                            __nv_bfloat16* __restrict__ Th, __nv_bfloat16* __restrict__ Tl)
{
    __shared__ float t[32][33];
    const int n0 = blockIdx.x * 32, k0 = blockIdx.y * 32;
    const int lx = threadIdx.x & 31, ly = threadIdx.x >> 5; // 32 x 8
    #pragma unroll
    for (int i = 0; i < 32; i += 8)
        t[ly + i][lx] = W[(size_t)(k0 + ly + i) * DMODEL + n0 + lx];
    __syncthreads();
    #pragma unroll
    for (int i = 0; i < 32; i += 8) {
        float v = t[lx][ly + i];
        __nv_bfloat16 h, l; split_bf16(v, h, l);
        const size_t o = (size_t)(n0 + ly + i) * DMODEL + k0 + lx;
        Th[o] = h; Tl[o] = l;
    }
}

// ======================= HMMA bf16x3 GEMM =======================
// C[4096,1024] = A[4096,1024] @ B[1024(N),1024(K)]^T + bias
// A given as hi/lo bf16 row-major [M,K]; B as hi/lo bf16 row-major [N,K].
// CTA tile 128x128, BK=32, 8 warps (4m x 2n -> 32x64 warp tile), 2-stage cp.async.
#define GBK 32
#define NCH (DMODEL / GBK)            // 32
#define ROWB 80                        // padded row stride in bytes (32 bf16 + 8 pad)
#define ARR_B (128 * ROWB)             // 10240 bytes per array
#define STAGE_B (4 * ARR_B)            // 40960 bytes per stage
#define GEMM_SMEM (2 * STAGE_B)        // 81920 bytes

__global__ __launch_bounds__(256, 1)
void gemm_bf16x3_kernel(const __nv_bfloat16* __restrict__ Ahi,
                        const __nv_bfloat16* __restrict__ Alo,
                        const __nv_bfloat16* __restrict__ Bhi,
                        const __nv_bfloat16* __restrict__ Blo,
                        const float* __restrict__ bias,
                        float* __restrict__ C)
{
    extern __shared__ char sm[];
    const uint32_t sbase = smem_u32(sm);

    const int tid  = threadIdx.x;
    const int lane = tid & 31;
    const int wid  = tid >> 5;
    const int mw0  = (wid & 3) * 32;   // warp m offset in tile
    const int nw0  = (wid >> 2) * 64;  // warp n offset in tile
    const int bm   = blockIdx.y * 128;
    const int bn   = blockIdx.x * 128;

    // loader mapping: 512 slots of 16B per array; 2 per thread
    const int r0 = (tid + 0)   >> 2, s0 = (tid + 0)   & 3;
    const int r1 = (tid + 256) >> 2, s1 = (tid + 256) & 3;

    const __nv_bfloat16* srcA[2] = { Ahi + (size_t)bm * DMODEL, Alo + (size_t)bm * DMODEL };
    const __nv_bfloat16* srcB[2] = { Bhi + (size_t)bn * DMODEL, Blo + (size_t)bn * DMODEL };

    float acc[2][8][4];
    #pragma unroll
    for (int i = 0; i < 2; i++)
        #pragma unroll
        for (int j = 0; j < 8; j++)
            #pragma unroll
            for (int q = 0; q < 4; q++) acc[i][j][q] = 0.f;

    // ldmatrix lane-address components (element offsets within padded rows)
    const int a_row  = (lane & 15);          // + mw0 + mi*16
    const int a_koff = (lane >> 4) * 8;      // k sub-offset
    const int b_row  = ((lane >> 4) << 3) + (lane & 7);  // + nw0 + nt2*16
    const int b_koff = ((lane >> 3) & 1) * 8;

    auto issue_loads = [&](int c, int stage) {
        const int k0 = c * GBK;
        const uint32_t sb = sbase + stage * STAGE_B;
        #pragma unroll
        for (int t = 0; t < 2; t++) {
            cp16(sb + t * ARR_B + r0 * ROWB + s0 * 16, srcA[t] + (size_t)r0 * DMODEL + k0 + s0 * 8);
            cp16(sb + t * ARR_B + r1 * ROWB + s1 * 16, srcA[t] + (size_t)r1 * DMODEL + k0 + s1 * 8);
        }
        #pragma unroll
        for (int t = 0; t < 2; t++) {
            cp16(sb + (2 + t) * ARR_B + r0 * ROWB + s0 * 16, srcB[t] + (size_t)r0 * DMODEL + k0 + s0 * 8);
            cp16(sb + (2 + t) * ARR_B + r1 * ROWB + s1 * 16, srcB[t] + (size_t)r1 * DMODEL + k0 + s1 * 8);
        }
    };

    issue_loads(0, 0);
    cp_commit();

    for (int c = 0; c < NCH; ++c) {
        const int stage = c & 1;
        const bool hasNext = (c + 1 < NCH);
        if (hasNext) { issue_loads(c + 1, stage ^ 1); cp_commit(); }
        if (hasNext) cp_wait1(); else cp_wait0();
        __syncthreads();

        const uint32_t sb = sbase + stage * STAGE_B;

        #pragma unroll
        for (int ks = 0; ks < 2; ++ks) {
            const int kk = ks * 16;  // element offset within chunk

            // A fragments (hi & lo): 2 m-tiles each
            uint32_t ah[2][4], al[2][4];
            #pragma unroll
            for (int mi = 0; mi < 2; ++mi) {
                const uint32_t arow = (uint32_t)(mw0 + mi * 16 + a_row);
                const uint32_t aoff = arow * ROWB + (kk + a_koff) * 2;
                ldsm_x4(ah[mi], sb + 0 * ARR_B + aoff);
                ldsm_x4(al[mi], sb + 1 * ARR_B + aoff);
            }

            // B double-tiles: nt2 covers 16 n (2 mma n-tiles) per ldmatrix.x4
            #pragma unroll
            for (int nt2 = 0; nt2 < 4; ++nt2) {
                const uint32_t brow = (uint32_t)(nw0 + nt2 * 16 + b_row);
                const uint32_t boff = brow * ROWB + (kk + b_koff) * 2;
                uint32_t bh[4], bl[4];
                ldsm_x4(bh, sb + 2 * ARR_B + boff);
                ldsm_x4(bl, sb + 3 * ARR_B + boff);
                #pragma unroll
                for (int mi = 0; mi < 2; ++mi) {
                    #pragma unroll
                    for (int half = 0; half < 2; ++half) {
                        float* cc = acc[mi][nt2 * 2 + half];
                        mma16816(cc, ah[mi], bh + half * 2);   // ahi*bhi
                        mma16816(cc, ah[mi], bl + half * 2);   // ahi*blo
                        mma16816(cc, al[mi], bh + half * 2);   // alo*bhi
                    }
                }
            }
        }
        __syncthreads();
    }

    // ---- epilogue: bias + store ----
    const int erow = lane >> 2;          // 0..7
    const int ecol = (lane & 3) * 2;     // 0,2,4,6
    #pragma unroll
    for (int mi = 0; mi < 2; ++mi) {
        #pragma unroll
        for (int ni = 0; ni < 8; ++ni) {
            const int n = bn + nw0 + ni * 8 + ecol;
            const float b0 = bias[n], b1 = bias[n + 1];
            const int m0 = bm + mw0 + mi * 16 + erow;
            float2 v0, v1;
            v0.x = acc[mi][ni][0] + b0; v0.y = acc[mi][ni][1] + b1;
            v1.x = acc[mi][ni][2] + b0; v1.y = acc[mi][ni][3] + b1;
            *(float2*)(C + (size_t)m0 * DMODEL + n)       = v0;
            *(float2*)(C + (size_t)(m0 + 8) * DMODEL + n) = v1;
        }
    }
}

// ======================= flash attention (fp32 SIMT, unchanged) =======================
#define BQ  128
#define BKV 128
#define STQ 132
#define STK 132
#define STV 68
#define STP 130
#define ATT_SMEM_FLOATS (DK*STQ + DK*STK + BKV*STV + BQ*STP)
#define ATT_SMEM_BYTES  (ATT_SMEM_FLOATS * 4)

__global__ __launch_bounds__(256)
void attn_kernel()
{
    extern __shared__ float smf[];
    float* QsT = smf;
    float* KsT = QsT + DK * STQ;
    float* Vs  = KsT + DK * STK;
    float* Ps  = Vs  + BKV * STV;

    const int tid = threadIdx.x;
    const int tx  = tid & 15;
    const int ty  = tid >> 4;
    const int h   = blockIdx.y;
    const int qt  = (int)gridDim.x - 1 - (int)blockIdx.x;
    const int q0  = qt * BQ;
    const int hoff = h * DK;

    {
        const int lq  = tid >> 4;
        const int ld0 = (tid & 15) << 2;
        #pragma unroll
        for (int it = 0; it < BQ / 16; it++) {
            const int q = lq + it * 16;
            const float4 v = *(const float4*)(g_q + (size_t)(q0 + q) * DMODEL + hoff + ld0);
            QsT[(ld0 + 0) * STQ + q] = v.x;
            QsT[(ld0 + 1) * STQ + q] = v.y;
            QsT[(ld0 + 2) * STQ + q] = v.z;
            QsT[(ld0 + 3) * STQ + q] = v.w;
        }
    }

    float m[8], l[8], o[8][4];
    #pragma unroll
    for (int i = 0; i < 8; i++) {
        m[i] = -1e30f; l[i] = 0.f;
        #pragma unroll
        for (int j = 0; j < 4; j++) o[i][j] = 0.f;
    }

    for (int kt = 0; kt <= qt; kt++) {
        const int k0 = kt * BKV;
        __syncthreads();
        {
            const int lr  = tid >> 4;
            const int ld0 = (tid & 15) << 2;
            #pragma unroll
            for (int it = 0; it < BKV / 16; it++) {
                const int kr = lr + it * 16;
                const float4 kv = *(const float4*)(g_k + (size_t)(k0 + kr) * DMODEL + hoff + ld0);
                KsT[(ld0 + 0) * STK + kr] = kv.x;
                KsT[(ld0 + 1) * STK + kr] = kv.y;
                KsT[(ld0 + 2) * STK + kr] = kv.z;
                KsT[(ld0 + 3) * STK + kr] = kv.w;
                const float4 vv = *(const float4*)(g_v + (size_t)(k0 + kr) * DMODEL + hoff + ld0);
                *(float4*)(Vs + kr * STV + ld0) = vv;
            }
        }
        __syncthreads();

        float s[8][8];
        #pragma unroll
        for (int i = 0; i < 8; i++)
            #pragma unroll
            for (int j = 0; j < 8; j++) s[i][j] = 0.f;

        #pragma unroll 4
        for (int kk = 0; kk < DK; kk++) {
            float a[8], b[8];
            *(float4*)&a[0] = *(const float4*)(QsT + kk * STQ + ty * 8);
            *(float4*)&a[4] = *(const float4*)(QsT + kk * STQ + ty * 8 + 4);
            *(float4*)&b[0] = *(const float4*)(KsT + kk * STK + tx * 8);
            *(float4*)&b[4] = *(const float4*)(KsT + kk * STK + tx * 8 + 4);
            #pragma unroll
            for (int i = 0; i < 8; i++)
                #pragma unroll
                for (int j = 0; j < 8; j++)
                    s[i][j] = fmaf(a[i], b[j], s[i][j]);
        }

        if (kt == qt) {
            #pragma unroll
            for (int i = 0; i < 8; i++) {
                const int qrow = ty * 8 + i;
                #pragma unroll
                for (int j = 0; j < 8; j++) {
                    const int kcol = tx * 8 + j;
                    s[i][j] = (kcol <= qrow) ? s[i][j] * 0.125f : -1e30f;
                }
            }
        } else {
            #pragma unroll
            for (int i = 0; i < 8; i++)
                #pragma unroll
                for (int j = 0; j < 8; j++) s[i][j] *= 0.125f;
        }

        #pragma unroll
        for (int i = 0; i < 8; i++) {
            float rmax = s[i][0];
            #pragma unroll
            for (int j = 1; j < 8; j++) rmax = fmaxf(rmax, s[i][j]);
            #pragma unroll
            for (int off = 8; off >= 1; off >>= 1)
                rmax = fmaxf(rmax, __shfl_xor_sync(0xffffffffu, rmax, off));

            const float mn    = fmaxf(m[i], rmax);
            const float alpha = __expf(m[i] - mn);
            float rsum = 0.f;
            #pragma unroll
            for (int j = 0; j < 8; j++) {
                const float p = __expf(s[i][j] - mn);
                s[i][j] = p;
                rsum += p;
            }
            #pragma unroll
            for (int off = 8; off >= 1; off >>= 1)
                rsum += __shfl_xor_sync(0xffffffffu, rsum, off);

            l[i] = l[i] * alpha + rsum;
            m[i] = mn;
            #pragma unroll
            for (int jd = 0; jd < 4; jd++) o[i][jd] *= alpha;
        }

        #pragma unroll
        for (int i = 0; i < 8; i++) {
            float* pr = Ps + (ty * 8 + i) * STP + tx * 8;
            #pragma unroll
            for (int j = 0; j < 8; j++) pr[j] = s[i][j];
        }
        __syncthreads();

        #pragma unroll 4
        for (int kk = 0; kk < BKV; kk++) {
            float a[8];
            #pragma unroll
            for (int i = 0; i < 8; i++) a[i] = Ps[(ty * 8 + i) * STP + kk];
            const float4 bv = *(const float4*)(Vs + kk * STV + tx * 4);
            #pragma unroll
            for (int i = 0; i < 8; i++) {
                o[i][0] = fmaf(a[i], bv.x, o[i][0]);
                o[i][1] = fmaf(a[i], bv.y, o[i][1]);
                o[i][2] = fmaf(a[i], bv.z, o[i][2]);
                o[i][3] = fmaf(a[i], bv.w, o[i][3]);
            }
        }
    }

    // epilogue: normalize, split to bf16 hi/lo for the O projection
    #pragma unroll
    for (int i = 0; i < 8; i++) {
        const float inv = 1.f / l[i];
        const size_t idx = (size_t)(q0 + ty * 8 + i) * DMODEL + hoff + tx * 4;
        float r[4] = { o[i][0]*inv, o[i][1]*inv, o[i][2]*inv, o[i][3]*inv };
        __nv_bfloat16 h[4], lo[4];
        #pragma unroll
        for (int j = 0; j < 4; j++) split_bf16(r[j], h[j], lo[j]);
        __nv_bfloat162* hp = (__nv_bfloat162*)(g_ch + idx);
        __nv_bfloat162* lp = (__nv_bfloat162*)(g_cl + idx);
        hp[0] = __nv_bfloat162(h[0], h[1]);  hp[1] = __nv_bfloat162(h[2], h[3]);
        lp[0] = __nv_bfloat162(lo[0], lo[1]); lp[1] = __nv_bfloat162(lo[2], lo[3]);
    }
}

// ======================= host launcher =======================
extern "C" void kernel_launch(void* const* d_in, const int* in_sizes, int n_in,
                              void* d_out, int out_size)
{
    (void)in_sizes; (void)n_in; (void)out_size;
    const float* x  = (const float*)d_in[0];
    const float* Wq = (const float*)d_in[2];
    const float* bq = (const float*)d_in[3];
    const float* Wk = (const float*)d_in[4];
    const float* bk = (const float*)d_in[5];
    const float* Wv = (const float*)d_in[6];
    const float* bv = (const float*)d_in[7];
    const float* Wo = (const float*)d_in[8];
    const float* bo = (const float*)d_in[9];
    float* out = (float*)d_out;

    float *qp, *kp, *vp;
    __nv_bfloat16 *xh, *xl, *ch, *cl;
    __nv_bfloat16 *wqh, *wql, *wkh, *wkl, *wvh, *wvl, *woh, *wol;
    cudaGetSymbolAddress((void**)&qp, g_q);
    cudaGetSymbolAddress((void**)&kp, g_k);
    cudaGetSymbolAddress((void**)&vp, g_v);
    cudaGetSymbolAddress((void**)&xh, g_xh);
    cudaGetSymbolAddress((void**)&xl, g_xl);
    cudaGetSymbolAddress((void**)&ch, g_ch);
    cudaGetSymbolAddress((void**)&cl, g_cl);
    cudaGetSymbolAddress((void**)&wqh, g_wqh);
    cudaGetSymbolAddress((void**)&wql, g_wql);
    cudaGetSymbolAddress((void**)&wkh, g_wkh);
    cudaGetSymbolAddress((void**)&wkl, g_wkl);
    cudaGetSymbolAddress((void**)&wvh, g_wvh);
    cudaGetSymbolAddress((void**)&wvl, g_wvl);
    cudaGetSymbolAddress((void**)&woh, g_woh);
    cudaGetSymbolAddress((void**)&wol, g_wol);

    // pre-pass: split x, transpose+split weights
    split_x_kernel<<<512, 256>>>(x, xh, xl, (S_LEN * DMODEL) / 4);
    const dim3 tgrid(DMODEL / 32, DMODEL / 32);
    transpose_split_kernel<<<tgrid, 256>>>(Wq, wqh, wql);
    transpose_split_kernel<<<tgrid, 256>>>(Wk, wkh, wkl);
    transpose_split_kernel<<<tgrid, 256>>>(Wv, wvh, wvl);
    transpose_split_kernel<<<tgrid, 256>>>(Wo, woh, wol);

    cudaFuncSetAttribute(gemm_bf16x3_kernel,
                         cudaFuncAttributeMaxDynamicSharedMemorySize, GEMM_SMEM);
    const dim3 ggrid(DMODEL / 128, S_LEN / 128);
    gemm_bf16x3_kernel<<<ggrid, 256, GEMM_SMEM>>>(xh, xl, wqh, wql, bq, qp);
    gemm_bf16x3_kernel<<<ggrid, 256, GEMM_SMEM>>>(xh, xl, wkh, wkl, bk, kp);
    gemm_bf16x3_kernel<<<ggrid, 256, GEMM_SMEM>>>(xh, xl, wvh, wvl, bv, vp);

    cudaFuncSetAttribute(attn_kernel,
                         cudaFuncAttributeMaxDynamicSharedMemorySize, ATT_SMEM_BYTES);
    attn_kernel<<<dim3(S_LEN / BQ, NHEADS), 256, ATT_SMEM_BYTES>>>();

    gemm_bf16x3_kernel<<<ggrid, 256, GEMM_SMEM>>>(ch, cl, woh, wol, bo, out);
}

// round 4
// speedup vs baseline: 2.6443x; 2.0208x over previous
#include <cuda_runtime.h>
#include <cuda_bf16.h>
#include <cstdint>
#include <math.h>

#define S_LEN  4096
#define DMODEL 1024
#define NHEADS 16
#define DK     64

// ======================= scratch (device globals) =======================
__device__ __nv_bfloat16 g_qh[(size_t)S_LEN * DMODEL];
__device__ __nv_bfloat16 g_ql[(size_t)S_LEN * DMODEL];
__device__ __nv_bfloat16 g_kh[(size_t)S_LEN * DMODEL];
__device__ __nv_bfloat16 g_kl[(size_t)S_LEN * DMODEL];
__device__ __nv_bfloat16 g_vh[(size_t)S_LEN * DMODEL];
__device__ __nv_bfloat16 g_vl[(size_t)S_LEN * DMODEL];

__device__ __nv_bfloat16 g_xh[(size_t)S_LEN * DMODEL];
__device__ __nv_bfloat16 g_xl[(size_t)S_LEN * DMODEL];
__device__ __nv_bfloat16 g_ch[(size_t)S_LEN * DMODEL];
__device__ __nv_bfloat16 g_cl[(size_t)S_LEN * DMODEL];

__device__ __nv_bfloat16 g_wqh[(size_t)DMODEL * DMODEL];
__device__ __nv_bfloat16 g_wql[(size_t)DMODEL * DMODEL];
__device__ __nv_bfloat16 g_wkh[(size_t)DMODEL * DMODEL];
__device__ __nv_bfloat16 g_wkl[(size_t)DMODEL * DMODEL];
__device__ __nv_bfloat16 g_wvh[(size_t)DMODEL * DMODEL];
__device__ __nv_bfloat16 g_wvl[(size_t)DMODEL * DMODEL];
__device__ __nv_bfloat16 g_woh[(size_t)DMODEL * DMODEL];
__device__ __nv_bfloat16 g_wol[(size_t)DMODEL * DMODEL];

// ======================= helpers =======================
__device__ __forceinline__ uint32_t smem_u32(const void* p) {
    uint32_t a;
    asm("{ .reg .u64 t; cvta.to.shared.u64 t, %1; cvt.u32.u64 %0, t; }" : "=r"(a) : "l"(p));
    return a;
}
__device__ __forceinline__ void cp16(uint32_t saddr, const void* g) {
    asm volatile("cp.async.ca.shared.global [%0], [%1], 16;" :: "r"(saddr), "l"(g));
}
__device__ __forceinline__ void cp_commit() { asm volatile("cp.async.commit_group;"); }
__device__ __forceinline__ void cp_wait1()  { asm volatile("cp.async.wait_group 1;"); }
__device__ __forceinline__ void cp_wait0()  { asm volatile("cp.async.wait_group 0;"); }

__device__ __forceinline__ void ldsm_x4(uint32_t* r, uint32_t addr) {
    asm volatile("ldmatrix.sync.aligned.m8n8.x4.shared.b16 {%0,%1,%2,%3}, [%4];"
                 : "=r"(r[0]), "=r"(r[1]), "=r"(r[2]), "=r"(r[3]) : "r"(addr));
}
__device__ __forceinline__ void ldsm_x4_t(uint32_t* r, uint32_t addr) {
    asm volatile("ldmatrix.sync.aligned.m8n8.x4.trans.shared.b16 {%0,%1,%2,%3}, [%4];"
                 : "=r"(r[0]), "=r"(r[1]), "=r"(r[2]), "=r"(r[3]) : "r"(addr));
}
__device__ __forceinline__ void mma16816(float* c, const uint32_t* a, const uint32_t* b) {
    asm volatile(
        "mma.sync.aligned.m16n8k16.row.col.f32.bf16.bf16.f32 "
        "{%0,%1,%2,%3}, {%4,%5,%6,%7}, {%8,%9}, {%0,%1,%2,%3};"
        : "+f"(c[0]), "+f"(c[1]), "+f"(c[2]), "+f"(c[3])
        : "r"(a[0]), "r"(a[1]), "r"(a[2]), "r"(a[3]), "r"(b[0]), "r"(b[1]));
}

__device__ __forceinline__ void split_bf16(float v, __nv_bfloat16& h, __nv_bfloat16& l) {
    h = __float2bfloat16(v);
    l = __float2bfloat16(v - __bfloat162float(h));
}
// split-pack two floats into bf16x2 hi and lo words
__device__ __forceinline__ void pack2(float x, float y, uint32_t& hi, uint32_t& lo) {
    __nv_bfloat16 xh, xl, yh, yl;
    split_bf16(x, xh, xl);
    split_bf16(y, yh, yl);
    __nv_bfloat162 H(xh, yh), L(xl, yl);
    hi = *(uint32_t*)&H;
    lo = *(uint32_t*)&L;
}

// ======================= pre-pass kernels =======================
__global__ __launch_bounds__(256)
void split_x_kernel(const float* __restrict__ src,
                    __nv_bfloat16* __restrict__ hi, __nv_bfloat16* __restrict__ lo, int n4)
{
    for (int i = blockIdx.x * blockDim.x + threadIdx.x; i < n4; i += gridDim.x * blockDim.x) {
        float4 v = ((const float4*)src)[i];
        __nv_bfloat16 h0,h1,h2,h3,l0,l1,l2,l3;
        split_bf16(v.x,h0,l0); split_bf16(v.y,h1,l1); split_bf16(v.z,h2,l2); split_bf16(v.w,h3,l3);
        __nv_bfloat162* hp = (__nv_bfloat162*)(hi + (size_t)i*4);
        __nv_bfloat162* lp = (__nv_bfloat162*)(lo + (size_t)i*4);
        hp[0] = __nv_bfloat162(h0,h1); hp[1] = __nv_bfloat162(h2,h3);
        lp[0] = __nv_bfloat162(l0,l1); lp[1] = __nv_bfloat162(l2,l3);
    }
}

__global__ __launch_bounds__(256)
void transpose_split_kernel(const float* __restrict__ W,
                            __nv_bfloat16* __restrict__ Th, __nv_bfloat16* __restrict__ Tl)
{
    __shared__ float t[32][33];
    const int n0 = blockIdx.x * 32, k0 = blockIdx.y * 32;
    const int lx = threadIdx.x & 31, ly = threadIdx.x >> 5;
    #pragma unroll
    for (int i = 0; i < 32; i += 8)
        t[ly + i][lx] = W[(size_t)(k0 + ly + i) * DMODEL + n0 + lx];
    __syncthreads();
    #pragma unroll
    for (int i = 0; i < 32; i += 8) {
        float v = t[lx][ly + i];
        __nv_bfloat16 h, l; split_bf16(v, h, l);
        const size_t o = (size_t)(n0 + ly + i) * DMODEL + k0 + lx;
        Th[o] = h; Tl[o] = l;
    }
}

// ======================= HMMA bf16x3 GEMM =======================
// mode 0: C = fp32 out + bias.   mode 1: split (C+bias)*scale into Chi/Clo bf16.
#define GBK 32
#define NCH (DMODEL / GBK)
#define ROWB 80
#define ARR_B (128 * ROWB)
#define STAGE_B (4 * ARR_B)
#define GEMM_SMEM (2 * STAGE_B)

__global__ __launch_bounds__(256, 1)
void gemm_bf16x3_kernel(const __nv_bfloat16* __restrict__ Ahi,
                        const __nv_bfloat16* __restrict__ Alo,
                        const __nv_bfloat16* __restrict__ Bhi,
                        const __nv_bfloat16* __restrict__ Blo,
                        const float* __restrict__ bias,
                        float* __restrict__ C,
                        __nv_bfloat16* __restrict__ Chi,
                        __nv_bfloat16* __restrict__ Clo,
                        int mode, float scale)
{
    extern __shared__ char sm[];
    const uint32_t sbase = smem_u32(sm);

    const int tid  = threadIdx.x;
    const int lane = tid & 31;
    const int wid  = tid >> 5;
    const int mw0  = (wid & 3) * 32;
    const int nw0  = (wid >> 2) * 64;
    const int bm   = blockIdx.y * 128;
    const int bn   = blockIdx.x * 128;

    const int r0 = (tid + 0)   >> 2, s0 = (tid + 0)   & 3;
    const int r1 = (tid + 256) >> 2, s1 = (tid + 256) & 3;

    const __nv_bfloat16* srcA[2] = { Ahi + (size_t)bm * DMODEL, Alo + (size_t)bm * DMODEL };
    const __nv_bfloat16* srcB[2] = { Bhi + (size_t)bn * DMODEL, Blo + (size_t)bn * DMODEL };

    float acc[2][8][4];
    #pragma unroll
    for (int i = 0; i < 2; i++)
        #pragma unroll
        for (int j = 0; j < 8; j++)
            #pragma unroll
            for (int q = 0; q < 4; q++) acc[i][j][q] = 0.f;

    const int a_row  = (lane & 15);
    const int a_koff = (lane >> 4) * 8;
    const int b_row  = ((lane >> 4) << 3) + (lane & 7);
    const int b_koff = ((lane >> 3) & 1) * 8;

    auto issue_loads = [&](int c, int stage) {
        const int k0 = c * GBK;
        const uint32_t sb = sbase + stage * STAGE_B;
        #pragma unroll
        for (int t = 0; t < 2; t++) {
            cp16(sb + t * ARR_B + r0 * ROWB + s0 * 16, srcA[t] + (size_t)r0 * DMODEL + k0 + s0 * 8);
            cp16(sb + t * ARR_B + r1 * ROWB + s1 * 16, srcA[t] + (size_t)r1 * DMODEL + k0 + s1 * 8);
        }
        #pragma unroll
        for (int t = 0; t < 2; t++) {
            cp16(sb + (2 + t) * ARR_B + r0 * ROWB + s0 * 16, srcB[t] + (size_t)r0 * DMODEL + k0 + s0 * 8);
            cp16(sb + (2 + t) * ARR_B + r1 * ROWB + s1 * 16, srcB[t] + (size_t)r1 * DMODEL + k0 + s1 * 8);
        }
    };

    issue_loads(0, 0);
    cp_commit();

    for (int c = 0; c < NCH; ++c) {
        const int stage = c & 1;
        const bool hasNext = (c + 1 < NCH);
        if (hasNext) { issue_loads(c + 1, stage ^ 1); cp_commit(); }
        if (hasNext) cp_wait1(); else cp_wait0();
        __syncthreads();

        const uint32_t sb = sbase + stage * STAGE_B;

        #pragma unroll
        for (int ks = 0; ks < 2; ++ks) {
            const int kk = ks * 16;
            uint32_t ah[2][4], al[2][4];
            #pragma unroll
            for (int mi = 0; mi < 2; ++mi) {
                const uint32_t arow = (uint32_t)(mw0 + mi * 16 + a_row);
                const uint32_t aoff = arow * ROWB + (kk + a_koff) * 2;
                ldsm_x4(ah[mi], sb + 0 * ARR_B + aoff);
                ldsm_x4(al[mi], sb + 1 * ARR_B + aoff);
            }
            #pragma unroll
            for (int nt2 = 0; nt2 < 4; ++nt2) {
                const uint32_t brow = (uint32_t)(nw0 + nt2 * 16 + b_row);
                const uint32_t boff = brow * ROWB + (kk + b_koff) * 2;
                uint32_t bh[4], bl[4];
                ldsm_x4(bh, sb + 2 * ARR_B + boff);
                ldsm_x4(bl, sb + 3 * ARR_B + boff);
                #pragma unroll
                for (int mi = 0; mi < 2; ++mi) {
                    #pragma unroll
                    for (int half = 0; half < 2; ++half) {
                        float* cc = acc[mi][nt2 * 2 + half];
                        mma16816(cc, ah[mi], bh + half * 2);
                        mma16816(cc, ah[mi], bl + half * 2);
                        mma16816(cc, al[mi], bh + half * 2);
                    }
                }
            }
        }
        __syncthreads();
    }

    // ---- epilogue ----
    const int erow = lane >> 2;
    const int ecol = (lane & 3) * 2;
    if (mode == 0) {
        #pragma unroll
        for (int mi = 0; mi < 2; ++mi) {
            #pragma unroll
            for (int ni = 0; ni < 8; ++ni) {
                const int n = bn + nw0 + ni * 8 + ecol;
                const float b0 = bias[n], b1 = bias[n + 1];
                const int m0 = bm + mw0 + mi * 16 + erow;
                float2 v0, v1;
                v0.x = acc[mi][ni][0] + b0; v0.y = acc[mi][ni][1] + b1;
                v1.x = acc[mi][ni][2] + b0; v1.y = acc[mi][ni][3] + b1;
                *(float2*)(C + (size_t)m0 * DMODEL + n)       = v0;
                *(float2*)(C + (size_t)(m0 + 8) * DMODEL + n) = v1;
            }
        }
    } else {
        #pragma unroll
        for (int mi = 0; mi < 2; ++mi) {
            #pragma unroll
            for (int ni = 0; ni < 8; ++ni) {
                const int n = bn + nw0 + ni * 8 + ecol;
                const float b0 = bias[n], b1 = bias[n + 1];
                const int m0 = bm + mw0 + mi * 16 + erow;
                uint32_t H, L;
                pack2((acc[mi][ni][0] + b0) * scale, (acc[mi][ni][1] + b1) * scale, H, L);
                *(uint32_t*)(Chi + (size_t)m0 * DMODEL + n) = H;
                *(uint32_t*)(Clo + (size_t)m0 * DMODEL + n) = L;
                pack2((acc[mi][ni][2] + b0) * scale, (acc[mi][ni][3] + b1) * scale, H, L);
                *(uint32_t*)(Chi + (size_t)(m0 + 8) * DMODEL + n) = H;
                *(uint32_t*)(Clo + (size_t)(m0 + 8) * DMODEL + n) = L;
            }
        }
    }
}

// ======================= HMMA flash attention =======================
// CTA = (head, 128-query tile), 256 threads, 8 warps x 16 query rows.
// kv tiles of 128 keys, double-buffered cp.async. Q pre-scaled by 1/8 in GEMM.
#define KVROW 72                       // bf16 elems per padded smem row (144 B)
#define KVARR_B (128 * KVROW * 2)      // 18432 B per array
#define ATT_SMEM (8 * KVARR_B)         // 2 buffers x {kh,kl,vh,vl} = 147456 B

__global__ __launch_bounds__(256, 1)
void attn_hmma_kernel()
{
    extern __shared__ __nv_bfloat16 smb[];
    const uint32_t sbase = smem_u32(smb);

    const int tid  = threadIdx.x;
    const int lane = tid & 31;
    const int w    = tid >> 5;
    const int h    = blockIdx.y;
    const int qt   = (int)gridDim.x - 1 - (int)blockIdx.x;
    const int q0   = qt * 128;
    const int hoff = h * DK;
    const int q0w  = q0 + w * 16;

    const int r  = lane >> 2;
    const int kc = (lane & 3) * 2;

    // ---- Q fragments from gmem (held in regs for the whole kernel) ----
    uint32_t qhf[4][4], qlf[4][4];
    #pragma unroll
    for (int ks = 0; ks < 4; ++ks) {
        const size_t rowA = (size_t)(q0w + r) * DMODEL + hoff + ks * 16 + kc;
        const size_t rowB = (size_t)(q0w + r + 8) * DMODEL + hoff + ks * 16 + kc;
        qhf[ks][0] = *(const uint32_t*)(g_qh + rowA);
        qhf[ks][1] = *(const uint32_t*)(g_qh + rowB);
        qhf[ks][2] = *(const uint32_t*)(g_qh + rowA + 8);
        qhf[ks][3] = *(const uint32_t*)(g_qh + rowB + 8);
        qlf[ks][0] = *(const uint32_t*)(g_ql + rowA);
        qlf[ks][1] = *(const uint32_t*)(g_ql + rowB);
        qlf[ks][2] = *(const uint32_t*)(g_ql + rowA + 8);
        qlf[ks][3] = *(const uint32_t*)(g_ql + rowB + 8);
    }

    auto issue_kv = [&](int kt, int buf) {
        const int k0 = kt * 128;
        const __nv_bfloat16* srcs[4] = { g_kh, g_kl, g_vh, g_vl };
        #pragma unroll
        for (int t = 0; t < 4; ++t) {
            const uint32_t sb = sbase + (buf * 4 + t) * KVARR_B;
            const __nv_bfloat16* src = srcs[t] + (size_t)k0 * DMODEL + hoff;
            #pragma unroll
            for (int j = 0; j < 4; ++j) {
                const int c = tid + j * 256;
                const int row = c >> 3, col = c & 7;
                cp16(sb + row * 144 + col * 16, src + (size_t)row * DMODEL + col * 8);
            }
        }
    };

    float m_[2] = { -1e30f, -1e30f }, l_[2] = { 0.f, 0.f };
    float oacc[8][4];
    #pragma unroll
    for (int i = 0; i < 8; i++)
        #pragma unroll
        for (int j = 0; j < 4; j++) oacc[i][j] = 0.f;

    issue_kv(0, 0);
    cp_commit();

    const uint32_t b_row = ((lane >> 4) << 3) + (lane & 7);
    const uint32_t b_k   = ((lane >> 3) & 1) * 8;
    const uint32_t vrow  = lane & 15;
    const uint32_t vcol  = (lane >> 4) * 8;

    for (int kt = 0; kt <= qt; ++kt) {
        const int buf = kt & 1;
        const bool hasNext = kt < qt;
        if (hasNext) { issue_kv(kt + 1, buf ^ 1); cp_commit(); }
        if (hasNext) cp_wait1(); else cp_wait0();
        __syncthreads();

        const uint32_t kh_b = sbase + (buf * 4 + 0) * KVARR_B;
        const uint32_t kl_b = sbase + (buf * 4 + 1) * KVARR_B;
        const uint32_t vh_b = sbase + (buf * 4 + 2) * KVARR_B;
        const uint32_t vl_b = sbase + (buf * 4 + 3) * KVARR_B;

        // ---- S = Q @ K^T (hi/lo x3) ----
        float s[16][4];
        #pragma unroll
        for (int i = 0; i < 16; i++)
            #pragma unroll
            for (int j = 0; j < 4; j++) s[i][j] = 0.f;

        #pragma unroll
        for (int ks = 0; ks < 4; ++ks) {
            #pragma unroll
            for (int nt2 = 0; nt2 < 8; ++nt2) {
                const uint32_t addr = (nt2 * 16 + b_row) * 144 + (ks * 16 + b_k) * 2;
                uint32_t bh[4], bl[4];
                ldsm_x4(bh, kh_b + addr);
                ldsm_x4(bl, kl_b + addr);
                #pragma unroll
                for (int hf = 0; hf < 2; ++hf) {
                    float* cc = s[nt2 * 2 + hf];
                    mma16816(cc, qhf[ks], bh + hf * 2);
                    mma16816(cc, qhf[ks], bl + hf * 2);
                    mma16816(cc, qlf[ks], bh + hf * 2);
                }
            }
        }

        // ---- causal mask on diagonal tile ----
        if (kt == qt) {
            #pragma unroll
            for (int nt = 0; nt < 16; ++nt) {
                #pragma unroll
                for (int c = 0; c < 4; ++c) {
                    const int key = nt * 8 + kc + (c & 1);
                    const int qq  = w * 16 + r + (c >> 1) * 8;
                    if (key > qq) s[nt][c] = -1e30f;
                }
            }
        }

        // ---- online softmax (2 rows per thread; row group = 4 lanes) ----
        float mx0 = -1e30f, mx1 = -1e30f;
        #pragma unroll
        for (int nt = 0; nt < 16; ++nt) {
            mx0 = fmaxf(mx0, fmaxf(s[nt][0], s[nt][1]));
            mx1 = fmaxf(mx1, fmaxf(s[nt][2], s[nt][3]));
        }
        mx0 = fmaxf(mx0, __shfl_xor_sync(0xffffffffu, mx0, 1));
        mx0 = fmaxf(mx0, __shfl_xor_sync(0xffffffffu, mx0, 2));
        mx1 = fmaxf(mx1, __shfl_xor_sync(0xffffffffu, mx1, 1));
        mx1 = fmaxf(mx1, __shfl_xor_sync(0xffffffffu, mx1, 2));

        const float nm0 = fmaxf(m_[0], mx0), nm1 = fmaxf(m_[1], mx1);
        const float al0 = __expf(m_[0] - nm0), al1 = __expf(m_[1] - nm1);
        float rs0 = 0.f, rs1 = 0.f;
        #pragma unroll
        for (int nt = 0; nt < 16; ++nt) {
            s[nt][0] = __expf(s[nt][0] - nm0);
            s[nt][1] = __expf(s[nt][1] - nm0);
            s[nt][2] = __expf(s[nt][2] - nm1);
            s[nt][3] = __expf(s[nt][3] - nm1);
            rs0 += s[nt][0] + s[nt][1];
            rs1 += s[nt][2] + s[nt][3];
        }
        rs0 += __shfl_xor_sync(0xffffffffu, rs0, 1);
        rs0 += __shfl_xor_sync(0xffffffffu, rs0, 2);
        rs1 += __shfl_xor_sync(0xffffffffu, rs1, 1);
        rs1 += __shfl_xor_sync(0xffffffffu, rs1, 2);

        l_[0] = l_[0] * al0 + rs0;  m_[0] = nm0;
        l_[1] = l_[1] * al1 + rs1;  m_[1] = nm1;
        #pragma unroll
        for (int dt = 0; dt < 8; ++dt) {
            oacc[dt][0] *= al0; oacc[dt][1] *= al0;
            oacc[dt][2] *= al1; oacc[dt][3] *= al1;
        }

        // ---- O += P @ V (P packed in regs, hi/lo x3; V via ldmatrix.trans) ----
        #pragma unroll
        for (int j = 0; j < 8; ++j) {
            uint32_t pah[4], pal[4];
            pack2(s[2*j][0],   s[2*j][1],   pah[0], pal[0]);
            pack2(s[2*j][2],   s[2*j][3],   pah[1], pal[1]);
            pack2(s[2*j+1][0], s[2*j+1][1], pah[2], pal[2]);
            pack2(s[2*j+1][2], s[2*j+1][3], pah[3], pal[3]);

            const uint32_t abase = (j * 16 + vrow) * 144 + vcol * 2;
            #pragma unroll
            for (int dg = 0; dg < 4; ++dg) {
                const uint32_t a2 = abase + dg * 32;
                uint32_t bh[4], bl[4];
                ldsm_x4_t(bh, vh_b + a2);
                ldsm_x4_t(bl, vl_b + a2);
                #pragma unroll
                for (int hf = 0; hf < 2; ++hf) {
                    float* cc = oacc[dg * 2 + hf];
                    mma16816(cc, pah, bh + hf * 2);
                    mma16816(cc, pah, bl + hf * 2);
                    mma16816(cc, pal, bh + hf * 2);
                }
            }
        }
        __syncthreads();
    }

    // ---- epilogue: normalize, split-store ctx hi/lo ----
    const float inv0 = 1.f / l_[0], inv1 = 1.f / l_[1];
    #pragma unroll
    for (int dt = 0; dt < 8; ++dt) {
        const size_t d = (size_t)hoff + dt * 8 + kc;
        const size_t rowA = (size_t)(q0w + r) * DMODEL + d;
        const size_t rowB = (size_t)(q0w + r + 8) * DMODEL + d;
        uint32_t H, L;
        pack2(oacc[dt][0] * inv0, oacc[dt][1] * inv0, H, L);
        *(uint32_t*)(g_ch + rowA) = H;
        *(uint32_t*)(g_cl + rowA) = L;
        pack2(oacc[dt][2] * inv1, oacc[dt][3] * inv1, H, L);
        *(uint32_t*)(g_ch + rowB) = H;
        *(uint32_t*)(g_cl + rowB) = L;
    }
}

// ======================= host launcher =======================
extern "C" void kernel_launch(void* const* d_in, const int* in_sizes, int n_in,
                              void* d_out, int out_size)
{
    (void)in_sizes; (void)n_in; (void)out_size;
    const float* x  = (const float*)d_in[0];
    const float* Wq = (const float*)d_in[2];
    const float* bq = (const float*)d_in[3];
    const float* Wk = (const float*)d_in[4];
    const float* bk = (const float*)d_in[5];
    const float* Wv = (const float*)d_in[6];
    const float* bv = (const float*)d_in[7];
    const float* Wo = (const float*)d_in[8];
    const float* bo = (const float*)d_in[9];
    float* out = (float*)d_out;

    __nv_bfloat16 *qh, *ql, *kh, *kl, *vh, *vl, *xh, *xl, *ch, *cl;
    __nv_bfloat16 *wqh, *wql, *wkh, *wkl, *wvh, *wvl, *woh, *wol;
    cudaGetSymbolAddress((void**)&qh, g_qh);
    cudaGetSymbolAddress((void**)&ql, g_ql);
    cudaGetSymbolAddress((void**)&kh, g_kh);
    cudaGetSymbolAddress((void**)&kl, g_kl);
    cudaGetSymbolAddress((void**)&vh, g_vh);
    cudaGetSymbolAddress((void**)&vl, g_vl);
    cudaGetSymbolAddress((void**)&xh, g_xh);
    cudaGetSymbolAddress((void**)&xl, g_xl);
    cudaGetSymbolAddress((void**)&ch, g_ch);
    cudaGetSymbolAddress((void**)&cl, g_cl);
    cudaGetSymbolAddress((void**)&wqh, g_wqh);
    cudaGetSymbolAddress((void**)&wql, g_wql);
    cudaGetSymbolAddress((void**)&wkh, g_wkh);
    cudaGetSymbolAddress((void**)&wkl, g_wkl);
    cudaGetSymbolAddress((void**)&wvh, g_wvh);
    cudaGetSymbolAddress((void**)&wvl, g_wvl);
    cudaGetSymbolAddress((void**)&woh, g_woh);
    cudaGetSymbolAddress((void**)&wol, g_wol);

    split_x_kernel<<<512, 256>>>(x, xh, xl, (S_LEN * DMODEL) / 4);
    const dim3 tgrid(DMODEL / 32, DMODEL / 32);
    transpose_split_kernel<<<tgrid, 256>>>(Wq, wqh, wql);
    transpose_split_kernel<<<tgrid, 256>>>(Wk, wkh, wkl);
    transpose_split_kernel<<<tgrid, 256>>>(Wv, wvh, wvl);
    transpose_split_kernel<<<tgrid, 256>>>(Wo, woh, wol);

    cudaFuncSetAttribute(gemm_bf16x3_kernel,
                         cudaFuncAttributeMaxDynamicSharedMemorySize, GEMM_SMEM);
    const dim3 ggrid(DMODEL / 128, S_LEN / 128);
    const float qscale = 0.125f;  // 1/sqrt(DK)
    gemm_bf16x3_kernel<<<ggrid, 256, GEMM_SMEM>>>(xh, xl, wqh, wql, bq, nullptr, qh, ql, 1, qscale);
    gemm_bf16x3_kernel<<<ggrid, 256, GEMM_SMEM>>>(xh, xl, wkh, wkl, bk, nullptr, kh, kl, 1, 1.0f);
    gemm_bf16x3_kernel<<<ggrid, 256, GEMM_SMEM>>>(xh, xl, wvh, wvl, bv, nullptr, vh, vl, 1, 1.0f);

    cudaFuncSetAttribute(attn_hmma_kernel,
                         cudaFuncAttributeMaxDynamicSharedMemorySize, ATT_SMEM);
    attn_hmma_kernel<<<dim3(S_LEN / 128, NHEADS), 256, ATT_SMEM>>>();

    gemm_bf16x3_kernel<<<ggrid, 256, GEMM_SMEM>>>(ch, cl, woh, wol, bo, out, nullptr, nullptr, 0, 1.0f);
}

// round 5
// speedup vs baseline: 3.2242x; 1.2193x over previous
#include <cuda_runtime.h>
#include <cuda_bf16.h>
#include <cstdint>
#include <math.h>

#define S_LEN  4096
#define DMODEL 1024
#define NHEADS 16
#define DK     64

// ======================= scratch (device globals) =======================
// int8 digit operands + scales
__device__ int8_t g_x1[(size_t)S_LEN * DMODEL];
__device__ int8_t g_x2[(size_t)S_LEN * DMODEL];
__device__ float  g_sx[S_LEN];

__device__ int8_t g_wq1[(size_t)DMODEL * DMODEL];
__device__ int8_t g_wq2[(size_t)DMODEL * DMODEL];
__device__ int8_t g_wk1[(size_t)DMODEL * DMODEL];
__device__ int8_t g_wk2[(size_t)DMODEL * DMODEL];
__device__ int8_t g_wv1[(size_t)DMODEL * DMODEL];
__device__ int8_t g_wv2[(size_t)DMODEL * DMODEL];
__device__ int8_t g_wo1[(size_t)DMODEL * DMODEL];
__device__ int8_t g_wo2[(size_t)DMODEL * DMODEL];
__device__ unsigned g_wbits[4 * DMODEL];   // col-max bits per weight

// attention operands (bf16 hi/lo) + fp32 ctx + ctx digits
__device__ __nv_bfloat16 g_qh[(size_t)S_LEN * DMODEL];
__device__ __nv_bfloat16 g_ql[(size_t)S_LEN * DMODEL];
__device__ __nv_bfloat16 g_kh[(size_t)S_LEN * DMODEL];
__device__ __nv_bfloat16 g_kl[(size_t)S_LEN * DMODEL];
__device__ __nv_bfloat16 g_vh[(size_t)S_LEN * DMODEL];
__device__ __nv_bfloat16 g_vl[(size_t)S_LEN * DMODEL];
__device__ float g_ctx[(size_t)S_LEN * DMODEL];
__device__ int8_t g_c1[(size_t)S_LEN * DMODEL];
__device__ int8_t g_c2[(size_t)S_LEN * DMODEL];
__device__ float  g_sc[S_LEN];

// ======================= helpers =======================
__device__ __forceinline__ uint32_t smem_u32(const void* p) {
    uint32_t a;
    asm("{ .reg .u64 t; cvta.to.shared.u64 t, %1; cvt.u32.u64 %0, t; }" : "=r"(a) : "l"(p));
    return a;
}
__device__ __forceinline__ void cp16(uint32_t saddr, const void* g) {
    asm volatile("cp.async.ca.shared.global [%0], [%1], 16;" :: "r"(saddr), "l"(g));
}
__device__ __forceinline__ void cp_commit() { asm volatile("cp.async.commit_group;"); }
__device__ __forceinline__ void cp_wait1()  { asm volatile("cp.async.wait_group 1;"); }
__device__ __forceinline__ void cp_wait0()  { asm volatile("cp.async.wait_group 0;"); }

__device__ __forceinline__ void ldsm_x4(uint32_t* r, uint32_t addr) {
    asm volatile("ldmatrix.sync.aligned.m8n8.x4.shared.b16 {%0,%1,%2,%3}, [%4];"
                 : "=r"(r[0]), "=r"(r[1]), "=r"(r[2]), "=r"(r[3]) : "r"(addr));
}
__device__ __forceinline__ void ldsm_x4_t(uint32_t* r, uint32_t addr) {
    asm volatile("ldmatrix.sync.aligned.m8n8.x4.trans.shared.b16 {%0,%1,%2,%3}, [%4];"
                 : "=r"(r[0]), "=r"(r[1]), "=r"(r[2]), "=r"(r[3]) : "r"(addr));
}
__device__ __forceinline__ void mma16816(float* c, const uint32_t* a, const uint32_t* b) {
    asm volatile(
        "mma.sync.aligned.m16n8k16.row.col.f32.bf16.bf16.f32 "
        "{%0,%1,%2,%3}, {%4,%5,%6,%7}, {%8,%9}, {%0,%1,%2,%3};"
        : "+f"(c[0]), "+f"(c[1]), "+f"(c[2]), "+f"(c[3])
        : "r"(a[0]), "r"(a[1]), "r"(a[2]), "r"(a[3]), "r"(b[0]), "r"(b[1]));
}
__device__ __forceinline__ void mma_s8(int* c, const uint32_t* a, const uint32_t* b) {
    asm volatile(
        "mma.sync.aligned.m16n8k32.row.col.s32.s8.s8.s32 "
        "{%0,%1,%2,%3}, {%4,%5,%6,%7}, {%8,%9}, {%0,%1,%2,%3};"
        : "+r"(c[0]), "+r"(c[1]), "+r"(c[2]), "+r"(c[3])
        : "r"(a[0]), "r"(a[1]), "r"(a[2]), "r"(a[3]), "r"(b[0]), "r"(b[1]));
}

__device__ __forceinline__ void split_bf16(float v, __nv_bfloat16& h, __nv_bfloat16& l) {
    h = __float2bfloat16(v);
    l = __float2bfloat16(v - __bfloat162float(h));
}
__device__ __forceinline__ void pack2(float x, float y, uint32_t& hi, uint32_t& lo) {
    __nv_bfloat16 xh, xl, yh, yl;
    split_bf16(x, xh, xl);
    split_bf16(y, yh, yl);
    __nv_bfloat162 H(xh, yh), L(xl, yl);
    hi = *(uint32_t*)&H;
    lo = *(uint32_t*)&L;
}
__device__ __forceinline__ void digits2(float alpha, int& d1, int& d2) {
    d1 = __float2int_rn(alpha);
    d2 = __float2int_rn((alpha - (float)d1) * 254.f);
}

// ======================= quantization pre-pass =======================
__global__ void zero_bits_kernel(unsigned* b) { b[blockIdx.x * 1024 + threadIdx.x] = 0u; }

// column max of W (= row max of W^T). grid (8,8), 256 thr.
__global__ __launch_bounds__(256)
void colmax_kernel(const float* __restrict__ W, unsigned* __restrict__ bits)
{
    const int c  = blockIdx.x * 128 + (threadIdx.x & 127);
    const int r0 = blockIdx.y * 128 + (threadIdx.x >> 7);
    const int re = blockIdx.y * 128 + 128;
    float m = 0.f;
    #pragma unroll 8
    for (int r = r0; r < re; r += 2)
        m = fmaxf(m, fabsf(W[(size_t)r * DMODEL + c]));
    atomicMax(bits + c, __float_as_uint(m));
}

// transpose W [K,N] -> digit arrays [N,K] int8 using per-n col max.
__global__ __launch_bounds__(256)
void transpose_quant_kernel(const float* __restrict__ W,
                            const unsigned* __restrict__ bits,
                            int8_t* __restrict__ B1, int8_t* __restrict__ B2)
{
    __shared__ float t[32][33];
    const int n0 = blockIdx.x * 32, k0 = blockIdx.y * 32;
    const int lx = threadIdx.x & 31, ly = threadIdx.x >> 5;
    #pragma unroll
    for (int i = 0; i < 32; i += 8)
        t[ly + i][lx] = W[(size_t)(k0 + ly + i) * DMODEL + n0 + lx];
    __syncthreads();
    #pragma unroll
    for (int i = 0; i < 32; i += 8) {
        const int n = n0 + ly + i;
        const float mx = fmaxf(__uint_as_float(bits[n]), 1e-30f);
        const float inv = 127.f / mx;
        const float v = t[lx][ly + i];
        int d1, d2;
        digits2(v * inv, d1, d2);
        const size_t o = (size_t)n * DMODEL + k0 + lx;
        B1[o] = (int8_t)d1;
        B2[o] = (int8_t)d2;
    }
}

// per-row quant of a [rows, 1024] fp32 matrix into digits + scale
__global__ __launch_bounds__(256)
void rowquant_kernel(const float* __restrict__ src,
                     int8_t* __restrict__ D1, int8_t* __restrict__ D2,
                     float* __restrict__ s)
{
    const int row = blockIdx.x;
    const int tid = threadIdx.x;
    const float4 v = ((const float4*)(src + (size_t)row * DMODEL))[tid];
    float m = fmaxf(fmaxf(fabsf(v.x), fabsf(v.y)), fmaxf(fabsf(v.z), fabsf(v.w)));
    #pragma unroll
    for (int o = 16; o >= 1; o >>= 1)
        m = fmaxf(m, __shfl_xor_sync(0xffffffffu, m, o));
    __shared__ float red[8];
    if ((tid & 31) == 0) red[tid >> 5] = m;
    __syncthreads();
    float mm = red[0];
    #pragma unroll
    for (int i = 1; i < 8; i++) mm = fmaxf(mm, red[i]);
    mm = fmaxf(mm, 1e-30f);
    if (tid == 0) s[row] = mm * (1.f / 127.f);
    const float inv = 127.f / mm;
    int d1, d2;
    char4 c1, c2;
    digits2(v.x * inv, d1, d2); c1.x = (char)d1; c2.x = (char)d2;
    digits2(v.y * inv, d1, d2); c1.y = (char)d1; c2.y = (char)d2;
    digits2(v.z * inv, d1, d2); c1.z = (char)d1; c2.z = (char)d2;
    digits2(v.w * inv, d1, d2); c1.w = (char)d1; c2.w = (char)d2;
    ((char4*)(D1 + (size_t)row * DMODEL))[tid] = c1;
    ((char4*)(D2 + (size_t)row * DMODEL))[tid] = c2;
}

// ======================= int8 dual-digit GEMM =======================
// C[m,n] = sA[m]*sB[n]*(acc1 + acc2/254) + bias[n]
// A digits [M,K] int8 row-major, B digits [N,K] int8 row-major (both K-major).
// CTA 128x128, BK=64 int8, 8 warps (4m x 2n -> 32x64), 2-stage cp.async.
#define QBK 64
#define QNCH (DMODEL / QBK)            // 16
#define QROWB 80                        // 64B data + 16B pad
#define QARR_B (128 * QROWB)            // 10240
#define QSTAGE_B (4 * QARR_B)           // 40960
#define QGEMM_SMEM (2 * QSTAGE_B)       // 81920

__global__ __launch_bounds__(256, 1)
void gemm_s8_kernel(const int8_t* __restrict__ A1, const int8_t* __restrict__ A2,
                    const float* __restrict__ sA,
                    const int8_t* __restrict__ B1, const int8_t* __restrict__ B2,
                    const unsigned* __restrict__ sBbits,
                    const float* __restrict__ bias,
                    float* __restrict__ C,
                    __nv_bfloat16* __restrict__ Chi, __nv_bfloat16* __restrict__ Clo,
                    int mode, float scale)
{
    extern __shared__ char sm[];
    const uint32_t sbase = smem_u32(sm);

    const int tid  = threadIdx.x;
    const int lane = tid & 31;
    const int wid  = tid >> 5;
    const int mw0  = (wid & 3) * 32;
    const int nw0  = (wid >> 2) * 64;
    const int bm   = blockIdx.y * 128;
    const int bn   = blockIdx.x * 128;

    const int8_t* srcs[4] = {
        A1 + (size_t)bm * DMODEL, A2 + (size_t)bm * DMODEL,
        B1 + (size_t)bn * DMODEL, B2 + (size_t)bn * DMODEL
    };

    int acc1[2][8][4], acc2[2][8][4];
    #pragma unroll
    for (int i = 0; i < 2; i++)
        #pragma unroll
        for (int j = 0; j < 8; j++)
            #pragma unroll
            for (int q = 0; q < 4; q++) { acc1[i][j][q] = 0; acc2[i][j][q] = 0; }

    // ldmatrix lane address components (bytes)
    const int a_row = lane & 15;
    const int a_kb  = (lane >> 4) * 16;
    const int b_row = ((lane >> 4) << 3) + (lane & 7);
    const int b_kb  = ((lane >> 3) & 1) * 16;

    auto issue_loads = [&](int c, int stage) {
        const int k0 = c * QBK;
        const uint32_t sb = sbase + stage * QSTAGE_B;
        #pragma unroll
        for (int t = 0; t < 4; t++) {
            #pragma unroll
            for (int jj = 0; jj < 2; jj++) {
                const int slot = tid + jj * 256;
                const int row = slot >> 2, col = slot & 3;
                cp16(sb + t * QARR_B + row * QROWB + col * 16,
                     srcs[t] + (size_t)row * DMODEL + k0 + col * 16);
            }
        }
    };

    issue_loads(0, 0);
    cp_commit();

    for (int c = 0; c < QNCH; ++c) {
        const int stage = c & 1;
        const bool hasNext = (c + 1 < QNCH);
        if (hasNext) { issue_loads(c + 1, stage ^ 1); cp_commit(); }
        if (hasNext) cp_wait1(); else cp_wait0();
        __syncthreads();

        const uint32_t sb = sbase + stage * QSTAGE_B;

        #pragma unroll
        for (int ks = 0; ks < 2; ++ks) {
            const int kb = ks * 32;   // byte offset of this k32 step
            uint32_t fa1[2][4], fa2[2][4];
            #pragma unroll
            for (int mi = 0; mi < 2; ++mi) {
                const uint32_t aoff = (uint32_t)(mw0 + mi * 16 + a_row) * QROWB + kb + a_kb;
                ldsm_x4(fa1[mi], sb + 0 * QARR_B + aoff);
                ldsm_x4(fa2[mi], sb + 1 * QARR_B + aoff);
            }
            #pragma unroll
            for (int nt2 = 0; nt2 < 4; ++nt2) {
                const uint32_t boff = (uint32_t)(nw0 + nt2 * 16 + b_row) * QROWB + kb + b_kb;
                uint32_t fb1[4], fb2[4];
                ldsm_x4(fb1, sb + 2 * QARR_B + boff);
                ldsm_x4(fb2, sb + 3 * QARR_B + boff);
                #pragma unroll
                for (int mi = 0; mi < 2; ++mi) {
                    #pragma unroll
                    for (int half = 0; half < 2; ++half) {
                        mma_s8(acc1[mi][nt2 * 2 + half], fa1[mi], fb1 + half * 2);
                        mma_s8(acc2[mi][nt2 * 2 + half], fa1[mi], fb2 + half * 2);
                        mma_s8(acc2[mi][nt2 * 2 + half], fa2[mi], fb1 + half * 2);
                    }
                }
            }
        }
        __syncthreads();
    }

    // ---- epilogue ----
    const int erow = lane >> 2;
    const int ecol = (lane & 3) * 2;
    #pragma unroll
    for (int mi = 0; mi < 2; ++mi) {
        const int m0 = bm + mw0 + mi * 16 + erow;
        const float sa0 = sA[m0], sa8 = sA[m0 + 8];
        #pragma unroll
        for (int ni = 0; ni < 8; ++ni) {
            const int n = bn + nw0 + ni * 8 + ecol;
            const float sb0 = fmaxf(__uint_as_float(sBbits[n]),     1e-30f) * (1.f / 127.f);
            const float sb1 = fmaxf(__uint_as_float(sBbits[n + 1]), 1e-30f) * (1.f / 127.f);
            const float b0 = bias[n], b1 = bias[n + 1];
            const float c00 = ((float)acc1[mi][ni][0] + (float)acc2[mi][ni][0] * (1.f / 254.f)) * (sa0 * sb0) + b0;
            const float c01 = ((float)acc1[mi][ni][1] + (float)acc2[mi][ni][1] * (1.f / 254.f)) * (sa0 * sb1) + b1;
            const float c10 = ((float)acc1[mi][ni][2] + (float)acc2[mi][ni][2] * (1.f / 254.f)) * (sa8 * sb0) + b0;
            const float c11 = ((float)acc1[mi][ni][3] + (float)acc2[mi][ni][3] * (1.f / 254.f)) * (sa8 * sb1) + b1;
            if (mode == 0) {
                float2 v0 = { c00, c01 }, v1 = { c10, c11 };
                *(float2*)(C + (size_t)m0 * DMODEL + n)       = v0;
                *(float2*)(C + (size_t)(m0 + 8) * DMODEL + n) = v1;
            } else {
                uint32_t H, L;
                pack2(c00 * scale, c01 * scale, H, L);
                *(uint32_t*)(Chi + (size_t)m0 * DMODEL + n) = H;
                *(uint32_t*)(Clo + (size_t)m0 * DMODEL + n) = L;
                pack2(c10 * scale, c11 * scale, H, L);
                *(uint32_t*)(Chi + (size_t)(m0 + 8) * DMODEL + n) = H;
                *(uint32_t*)(Clo + (size_t)(m0 + 8) * DMODEL + n) = L;
            }
        }
    }
}

// ======================= HMMA flash attention (bf16 hi/lo x3) =======================
#define KVROW 72
#define KVARR_B (128 * KVROW * 2)
#define ATT_SMEM (8 * KVARR_B)

__global__ __launch_bounds__(256, 1)
void attn_hmma_kernel()
{
    extern __shared__ __nv_bfloat16 smb[];
    const uint32_t sbase = smem_u32(smb);

    const int tid  = threadIdx.x;
    const int lane = tid & 31;
    const int w    = tid >> 5;
    const int h    = blockIdx.y;
    const int qt   = (int)gridDim.x - 1 - (int)blockIdx.x;
    const int q0   = qt * 128;
    const int hoff = h * DK;
    const int q0w  = q0 + w * 16;

    const int r  = lane >> 2;
    const int kc = (lane & 3) * 2;

    uint32_t qhf[4][4], qlf[4][4];
    #pragma unroll
    for (int ks = 0; ks < 4; ++ks) {
        const size_t rowA = (size_t)(q0w + r) * DMODEL + hoff + ks * 16 + kc;
        const size_t rowB = (size_t)(q0w + r + 8) * DMODEL + hoff + ks * 16 + kc;
        qhf[ks][0] = *(const uint32_t*)(g_qh + rowA);
        qhf[ks][1] = *(const uint32_t*)(g_qh + rowB);
        qhf[ks][2] = *(const uint32_t*)(g_qh + rowA + 8);
        qhf[ks][3] = *(const uint32_t*)(g_qh + rowB + 8);
        qlf[ks][0] = *(const uint32_t*)(g_ql + rowA);
        qlf[ks][1] = *(const uint32_t*)(g_ql + rowB);
        qlf[ks][2] = *(const uint32_t*)(g_ql + rowA + 8);
        qlf[ks][3] = *(const uint32_t*)(g_ql + rowB + 8);
    }

    auto issue_kv = [&](int kt, int buf) {
        const int k0 = kt * 128;
        const __nv_bfloat16* srcs[4] = { g_kh, g_kl, g_vh, g_vl };
        #pragma unroll
        for (int t = 0; t < 4; ++t) {
            const uint32_t sb = sbase + (buf * 4 + t) * KVARR_B;
            const __nv_bfloat16* src = srcs[t] + (size_t)k0 * DMODEL + hoff;
            #pragma unroll
            for (int j = 0; j < 4; ++j) {
                const int c = tid + j * 256;
                const int row = c >> 3, col = c & 7;
                cp16(sb + row * 144 + col * 16, src + (size_t)row * DMODEL + col * 8);
            }
        }
    };

    float m_[2] = { -1e30f, -1e30f }, l_[2] = { 0.f, 0.f };
    float oacc[8][4];
    #pragma unroll
    for (int i = 0; i < 8; i++)
        #pragma unroll
        for (int j = 0; j < 4; j++) oacc[i][j] = 0.f;

    issue_kv(0, 0);
    cp_commit();

    const uint32_t b_row = ((lane >> 4) << 3) + (lane & 7);
    const uint32_t b_k   = ((lane >> 3) & 1) * 8;
    const uint32_t vrow  = lane & 15;
    const uint32_t vcol  = (lane >> 4) * 8;

    for (int kt = 0; kt <= qt; ++kt) {
        const int buf = kt & 1;
        const bool hasNext = kt < qt;
        if (hasNext) { issue_kv(kt + 1, buf ^ 1); cp_commit(); }
        if (hasNext) cp_wait1(); else cp_wait0();
        __syncthreads();

        const uint32_t kh_b = sbase + (buf * 4 + 0) * KVARR_B;
        const uint32_t kl_b = sbase + (buf * 4 + 1) * KVARR_B;
        const uint32_t vh_b = sbase + (buf * 4 + 2) * KVARR_B;
        const uint32_t vl_b = sbase + (buf * 4 + 3) * KVARR_B;

        float s[16][4];
        #pragma unroll
        for (int i = 0; i < 16; i++)
            #pragma unroll
            for (int j = 0; j < 4; j++) s[i][j] = 0.f;

        #pragma unroll
        for (int ks = 0; ks < 4; ++ks) {
            #pragma unroll
            for (int nt2 = 0; nt2 < 8; ++nt2) {
                const uint32_t addr = (nt2 * 16 + b_row) * 144 + (ks * 16 + b_k) * 2;
                uint32_t bh[4], bl[4];
                ldsm_x4(bh, kh_b + addr);
                ldsm_x4(bl, kl_b + addr);
                #pragma unroll
                for (int hf = 0; hf < 2; ++hf) {
                    float* cc = s[nt2 * 2 + hf];
                    mma16816(cc, qhf[ks], bh + hf * 2);
                    mma16816(cc, qhf[ks], bl + hf * 2);
                    mma16816(cc, qlf[ks], bh + hf * 2);
                }
            }
        }

        if (kt == qt) {
            #pragma unroll
            for (int nt = 0; nt < 16; ++nt) {
                #pragma unroll
                for (int c = 0; c < 4; ++c) {
                    const int key = nt * 8 + kc + (c & 1);
                    const int qq  = w * 16 + r + (c >> 1) * 8;
                    if (key > qq) s[nt][c] = -1e30f;
                }
            }
        }

        float mx0 = -1e30f, mx1 = -1e30f;
        #pragma unroll
        for (int nt = 0; nt < 16; ++nt) {
            mx0 = fmaxf(mx0, fmaxf(s[nt][0], s[nt][1]));
            mx1 = fmaxf(mx1, fmaxf(s[nt][2], s[nt][3]));
        }
        mx0 = fmaxf(mx0, __shfl_xor_sync(0xffffffffu, mx0, 1));
        mx0 = fmaxf(mx0, __shfl_xor_sync(0xffffffffu, mx0, 2));
        mx1 = fmaxf(mx1, __shfl_xor_sync(0xffffffffu, mx1, 1));
        mx1 = fmaxf(mx1, __shfl_xor_sync(0xffffffffu, mx1, 2));

        const float nm0 = fmaxf(m_[0], mx0), nm1 = fmaxf(m_[1], mx1);
        const float al0 = __expf(m_[0] - nm0), al1 = __expf(m_[1] - nm1);
        float rs0 = 0.f, rs1 = 0.f;
        #pragma unroll
        for (int nt = 0; nt < 16; ++nt) {
            s[nt][0] = __expf(s[nt][0] - nm0);
            s[nt][1] = __expf(s[nt][1] - nm0);
            s[nt][2] = __expf(s[nt][2] - nm1);
            s[nt][3] = __expf(s[nt][3] - nm1);
            rs0 += s[nt][0] + s[nt][1];
            rs1 += s[nt][2] + s[nt][3];
        }
        rs0 += __shfl_xor_sync(0xffffffffu, rs0, 1);
        rs0 += __shfl_xor_sync(0xffffffffu, rs0, 2);
        rs1 += __shfl_xor_sync(0xffffffffu, rs1, 1);
        rs1 += __shfl_xor_sync(0xffffffffu, rs1, 2);

        l_[0] = l_[0] * al0 + rs0;  m_[0] = nm0;
        l_[1] = l_[1] * al1 + rs1;  m_[1] = nm1;
        #pragma unroll
        for (int dt = 0; dt < 8; ++dt) {
            oacc[dt][0] *= al0; oacc[dt][1] *= al0;
            oacc[dt][2] *= al1; oacc[dt][3] *= al1;
        }

        #pragma unroll
        for (int j = 0; j < 8; ++j) {
            uint32_t pah[4], pal[4];
            pack2(s[2*j][0],   s[2*j][1],   pah[0], pal[0]);
            pack2(s[2*j][2],   s[2*j][3],   pah[1], pal[1]);
            pack2(s[2*j+1][0], s[2*j+1][1], pah[2], pal[2]);
            pack2(s[2*j+1][2], s[2*j+1][3], pah[3], pal[3]);

            const uint32_t abase = (j * 16 + vrow) * 144 + vcol * 2;
            #pragma unroll
            for (int dg = 0; dg < 4; ++dg) {
                const uint32_t a2 = abase + dg * 32;
                uint32_t bh[4], bl[4];
                ldsm_x4_t(bh, vh_b + a2);
                ldsm_x4_t(bl, vl_b + a2);
                #pragma unroll
                for (int hf = 0; hf < 2; ++hf) {
                    float* cc = oacc[dg * 2 + hf];
                    mma16816(cc, pah, bh + hf * 2);
                    mma16816(cc, pah, bl + hf * 2);
                    mma16816(cc, pal, bh + hf * 2);
                }
            }
        }
        __syncthreads();
    }

    // ---- epilogue: normalize, write fp32 ctx ----
    const float inv0 = 1.f / l_[0], inv1 = 1.f / l_[1];
    #pragma unroll
    for (int dt = 0; dt < 8; ++dt) {
        const size_t d = (size_t)hoff + dt * 8 + kc;
        const size_t rowA = (size_t)(q0w + r) * DMODEL + d;
        const size_t rowB = (size_t)(q0w + r + 8) * DMODEL + d;
        float2 a0 = { oacc[dt][0] * inv0, oacc[dt][1] * inv0 };
        float2 a1 = { oacc[dt][2] * inv1, oacc[dt][3] * inv1 };
        *(float2*)(g_ctx + rowA) = a0;
        *(float2*)(g_ctx + rowB) = a1;
    }
}

// ======================= host launcher =======================
extern "C" void kernel_launch(void* const* d_in, const int* in_sizes, int n_in,
                              void* d_out, int out_size)
{
    (void)in_sizes; (void)n_in; (void)out_size;
    const float* x  = (const float*)d_in[0];
    const float* Wq = (const float*)d_in[2];
    const float* bq = (const float*)d_in[3];
    const float* Wk = (const float*)d_in[4];
    const float* bk = (const float*)d_in[5];
    const float* Wv = (const float*)d_in[6];
    const float* bv = (const float*)d_in[7];
    const float* Wo = (const float*)d_in[8];
    const float* bo = (const float*)d_in[9];
    float* out = (float*)d_out;

    int8_t *x1, *x2, *c1, *c2;
    float *sx, *sc, *ctx;
    unsigned* wbits;
    int8_t *wq1, *wq2, *wk1, *wk2, *wv1, *wv2, *wo1, *wo2;
    __nv_bfloat16 *qh, *ql, *kh, *kl, *vh, *vl;

    cudaGetSymbolAddress((void**)&x1, g_x1);
    cudaGetSymbolAddress((void**)&x2, g_x2);
    cudaGetSymbolAddress((void**)&sx, g_sx);
    cudaGetSymbolAddress((void**)&c1, g_c1);
    cudaGetSymbolAddress((void**)&c2, g_c2);
    cudaGetSymbolAddress((void**)&sc, g_sc);
    cudaGetSymbolAddress((void**)&ctx, g_ctx);
    cudaGetSymbolAddress((void**)&wbits, g_wbits);
    cudaGetSymbolAddress((void**)&wq1, g_wq1);
    cudaGetSymbolAddress((void**)&wq2, g_wq2);
    cudaGetSymbolAddress((void**)&wk1, g_wk1);
    cudaGetSymbolAddress((void**)&wk2, g_wk2);
    cudaGetSymbolAddress((void**)&wv1, g_wv1);
    cudaGetSymbolAddress((void**)&wv2, g_wv2);
    cudaGetSymbolAddress((void**)&wo1, g_wo1);
    cudaGetSymbolAddress((void**)&wo2, g_wo2);
    cudaGetSymbolAddress((void**)&qh, g_qh);
    cudaGetSymbolAddress((void**)&ql, g_ql);
    cudaGetSymbolAddress((void**)&kh, g_kh);
    cudaGetSymbolAddress((void**)&kl, g_kl);
    cudaGetSymbolAddress((void**)&vh, g_vh);
    cudaGetSymbolAddress((void**)&vl, g_vl);

    // ---- quantization pre-pass ----
    zero_bits_kernel<<<4, 1024>>>(wbits);
    const dim3 cmg(8, 8);
    colmax_kernel<<<cmg, 256>>>(Wq, wbits + 0 * DMODEL);
    colmax_kernel<<<cmg, 256>>>(Wk, wbits + 1 * DMODEL);
    colmax_kernel<<<cmg, 256>>>(Wv, wbits + 2 * DMODEL);
    colmax_kernel<<<cmg, 256>>>(Wo, wbits + 3 * DMODEL);
    const dim3 tqg(32, 32);
    transpose_quant_kernel<<<tqg, 256>>>(Wq, wbits + 0 * DMODEL, wq1, wq2);
    transpose_quant_kernel<<<tqg, 256>>>(Wk, wbits + 1 * DMODEL, wk1, wk2);
    transpose_quant_kernel<<<tqg, 256>>>(Wv, wbits + 2 * DMODEL, wv1, wv2);
    transpose_quant_kernel<<<tqg, 256>>>(Wo, wbits + 3 * DMODEL, wo1, wo2);
    rowquant_kernel<<<S_LEN, 256>>>(x, x1, x2, sx);

    // ---- Q/K/V projections (int8 dual-digit) ----
    cudaFuncSetAttribute(gemm_s8_kernel,
                         cudaFuncAttributeMaxDynamicSharedMemorySize, QGEMM_SMEM);
    const dim3 ggrid(DMODEL / 128, S_LEN / 128);
    const float qscale = 0.125f;  // 1/sqrt(DK)
    gemm_s8_kernel<<<ggrid, 256, QGEMM_SMEM>>>(x1, x2, sx, wq1, wq2, wbits + 0 * DMODEL,
                                               bq, nullptr, qh, ql, 1, qscale);
    gemm_s8_kernel<<<ggrid, 256, QGEMM_SMEM>>>(x1, x2, sx, wk1, wk2, wbits + 1 * DMODEL,
                                               bk, nullptr, kh, kl, 1, 1.0f);
    gemm_s8_kernel<<<ggrid, 256, QGEMM_SMEM>>>(x1, x2, sx, wv1, wv2, wbits + 2 * DMODEL,
                                               bv, nullptr, vh, vl, 1, 1.0f);

    // ---- attention ----
    cudaFuncSetAttribute(attn_hmma_kernel,
                         cudaFuncAttributeMaxDynamicSharedMemorySize, ATT_SMEM);
    attn_hmma_kernel<<<dim3(S_LEN / 128, NHEADS), 256, ATT_SMEM>>>();

    // ---- O projection ----
    rowquant_kernel<<<S_LEN, 256>>>(ctx, c1, c2, sc);
    gemm_s8_kernel<<<ggrid, 256, QGEMM_SMEM>>>(c1, c2, sc, wo1, wo2, wbits + 3 * DMODEL,
                                               bo, out, nullptr, nullptr, 0, 1.0f);
}

// round 7
// speedup vs baseline: 3.2776x; 1.0166x over previous
#include <cuda_runtime.h>
#include <cuda_bf16.h>
#include <cstdint>
#include <math.h>

#define S_LEN  4096
#define DMODEL 1024
#define NHEADS 16
#define DK     64

// ======================= scratch (device globals) =======================
__device__ int8_t g_x1[(size_t)S_LEN * DMODEL];
__device__ int8_t g_x2[(size_t)S_LEN * DMODEL];
__device__ float  g_sx[S_LEN];

__device__ int8_t g_wq1[(size_t)DMODEL * DMODEL];
__device__ int8_t g_wq2[(size_t)DMODEL * DMODEL];
__device__ int8_t g_wk1[(size_t)DMODEL * DMODEL];
__device__ int8_t g_wk2[(size_t)DMODEL * DMODEL];
__device__ int8_t g_wv1[(size_t)DMODEL * DMODEL];
__device__ int8_t g_wv2[(size_t)DMODEL * DMODEL];
__device__ int8_t g_wo1[(size_t)DMODEL * DMODEL];
__device__ int8_t g_wo2[(size_t)DMODEL * DMODEL];
__device__ unsigned g_wbits[5 * DMODEL];   // col-max bits: Wq,Wk,Wv,Wo,V

// attention operands
__device__ int8_t g_q1[(size_t)S_LEN * DMODEL];
__device__ int8_t g_q2[(size_t)S_LEN * DMODEL];
__device__ int8_t g_k1[(size_t)S_LEN * DMODEL];
__device__ int8_t g_k2[(size_t)S_LEN * DMODEL];
__device__ float  g_sq[NHEADS * S_LEN];    // [head][token]
__device__ float  g_sk[NHEADS * S_LEN];    // [head][token]
__device__ float  g_vf[(size_t)S_LEN * DMODEL];      // V fp32
__device__ int8_t g_v1T[(size_t)DMODEL * S_LEN];     // V^T digits [col][token]
__device__ int8_t g_v2T[(size_t)DMODEL * S_LEN];
__device__ float  g_sv[DMODEL];                      // per-col V scale (max/127)

__device__ float  g_ctx[(size_t)S_LEN * DMODEL];
__device__ int8_t g_c1[(size_t)S_LEN * DMODEL];
__device__ int8_t g_c2[(size_t)S_LEN * DMODEL];
__device__ float  g_sc[S_LEN];

// ======================= helpers =======================
__device__ __forceinline__ uint32_t smem_u32(const void* p) {
    uint32_t a;
    asm("{ .reg .u64 t; cvta.to.shared.u64 t, %1; cvt.u32.u64 %0, t; }" : "=r"(a) : "l"(p));
    return a;
}
__device__ __forceinline__ void cp16(uint32_t saddr, const void* g) {
    asm volatile("cp.async.ca.shared.global [%0], [%1], 16;" :: "r"(saddr), "l"(g));
}
__device__ __forceinline__ void cp_commit() { asm volatile("cp.async.commit_group;"); }
__device__ __forceinline__ void cp_wait1()  { asm volatile("cp.async.wait_group 1;"); }
__device__ __forceinline__ void cp_wait0()  { asm volatile("cp.async.wait_group 0;"); }

__device__ __forceinline__ void ldsm_x4(uint32_t* r, uint32_t addr) {
    asm volatile("ldmatrix.sync.aligned.m8n8.x4.shared.b16 {%0,%1,%2,%3}, [%4];"
                 : "=r"(r[0]), "=r"(r[1]), "=r"(r[2]), "=r"(r[3]) : "r"(addr));
}
__device__ __forceinline__ void mma_s8(int* c, const uint32_t* a, const uint32_t* b) {
    asm volatile(
        "mma.sync.aligned.m16n8k32.row.col.s32.s8.s8.s32 "
        "{%0,%1,%2,%3}, {%4,%5,%6,%7}, {%8,%9}, {%0,%1,%2,%3};"
        : "+r"(c[0]), "+r"(c[1]), "+r"(c[2]), "+r"(c[3])
        : "r"(a[0]), "r"(a[1]), "r"(a[2]), "r"(a[3]), "r"(b[0]), "r"(b[1]));
}
__device__ __forceinline__ void digits2(float alpha, int& d1, int& d2) {
    d1 = __float2int_rn(alpha);
    d2 = __float2int_rn((alpha - (float)d1) * 254.f);
}
// pack two values' digit-1 into u16 (returns), digit-2 into w2
__device__ __forceinline__ uint32_t pack_dig(float a, float b, uint32_t& w2) {
    int a1, a2, b1, b2;
    digits2(a, a1, a2);
    digits2(b, b1, b2);
    w2 = (uint32_t)(a2 & 0xff) | (((uint32_t)(b2 & 0xff)) << 8);
    return (uint32_t)(a1 & 0xff) | (((uint32_t)(b1 & 0xff)) << 8);
}

// ======================= quantization pre-pass =======================
__global__ void zero_bits_kernel(unsigned* b) { b[blockIdx.x * 1024 + threadIdx.x] = 0u; }

// batched column-max over the 4 weight matrices. grid (8,8,4), 256 thr.
__global__ __launch_bounds__(256)
void colmax4_kernel(const float* __restrict__ W0, const float* __restrict__ W1,
                    const float* __restrict__ W2, const float* __restrict__ W3,
                    unsigned* __restrict__ bits)
{
    const float* W = (blockIdx.z == 0) ? W0 : (blockIdx.z == 1) ? W1 : (blockIdx.z == 2) ? W2 : W3;
    unsigned* b = bits + blockIdx.z * DMODEL;
    const int c  = blockIdx.x * 128 + (threadIdx.x & 127);
    const int r0 = blockIdx.y * 128 + (threadIdx.x >> 7);
    const int re = blockIdx.y * 128 + 128;
    float m = 0.f;
    #pragma unroll 8
    for (int r = r0; r < re; r += 2)
        m = fmaxf(m, fabsf(W[(size_t)r * DMODEL + c]));
    atomicMax(b + c, __float_as_uint(m));
}

// generic column max (used for V fp32, 4096 rows): grid (8, rows/128)
__global__ __launch_bounds__(256)
void colmax_kernel(const float* __restrict__ W, unsigned* __restrict__ bits)
{
    const int c  = blockIdx.x * 128 + (threadIdx.x & 127);
    const int r0 = blockIdx.y * 128 + (threadIdx.x >> 7);
    const int re = blockIdx.y * 128 + 128;
    float m = 0.f;
    #pragma unroll 8
    for (int r = r0; r < re; r += 2)
        m = fmaxf(m, fabsf(W[(size_t)r * DMODEL + c]));
    atomicMax(bits + c, __float_as_uint(m));
}

// batched transpose+quant of the 4 weights: W [K,N] -> [N,K] digits. grid (32,32,4)
__global__ __launch_bounds__(256)
void transpose_quant4_kernel(const float* __restrict__ W0, const float* __restrict__ W1,
                             const float* __restrict__ W2, const float* __restrict__ W3,
                             const unsigned* __restrict__ bits,
                             int8_t* __restrict__ O10, int8_t* __restrict__ O20,
                             int8_t* __restrict__ O11, int8_t* __restrict__ O21,
                             int8_t* __restrict__ O12, int8_t* __restrict__ O22,
                             int8_t* __restrict__ O13, int8_t* __restrict__ O23)
{
    const int z = blockIdx.z;
    const float* W = (z == 0) ? W0 : (z == 1) ? W1 : (z == 2) ? W2 : W3;
    int8_t* B1 = (z == 0) ? O10 : (z == 1) ? O11 : (z == 2) ? O12 : O13;
    int8_t* B2 = (z == 0) ? O20 : (z == 1) ? O21 : (z == 2) ? O22 : O23;
    const unsigned* b = bits + z * DMODEL;

    __shared__ float t[32][33];
    const int n0 = blockIdx.x * 32, k0 = blockIdx.y * 32;
    const int lx = threadIdx.x & 31, ly = threadIdx.x >> 5;
    #pragma unroll
    for (int i = 0; i < 32; i += 8)
        t[ly + i][lx] = W[(size_t)(k0 + ly + i) * DMODEL + n0 + lx];
    __syncthreads();
    #pragma unroll
    for (int i = 0; i < 32; i += 8) {
        const int n = n0 + ly + i;
        const float mx = fmaxf(__uint_as_float(b[n]), 1e-30f);
        const float inv = 127.f / mx;
        int d1, d2;
        digits2(t[lx][ly + i] * inv, d1, d2);
        const size_t o = (size_t)n * DMODEL + k0 + lx;
        B1[o] = (int8_t)d1;
        B2[o] = (int8_t)d2;
    }
}

// V fp32 [token, col] -> V^T digits [col, token] with per-col scale. grid (32, 128)
__global__ __launch_bounds__(256)
void vprep_kernel(const float* __restrict__ V, const unsigned* __restrict__ bits,
                  int8_t* __restrict__ T1, int8_t* __restrict__ T2,
                  float* __restrict__ sv)
{
    __shared__ float t[32][33];
    const int c0 = blockIdx.x * 32, t0 = blockIdx.y * 32;
    const int lx = threadIdx.x & 31, ly = threadIdx.x >> 5;
    #pragma unroll
    for (int i = 0; i < 32; i += 8)
        t[ly + i][lx] = V[(size_t)(t0 + ly + i) * DMODEL + c0 + lx];
    __syncthreads();
    #pragma unroll
    for (int i = 0; i < 32; i += 8) {
        const int c = c0 + ly + i;
        const float mx = fmaxf(__uint_as_float(bits[c]), 1e-30f);
        if (blockIdx.y == 0 && lx == 0) sv[c] = mx * (1.f / 127.f);
        const float inv = 127.f / mx;
        int d1, d2;
        digits2(t[lx][ly + i] * inv, d1, d2);
        const size_t o = (size_t)c * S_LEN + t0 + lx;
        T1[o] = (int8_t)d1;
        T2[o] = (int8_t)d2;
    }
}

// per-row quant of a [rows,1024] fp32 matrix -> digits + scale
__global__ __launch_bounds__(256)
void rowquant_kernel(const float* __restrict__ src,
                     int8_t* __restrict__ D1, int8_t* __restrict__ D2,
                     float* __restrict__ s)
{
    const int row = blockIdx.x;
    const int tid = threadIdx.x;
    const float4 v = ((const float4*)(src + (size_t)row * DMODEL))[tid];
    float m = fmaxf(fmaxf(fabsf(v.x), fabsf(v.y)), fmaxf(fabsf(v.z), fabsf(v.w)));
    #pragma unroll
    for (int o = 16; o >= 1; o >>= 1)
        m = fmaxf(m, __shfl_xor_sync(0xffffffffu, m, o));
    __shared__ float red[8];
    if ((tid & 31) == 0) red[tid >> 5] = m;
    __syncthreads();
    float mm = red[0];
    #pragma unroll
    for (int i = 1; i < 8; i++) mm = fmaxf(mm, red[i]);
    mm = fmaxf(mm, 1e-30f);
    if (tid == 0) s[row] = mm * (1.f / 127.f);
    const float inv = 127.f / mm;
    int d1, d2;
    char4 c1, c2;
    digits2(v.x * inv, d1, d2); c1.x = (char)d1; c2.x = (char)d2;
    digits2(v.y * inv, d1, d2); c1.y = (char)d1; c2.y = (char)d2;
    digits2(v.z * inv, d1, d2); c1.z = (char)d1; c2.z = (char)d2;
    digits2(v.w * inv, d1, d2); c1.w = (char)d1; c2.w = (char)d2;
    ((char4*)(D1 + (size_t)row * DMODEL))[tid] = c1;
    ((char4*)(D2 + (size_t)row * DMODEL))[tid] = c2;
}

// ======================= int8 dual-digit GEMM =======================
// mode 0: fp32 out C + bias.
// mode 2: per-(row,head) quantized int8 digit output + scale (scale *= smul).
#define QBK 64
#define QNCH (DMODEL / QBK)
#define QROWB 80
#define QARR_B (128 * QROWB)
#define QSTAGE_B (4 * QARR_B)
#define QGEMM_SMEM (2 * QSTAGE_B)

__global__ __launch_bounds__(256, 1)
void gemm_s8_kernel(const int8_t* __restrict__ A1, const int8_t* __restrict__ A2,
                    const float* __restrict__ sA,
                    const int8_t* __restrict__ B1, const int8_t* __restrict__ B2,
                    const unsigned* __restrict__ sBbits,
                    const float* __restrict__ bias,
                    float* __restrict__ C,
                    int8_t* __restrict__ D1, int8_t* __restrict__ D2,
                    float* __restrict__ sOut,
                    int mode, float smul)
{
    extern __shared__ char sm[];
    const uint32_t sbase = smem_u32(sm);

    const int tid  = threadIdx.x;
    const int lane = tid & 31;
    const int wid  = tid >> 5;
    const int mw0  = (wid & 3) * 32;
    const int nw0  = (wid >> 2) * 64;
    const int bm   = blockIdx.y * 128;
    const int bn   = blockIdx.x * 128;

    const int8_t* srcs[4] = {
        A1 + (size_t)bm * DMODEL, A2 + (size_t)bm * DMODEL,
        B1 + (size_t)bn * DMODEL, B2 + (size_t)bn * DMODEL
    };

    int acc1[2][8][4], acc2[2][8][4];
    #pragma unroll
    for (int i = 0; i < 2; i++)
        #pragma unroll
        for (int j = 0; j < 8; j++)
            #pragma unroll
            for (int q = 0; q < 4; q++) { acc1[i][j][q] = 0; acc2[i][j][q] = 0; }

    const int a_row = lane & 15;
    const int a_kb  = (lane >> 4) * 16;
    const int b_row = ((lane >> 4) << 3) + (lane & 7);
    const int b_kb  = ((lane >> 3) & 1) * 16;

    auto issue_loads = [&](int c, int stage) {
        const int k0 = c * QBK;
        const uint32_t sb = sbase + stage * QSTAGE_B;
        #pragma unroll
        for (int t = 0; t < 4; t++) {
            #pragma unroll
            for (int jj = 0; jj < 2; jj++) {
                const int slot = tid + jj * 256;
                const int row = slot >> 2, col = slot & 3;
                cp16(sb + t * QARR_B + row * QROWB + col * 16,
                     srcs[t] + (size_t)row * DMODEL + k0 + col * 16);
            }
        }
    };

    issue_loads(0, 0);
    cp_commit();

    for (int c = 0; c < QNCH; ++c) {
        const int stage = c & 1;
        const bool hasNext = (c + 1 < QNCH);
        if (hasNext) { issue_loads(c + 1, stage ^ 1); cp_commit(); }
        if (hasNext) cp_wait1(); else cp_wait0();
        __syncthreads();

        const uint32_t sb = sbase + stage * QSTAGE_B;

        #pragma unroll
        for (int ks = 0; ks < 2; ++ks) {
            const int kb = ks * 32;
            uint32_t fa1[2][4], fa2[2][4];
            #pragma unroll
            for (int mi = 0; mi < 2; ++mi) {
                const uint32_t aoff = (uint32_t)(mw0 + mi * 16 + a_row) * QROWB + kb + a_kb;
                ldsm_x4(fa1[mi], sb + 0 * QARR_B + aoff);
                ldsm_x4(fa2[mi], sb + 1 * QARR_B + aoff);
            }
            #pragma unroll
            for (int nt2 = 0; nt2 < 4; ++nt2) {
                const uint32_t boff = (uint32_t)(nw0 + nt2 * 16 + b_row) * QROWB + kb + b_kb;
                uint32_t fb1[4], fb2[4];
                ldsm_x4(fb1, sb + 2 * QARR_B + boff);
                ldsm_x4(fb2, sb + 3 * QARR_B + boff);
                #pragma unroll
                for (int mi = 0; mi < 2; ++mi) {
                    #pragma unroll
                    for (int half = 0; half < 2; ++half) {
                        mma_s8(acc1[mi][nt2 * 2 + half], fa1[mi], fb1 + half * 2);
                        mma_s8(acc2[mi][nt2 * 2 + half], fa1[mi], fb2 + half * 2);
                        mma_s8(acc2[mi][nt2 * 2 + half], fa2[mi], fb1 + half * 2);
                    }
                }
            }
        }
        __syncthreads();
    }

    // ---- epilogue ----
    const int erow = lane >> 2;
    const int ecol = (lane & 3) * 2;
    if (mode == 0) {
        #pragma unroll
        for (int mi = 0; mi < 2; ++mi) {
            const int m0 = bm + mw0 + mi * 16 + erow;
            const float sa0 = sA[m0], sa8 = sA[m0 + 8];
            #pragma unroll
            for (int ni = 0; ni < 8; ++ni) {
                const int n = bn + nw0 + ni * 8 + ecol;
                const float sb0 = fmaxf(__uint_as_float(sBbits[n]),     1e-30f) * (1.f / 127.f);
                const float sb1 = fmaxf(__uint_as_float(sBbits[n + 1]), 1e-30f) * (1.f / 127.f);
                const float b0 = bias[n], b1 = bias[n + 1];
                float2 v0, v1;
                v0.x = ((float)acc1[mi][ni][0] + (float)acc2[mi][ni][0] * (1.f / 254.f)) * (sa0 * sb0) + b0;
                v0.y = ((float)acc1[mi][ni][1] + (float)acc2[mi][ni][1] * (1.f / 254.f)) * (sa0 * sb1) + b1;
                v1.x = ((float)acc1[mi][ni][2] + (float)acc2[mi][ni][2] * (1.f / 254.f)) * (sa8 * sb0) + b0;
                v1.y = ((float)acc1[mi][ni][3] + (float)acc2[mi][ni][3] * (1.f / 254.f)) * (sa8 * sb1) + b1;
                *(float2*)(C + (size_t)m0 * DMODEL + n)       = v0;
                *(float2*)(C + (size_t)(m0 + 8) * DMODEL + n) = v1;
            }
        }
    } else {
        const int head = (bn + nw0) >> 6;   // 64 cols per head; warp covers one head
        #pragma unroll
        for (int mi = 0; mi < 2; ++mi) {
            const int m0 = bm + mw0 + mi * 16 + erow;
            const float sa0 = sA[m0], sa8 = sA[m0 + 8];
            float v0[16], v1[16];
            #pragma unroll
            for (int ni = 0; ni < 8; ++ni) {
                const int n = bn + nw0 + ni * 8 + ecol;
                const float sb0 = fmaxf(__uint_as_float(sBbits[n]),     1e-30f) * (1.f / 127.f);
                const float sb1 = fmaxf(__uint_as_float(sBbits[n + 1]), 1e-30f) * (1.f / 127.f);
                const float b0 = bias[n], b1 = bias[n + 1];
                v0[ni * 2 + 0] = ((float)acc1[mi][ni][0] + (float)acc2[mi][ni][0] * (1.f / 254.f)) * (sa0 * sb0) + b0;
                v0[ni * 2 + 1] = ((float)acc1[mi][ni][1] + (float)acc2[mi][ni][1] * (1.f / 254.f)) * (sa0 * sb1) + b1;
                v1[ni * 2 + 0] = ((float)acc1[mi][ni][2] + (float)acc2[mi][ni][2] * (1.f / 254.f)) * (sa8 * sb0) + b0;
                v1[ni * 2 + 1] = ((float)acc1[mi][ni][3] + (float)acc2[mi][ni][3] * (1.f / 254.f)) * (sa8 * sb1) + b1;
            }
            float mx0 = 0.f, mx1 = 0.f;
            #pragma unroll
            for (int i = 0; i < 16; i++) {
                mx0 = fmaxf(mx0, fabsf(v0[i]));
                mx1 = fmaxf(mx1, fabsf(v1[i]));
            }
            mx0 = fmaxf(mx0, __shfl_xor_sync(0xffffffffu, mx0, 1));
            mx0 = fmaxf(mx0, __shfl_xor_sync(0xffffffffu, mx0, 2));
            mx1 = fmaxf(mx1, __shfl_xor_sync(0xffffffffu, mx1, 1));
            mx1 = fmaxf(mx1, __shfl_xor_sync(0xffffffffu, mx1, 2));
            mx0 = fmaxf(mx0, 1e-20f);
            mx1 = fmaxf(mx1, 1e-20f);
            if ((lane & 3) == 0) {
                sOut[head * S_LEN + m0]     = mx0 * (smul / 127.f);
                sOut[head * S_LEN + m0 + 8] = mx1 * (smul / 127.f);
            }
            const float i0 = 127.f / mx0, i1 = 127.f / mx1;
            #pragma unroll
            for (int ni = 0; ni < 8; ++ni) {
                const int n = bn + nw0 + ni * 8 + ecol;
                uint32_t w2;
                uint32_t w1 = pack_dig(v0[ni * 2] * i0, v0[ni * 2 + 1] * i0, w2);
                *(uint16_t*)(D1 + (size_t)m0 * DMODEL + n) = (uint16_t)w1;
                *(uint16_t*)(D2 + (size_t)m0 * DMODEL + n) = (uint16_t)w2;
                w1 = pack_dig(v1[ni * 2] * i1, v1[ni * 2 + 1] * i1, w2);
                *(uint16_t*)(D1 + (size_t)(m0 + 8) * DMODEL + n) = (uint16_t)w1;
                *(uint16_t*)(D2 + (size_t)(m0 + 8) * DMODEL + n) = (uint16_t)w2;
            }
        }
    }
}

// ======================= int8 flash attention =======================
// CTA = (head, 128-query tile), 8 warps x 16 query rows, KV tiles of 128 keys.
#define AK_ROWB 80
#define AK_B (128 * AK_ROWB)            // 10240 per K digit
#define AV_ROWB 144
#define AV_B (64 * AV_ROWB)             // 9216 per V digit
#define ASK_OFF (2 * AK_B + 2 * AV_B)   // 38912
#define ABUF_B (ASK_OFF + 512)          // 39424
#define AP_ROWB 144
#define AP_B (128 * AP_ROWB)            // 18432 per P digit
#define AP_OFF (2 * ABUF_B)             // 78848
#define ATT_SMEM (AP_OFF + 2 * AP_B)    // 115712

__global__ __launch_bounds__(256, 1)
void attn_s8_kernel()
{
    extern __shared__ char sm[];
    const uint32_t sbase = smem_u32(sm);

    const int tid  = threadIdx.x;
    const int lane = tid & 31;
    const int w    = tid >> 5;
    const int h    = blockIdx.y;
    const int qt   = (int)gridDim.x - 1 - (int)blockIdx.x;
    const int q0   = qt * 128;
    const int hoff = h * DK;
    const int q0w  = q0 + w * 16;

    const int r  = lane >> 2;
    const int kc = (lane & 3) * 2;

    // ---- Q A-fragments (int8 digits) held in regs ----
    uint32_t q1f[2][4], q2f[2][4];
    {
        const int qb = (lane & 3) * 4;
        #pragma unroll
        for (int g = 0; g < 2; ++g) {
            const size_t bA = (size_t)(q0w + r) * DMODEL + hoff + g * 32 + qb;
            const size_t bB = (size_t)(q0w + r + 8) * DMODEL + hoff + g * 32 + qb;
            q1f[g][0] = *(const uint32_t*)(g_q1 + bA);
            q1f[g][1] = *(const uint32_t*)(g_q1 + bB);
            q1f[g][2] = *(const uint32_t*)(g_q1 + bA + 16);
            q1f[g][3] = *(const uint32_t*)(g_q1 + bB + 16);
            q2f[g][0] = *(const uint32_t*)(g_q2 + bA);
            q2f[g][1] = *(const uint32_t*)(g_q2 + bB);
            q2f[g][2] = *(const uint32_t*)(g_q2 + bA + 16);
            q2f[g][3] = *(const uint32_t*)(g_q2 + bB + 16);
        }
    }
    const float sq0f = g_sq[h * S_LEN + q0w + r]     * (1.f / 254.f);
    const float sq1f = g_sq[h * S_LEN + q0w + r + 8] * (1.f / 254.f);

    // ---- per-d V scale regs ----
    float svf[8][2];
    #pragma unroll
    for (int dt = 0; dt < 8; ++dt) {
        const float2 t = *(const float2*)(g_sv + hoff + dt * 8 + kc);
        svf[dt][0] = t.x * (1.f / (127.f * 254.f));
        svf[dt][1] = t.y * (1.f / (127.f * 254.f));
    }

    auto issue_kv = [&](int kt, int buf) {
        const int k0 = kt * 128;
        const uint32_t sb = sbase + buf * ABUF_B;
        const int8_t* ks[2] = { g_k1, g_k2 };
        const int8_t* vs[2] = { g_v1T, g_v2T };
        #pragma unroll
        for (int d = 0; d < 2; ++d) {
            #pragma unroll
            for (int j = 0; j < 2; ++j) {
                const int slot = tid + j * 256;
                const int row = slot >> 2, col = slot & 3;
                cp16(sb + d * AK_B + row * AK_ROWB + col * 16,
                     ks[d] + (size_t)(k0 + row) * DMODEL + hoff + col * 16);
            }
        }
        #pragma unroll
        for (int d = 0; d < 2; ++d) {
            #pragma unroll
            for (int j = 0; j < 2; ++j) {
                const int slot = tid + j * 256;
                const int row = slot >> 3, col = slot & 7;
                cp16(sb + 2 * AK_B + d * AV_B + row * AV_ROWB + col * 16,
                     vs[d] + (size_t)(hoff + row) * S_LEN + k0 + col * 16);
            }
        }
        if (tid < 32)
            cp16(sb + ASK_OFF + tid * 16, g_sk + h * S_LEN + k0 + tid * 4);
    };

    float m_[2] = { -1e30f, -1e30f }, l_[2] = { 0.f, 0.f };
    float oacc[8][4];
    #pragma unroll
    for (int i = 0; i < 8; i++)
        #pragma unroll
        for (int j = 0; j < 4; j++) oacc[i][j] = 0.f;

    issue_kv(0, 0);
    cp_commit();

    const uint32_t b_off  = (uint32_t)(((lane >> 4) << 3) + (lane & 7));
    const uint32_t kb_off = ((lane >> 3) & 1) * 16;
    const uint32_t p_row  = (uint32_t)(w * 16 + (lane & 15)) * AP_ROWB + (lane >> 4) * 16;

    for (int kt = 0; kt <= qt; ++kt) {
        const int buf = kt & 1;
        const bool hasNext = kt < qt;
        if (hasNext) { issue_kv(kt + 1, buf ^ 1); cp_commit(); }
        if (hasNext) cp_wait1(); else cp_wait0();
        __syncthreads();

        const uint32_t k1b = sbase + buf * ABUF_B;
        const uint32_t k2b = k1b + AK_B;
        const uint32_t v1b = k1b + 2 * AK_B;
        const uint32_t v2b = v1b + AV_B;
        const float* sks = (const float*)(sm + buf * ABUF_B + ASK_OFF);

        // ---- S = Q @ K^T (dual-digit int8) ----
        float s[16][4];
        #pragma unroll
        for (int nt2 = 0; nt2 < 8; ++nt2) {
            int a1[2][4] = { {0,0,0,0}, {0,0,0,0} };
            int a2[2][4] = { {0,0,0,0}, {0,0,0,0} };
            #pragma unroll
            for (int g = 0; g < 2; ++g) {
                const uint32_t addr = (uint32_t)(nt2 * 16 + b_off) * AK_ROWB + g * 32 + kb_off;
                uint32_t fb1[4], fb2[4];
                ldsm_x4(fb1, k1b + addr);
                ldsm_x4(fb2, k2b + addr);
                #pragma unroll
                for (int hf = 0; hf < 2; ++hf) {
                    mma_s8(a1[hf], q1f[g], fb1 + hf * 2);
                    mma_s8(a2[hf], q1f[g], fb2 + hf * 2);
                    mma_s8(a2[hf], q2f[g], fb1 + hf * 2);
                }
            }
            #pragma unroll
            for (int hf = 0; hf < 2; ++hf) {
                const float2 sk2 = *(const float2*)(sks + (nt2 * 2 + hf) * 8 + kc);
                const float t00 = sq0f * sk2.x, t01 = sq0f * sk2.y;
                const float t10 = sq1f * sk2.x, t11 = sq1f * sk2.y;
                s[nt2 * 2 + hf][0] = (float)(a1[hf][0] * 254 + a2[hf][0]) * t00;
                s[nt2 * 2 + hf][1] = (float)(a1[hf][1] * 254 + a2[hf][1]) * t01;
                s[nt2 * 2 + hf][2] = (float)(a1[hf][2] * 254 + a2[hf][2]) * t10;
                s[nt2 * 2 + hf][3] = (float)(a1[hf][3] * 254 + a2[hf][3]) * t11;
            }
        }

        // ---- causal mask on diagonal tile ----
        if (kt == qt) {
            #pragma unroll
            for (int nt = 0; nt < 16; ++nt) {
                #pragma unroll
                for (int c = 0; c < 4; ++c) {
                    const int key = nt * 8 + kc + (c & 1);
                    const int qq  = w * 16 + r + (c >> 1) * 8;
                    if (key > qq) s[nt][c] = -1e30f;
                }
            }
        }

        // ---- online softmax ----
        float mx0 = -1e30f, mx1 = -1e30f;
        #pragma unroll
        for (int nt = 0; nt < 16; ++nt) {
            mx0 = fmaxf(mx0, fmaxf(s[nt][0], s[nt][1]));
            mx1 = fmaxf(mx1, fmaxf(s[nt][2], s[nt][3]));
        }
        mx0 = fmaxf(mx0, __shfl_xor_sync(0xffffffffu, mx0, 1));
        mx0 = fmaxf(mx0, __shfl_xor_sync(0xffffffffu, mx0, 2));
        mx1 = fmaxf(mx1, __shfl_xor_sync(0xffffffffu, mx1, 1));
        mx1 = fmaxf(mx1, __shfl_xor_sync(0xffffffffu, mx1, 2));

        const float nm0 = fmaxf(m_[0], mx0), nm1 = fmaxf(m_[1], mx1);
        const float al0 = __expf(m_[0] - nm0), al1 = __expf(m_[1] - nm1);
        float rs0 = 0.f, rs1 = 0.f;
        #pragma unroll
        for (int nt = 0; nt < 16; ++nt) {
            s[nt][0] = __expf(s[nt][0] - nm0);
            s[nt][1] = __expf(s[nt][1] - nm0);
            s[nt][2] = __expf(s[nt][2] - nm1);
            s[nt][3] = __expf(s[nt][3] - nm1);
            rs0 += s[nt][0] + s[nt][1];
            rs1 += s[nt][2] + s[nt][3];
        }
        rs0 += __shfl_xor_sync(0xffffffffu, rs0, 1);
        rs0 += __shfl_xor_sync(0xffffffffu, rs0, 2);
        rs1 += __shfl_xor_sync(0xffffffffu, rs1, 1);
        rs1 += __shfl_xor_sync(0xffffffffu, rs1, 2);

        l_[0] = l_[0] * al0 + rs0;  m_[0] = nm0;
        l_[1] = l_[1] * al1 + rs1;  m_[1] = nm1;
        #pragma unroll
        for (int dt = 0; dt < 8; ++dt) {
            oacc[dt][0] *= al0; oacc[dt][1] *= al0;
            oacc[dt][2] *= al1; oacc[dt][3] *= al1;
        }

        // ---- quantize P to dual digits, stage per-warp into smem ----
        #pragma unroll
        for (int nt = 0; nt < 16; ++nt) {
            uint32_t w2;
            uint32_t w1 = pack_dig(s[nt][0] * 127.f, s[nt][1] * 127.f, w2);
            *(uint16_t*)(sm + AP_OFF + (size_t)(w * 16 + r) * AP_ROWB + nt * 8 + kc) = (uint16_t)w1;
            *(uint16_t*)(sm + AP_OFF + AP_B + (size_t)(w * 16 + r) * AP_ROWB + nt * 8 + kc) = (uint16_t)w2;
            w1 = pack_dig(s[nt][2] * 127.f, s[nt][3] * 127.f, w2);
            *(uint16_t*)(sm + AP_OFF + (size_t)(w * 16 + r + 8) * AP_ROWB + nt * 8 + kc) = (uint16_t)w1;
            *(uint16_t*)(sm + AP_OFF + AP_B + (size_t)(w * 16 + r + 8) * AP_ROWB + nt * 8 + kc) = (uint16_t)w2;
        }
        __syncwarp();

        // ---- reload P as A-fragments ----
        uint32_t p1f[4][4], p2f[4][4];
        #pragma unroll
        for (int g = 0; g < 4; ++g) {
            ldsm_x4(p1f[g], sbase + AP_OFF + p_row + g * 32);
            ldsm_x4(p2f[g], sbase + AP_OFF + AP_B + p_row + g * 32);
        }

        // ---- O += P @ V (dual-digit int8, V^T in smem) ----
        #pragma unroll
        for (int dg = 0; dg < 4; ++dg) {
            int a1[2][4] = { {0,0,0,0}, {0,0,0,0} };
            int a2[2][4] = { {0,0,0,0}, {0,0,0,0} };
            #pragma unroll
            for (int g = 0; g < 4; ++g) {
                const uint32_t addr = (uint32_t)(dg * 16 + b_off) * AV_ROWB + g * 32 + kb_off;
                uint32_t fb1[4], fb2[4];
                ldsm_x4(fb1, v1b + addr);
                ldsm_x4(fb2, v2b + addr);
                #pragma unroll
                for (int hf = 0; hf < 2; ++hf) {
                    mma_s8(a1[hf], p1f[g], fb1 + hf * 2);
                    mma_s8(a2[hf], p1f[g], fb2 + hf * 2);
                    mma_s8(a2[hf], p2f[g], fb1 + hf * 2);
                }
            }
            #pragma unroll
            for (int hf = 0; hf < 2; ++hf) {
                #pragma unroll
                for (int c = 0; c < 4; ++c)
                    oacc[dg * 2 + hf][c] += (float)(a1[hf][c] * 254 + a2[hf][c]) * svf[dg * 2 + hf][c & 1];
            }
        }
        __syncthreads();
    }

    // ---- epilogue: normalize, write fp32 ctx ----
    const float inv0 = 1.f / l_[0], inv1 = 1.f / l_[1];
    #pragma unroll
    for (int dt = 0; dt < 8; ++dt) {
        const size_t d = (size_t)hoff + dt * 8 + kc;
        const size_t rowA = (size_t)(q0w + r) * DMODEL + d;
        const size_t rowB = (size_t)(q0w + r + 8) * DMODEL + d;
        float2 a0 = { oacc[dt][0] * inv0, oacc[dt][1] * inv0 };
        float2 a1 = { oacc[dt][2] * inv1, oacc[dt][3] * inv1 };
        *(float2*)(g_ctx + rowA) = a0;
        *(float2*)(g_ctx + rowB) = a1;
    }
}

// ======================= host launcher =======================
extern "C" void kernel_launch(void* const* d_in, const int* in_sizes, int n_in,
                              void* d_out, int out_size)
{
    (void)in_sizes; (void)n_in; (void)out_size;
    const float* x  = (const float*)d_in[0];
    const float* Wq = (const float*)d_in[2];
    const float* bq = (const float*)d_in[3];
    const float* Wk = (const float*)d_in[4];
    const float* bk = (const float*)d_in[5];
    const float* Wv = (const float*)d_in[6];
    const float* bv = (const float*)d_in[7];
    const float* Wo = (const float*)d_in[8];
    const float* bo = (const float*)d_in[9];
    float* out = (float*)d_out;

    int8_t *x1, *x2, *c1, *c2, *q1, *q2, *k1, *k2, *v1T, *v2T;
    float *sx, *sc, *ctx, *sq, *sk, *vf, *sv;
    unsigned* wbits;
    int8_t *wq1, *wq2, *wk1, *wk2, *wv1, *wv2, *wo1, *wo2;

    cudaGetSymbolAddress((void**)&x1, g_x1);
    cudaGetSymbolAddress((void**)&x2, g_x2);
    cudaGetSymbolAddress((void**)&sx, g_sx);
    cudaGetSymbolAddress((void**)&c1, g_c1);
    cudaGetSymbolAddress((void**)&c2, g_c2);
    cudaGetSymbolAddress((void**)&sc, g_sc);
    cudaGetSymbolAddress((void**)&ctx, g_ctx);
    cudaGetSymbolAddress((void**)&wbits, g_wbits);
    cudaGetSymbolAddress((void**)&wq1, g_wq1);
    cudaGetSymbolAddress((void**)&wq2, g_wq2);
    cudaGetSymbolAddress((void**)&wk1, g_wk1);
    cudaGetSymbolAddress((void**)&wk2, g_wk2);
    cudaGetSymbolAddress((void**)&wv1, g_wv1);
    cudaGetSymbolAddress((void**)&wv2, g_wv2);
    cudaGetSymbolAddress((void**)&wo1, g_wo1);
    cudaGetSymbolAddress((void**)&wo2, g_wo2);
    cudaGetSymbolAddress((void**)&q1, g_q1);
    cudaGetSymbolAddress((void**)&q2, g_q2);
    cudaGetSymbolAddress((void**)&k1, g_k1);
    cudaGetSymbolAddress((void**)&k2, g_k2);
    cudaGetSymbolAddress((void**)&sq, g_sq);
    cudaGetSymbolAddress((void**)&sk, g_sk);
    cudaGetSymbolAddress((void**)&vf, g_vf);
    cudaGetSymbolAddress((void**)&v1T, g_v1T);
    cudaGetSymbolAddress((void**)&v2T, g_v2T);
    cudaGetSymbolAddress((void**)&sv, g_sv);

    // ---- weight + input quantization pre-pass ----
    zero_bits_kernel<<<5, 1024>>>(wbits);
    colmax4_kernel<<<dim3(8, 8, 4), 256>>>(Wq, Wk, Wv, Wo, wbits);
    transpose_quant4_kernel<<<dim3(32, 32, 4), 256>>>(Wq, Wk, Wv, Wo, wbits,
                                                      wq1, wq2, wk1, wk2,
                                                      wv1, wv2, wo1, wo2);
    rowquant_kernel<<<S_LEN, 256>>>(x, x1, x2, sx);

    // ---- projections ----
    cudaFuncSetAttribute(gemm_s8_kernel,
                         cudaFuncAttributeMaxDynamicSharedMemorySize, QGEMM_SMEM);
    const dim3 ggrid(DMODEL / 128, S_LEN / 128);
    gemm_s8_kernel<<<ggrid, 256, QGEMM_SMEM>>>(x1, x2, sx, wq1, wq2, wbits + 0 * DMODEL,
                                               bq, nullptr, q1, q2, sq, 2, 0.125f);
    gemm_s8_kernel<<<ggrid, 256, QGEMM_SMEM>>>(x1, x2, sx, wk1, wk2, wbits + 1 * DMODEL,
                                               bk, nullptr, k1, k2, sk, 2, 1.0f);
    gemm_s8_kernel<<<ggrid, 256, QGEMM_SMEM>>>(x1, x2, sx, wv1, wv2, wbits + 2 * DMODEL,
                                               bv, vf, nullptr, nullptr, nullptr, 0, 1.0f);

    // ---- V -> per-col quantized V^T digits ----
    colmax_kernel<<<dim3(8, 32), 256>>>(vf, wbits + 4 * DMODEL);
    vprep_kernel<<<dim3(32, 128), 256>>>(vf, wbits + 4 * DMODEL, v1T, v2T, sv);

    // ---- attention ----
    cudaFuncSetAttribute(attn_s8_kernel,
                         cudaFuncAttributeMaxDynamicSharedMemorySize, ATT_SMEM);
    attn_s8_kernel<<<dim3(S_LEN / 128, NHEADS), 256, ATT_SMEM>>>();

    // ---- O projection ----
    rowquant_kernel<<<S_LEN, 256>>>(ctx, c1, c2, sc);
    gemm_s8_kernel<<<ggrid, 256, QGEMM_SMEM>>>(c1, c2, sc, wo1, wo2, wbits + 3 * DMODEL,
                                               bo, out, nullptr, nullptr, nullptr, 0, 1.0f);
}

// round 8
// speedup vs baseline: 3.3974x; 1.0365x over previous
#include <cuda_runtime.h>
#include <cuda_bf16.h>
#include <cstdint>
#include <math.h>

#define S_LEN  4096
#define DMODEL 1024
#define NHEADS 16
#define DK     64

// ======================= scratch (device globals) =======================
__device__ int8_t g_x1[(size_t)S_LEN * DMODEL];
__device__ int8_t g_x2[(size_t)S_LEN * DMODEL];
__device__ float  g_sx[S_LEN];

__device__ int8_t g_wq1[(size_t)DMODEL * DMODEL];
__device__ int8_t g_wq2[(size_t)DMODEL * DMODEL];
__device__ int8_t g_wk1[(size_t)DMODEL * DMODEL];
__device__ int8_t g_wk2[(size_t)DMODEL * DMODEL];
__device__ int8_t g_wv1[(size_t)DMODEL * DMODEL];
__device__ int8_t g_wv2[(size_t)DMODEL * DMODEL];
__device__ int8_t g_wo1[(size_t)DMODEL * DMODEL];
__device__ int8_t g_wo2[(size_t)DMODEL * DMODEL];
__device__ unsigned g_wbits[4 * DMODEL];

// attention operands
__device__ int8_t g_q1[(size_t)S_LEN * DMODEL];
__device__ int8_t g_q2[(size_t)S_LEN * DMODEL];
__device__ int8_t g_k1[(size_t)S_LEN * DMODEL];
__device__ int8_t g_k2[(size_t)S_LEN * DMODEL];
__device__ float  g_sq[NHEADS * S_LEN];
__device__ float  g_sk[NHEADS * S_LEN];
__device__ __nv_bfloat16 g_vh[(size_t)S_LEN * DMODEL];
__device__ __nv_bfloat16 g_vl[(size_t)S_LEN * DMODEL];

__device__ float  g_ctx[(size_t)S_LEN * DMODEL];
__device__ int8_t g_c1[(size_t)S_LEN * DMODEL];
__device__ int8_t g_c2[(size_t)S_LEN * DMODEL];
__device__ float  g_sc[S_LEN];

// ======================= helpers =======================
__device__ __forceinline__ uint32_t smem_u32(const void* p) {
    uint32_t a;
    asm("{ .reg .u64 t; cvta.to.shared.u64 t, %1; cvt.u32.u64 %0, t; }" : "=r"(a) : "l"(p));
    return a;
}
__device__ __forceinline__ void cp16(uint32_t saddr, const void* g) {
    asm volatile("cp.async.ca.shared.global [%0], [%1], 16;" :: "r"(saddr), "l"(g));
}
__device__ __forceinline__ void cp_commit() { asm volatile("cp.async.commit_group;"); }
__device__ __forceinline__ void cp_wait1()  { asm volatile("cp.async.wait_group 1;"); }
__device__ __forceinline__ void cp_wait0()  { asm volatile("cp.async.wait_group 0;"); }

__device__ __forceinline__ void ldsm_x4(uint32_t* r, uint32_t addr) {
    asm volatile("ldmatrix.sync.aligned.m8n8.x4.shared.b16 {%0,%1,%2,%3}, [%4];"
                 : "=r"(r[0]), "=r"(r[1]), "=r"(r[2]), "=r"(r[3]) : "r"(addr));
}
__device__ __forceinline__ void ldsm_x4_t(uint32_t* r, uint32_t addr) {
    asm volatile("ldmatrix.sync.aligned.m8n8.x4.trans.shared.b16 {%0,%1,%2,%3}, [%4];"
                 : "=r"(r[0]), "=r"(r[1]), "=r"(r[2]), "=r"(r[3]) : "r"(addr));
}
__device__ __forceinline__ void mma_s8(int* c, const uint32_t* a, const uint32_t* b) {
    asm volatile(
        "mma.sync.aligned.m16n8k32.row.col.s32.s8.s8.s32 "
        "{%0,%1,%2,%3}, {%4,%5,%6,%7}, {%8,%9}, {%0,%1,%2,%3};"
        : "+r"(c[0]), "+r"(c[1]), "+r"(c[2]), "+r"(c[3])
        : "r"(a[0]), "r"(a[1]), "r"(a[2]), "r"(a[3]), "r"(b[0]), "r"(b[1]));
}
__device__ __forceinline__ void mma16816(float* c, const uint32_t* a, const uint32_t* b) {
    asm volatile(
        "mma.sync.aligned.m16n8k16.row.col.f32.bf16.bf16.f32 "
        "{%0,%1,%2,%3}, {%4,%5,%6,%7}, {%8,%9}, {%0,%1,%2,%3};"
        : "+f"(c[0]), "+f"(c[1]), "+f"(c[2]), "+f"(c[3])
        : "r"(a[0]), "r"(a[1]), "r"(a[2]), "r"(a[3]), "r"(b[0]), "r"(b[1]));
}
__device__ __forceinline__ float ex2f(float x) {
    float y;
    asm("ex2.approx.f32 %0, %1;" : "=f"(y) : "f"(x));
    return y;
}
__device__ __forceinline__ void digits2(float alpha, int& d1, int& d2) {
    d1 = __float2int_rn(alpha);
    d2 = __float2int_rn((alpha - (float)d1) * 254.f);
}
__device__ __forceinline__ uint32_t pack_dig(float a, float b, uint32_t& w2) {
    int a1, a2, b1, b2;
    digits2(a, a1, a2);
    digits2(b, b1, b2);
    w2 = (uint32_t)(a2 & 0xff) | (((uint32_t)(b2 & 0xff)) << 8);
    return (uint32_t)(a1 & 0xff) | (((uint32_t)(b1 & 0xff)) << 8);
}
__device__ __forceinline__ void split_bf16(float v, __nv_bfloat16& h, __nv_bfloat16& l) {
    h = __float2bfloat16(v);
    l = __float2bfloat16(v - __bfloat162float(h));
}
__device__ __forceinline__ void pack2(float x, float y, uint32_t& hi, uint32_t& lo) {
    __nv_bfloat16 xh, xl, yh, yl;
    split_bf16(x, xh, xl);
    split_bf16(y, yh, yl);
    __nv_bfloat162 H(xh, yh), L(xl, yl);
    hi = *(uint32_t*)&H;
    lo = *(uint32_t*)&L;
}
__device__ __forceinline__ uint32_t pack4b(int a, int b, int c, int d) {
    return (uint32_t)(a & 0xff) | (((uint32_t)(b & 0xff)) << 8) |
           (((uint32_t)(c & 0xff)) << 16) | (((uint32_t)(d & 0xff)) << 24);
}

// ======================= fused weight prep =======================
// grid (8, 4): block owns 128 cols of W[z]; colmax then transpose+quantize.
__global__ __launch_bounds__(256)
void wprep_kernel(const float* __restrict__ Wq, const float* __restrict__ Wk,
                  const float* __restrict__ Wv, const float* __restrict__ Wo)
{
    const int z = blockIdx.y;
    const float* W = (z == 0) ? Wq : (z == 1) ? Wk : (z == 2) ? Wv : Wo;
    int8_t* B1 = (z == 0) ? g_wq1 : (z == 1) ? g_wk1 : (z == 2) ? g_wv1 : g_wo1;
    int8_t* B2 = (z == 0) ? g_wq2 : (z == 1) ? g_wk2 : (z == 2) ? g_wv2 : g_wo2;
    unsigned* bits = g_wbits + z * DMODEL;

    const int tid = threadIdx.x;
    const int c0 = blockIdx.x * 128;

    __shared__ float pm[2][128];
    __shared__ float sinv[128];
    __shared__ float tile[128][33];

    // phase 1: column max
    {
        const int col = c0 + (tid & 127);
        const int half = tid >> 7;
        float m = 0.f;
        for (int r = half; r < DMODEL; r += 2)
            m = fmaxf(m, fabsf(W[(size_t)r * DMODEL + col]));
        pm[half][tid & 127] = m;
    }
    __syncthreads();
    if (tid < 128) {
        const float mx = fmaxf(fmaxf(pm[0][tid], pm[1][tid]), 1e-30f);
        bits[c0 + tid] = __float_as_uint(mx);
        sinv[tid] = 127.f / mx;
    }
    __syncthreads();

    // phase 2: transpose + quantize in 128k x 32col tiles
    for (int kg = 0; kg < 8; ++kg) {
        const int k0 = kg * 128;
        for (int cg = 0; cg < 4; ++cg) {
            const int cc0 = c0 + cg * 32;
            #pragma unroll
            for (int i = 0; i < 16; ++i) {
                const int idx = tid + i * 256;
                const int kr = idx >> 5, cc = idx & 31;
                tile[kr][cc] = W[(size_t)(k0 + kr) * DMODEL + cc0 + cc];
            }
            __syncthreads();
            const int cw = tid >> 3;              // 0..31
            const int kk = (tid & 7) * 16;        // 0..112
            const float inv = sinv[cg * 32 + cw];
            int d1[16], d2[16];
            #pragma unroll
            for (int i = 0; i < 16; ++i)
                digits2(tile[kk + i][cw] * inv, d1[i], d2[i]);
            uint4 u1, u2;
            u1.x = pack4b(d1[0], d1[1], d1[2], d1[3]);
            u1.y = pack4b(d1[4], d1[5], d1[6], d1[7]);
            u1.z = pack4b(d1[8], d1[9], d1[10], d1[11]);
            u1.w = pack4b(d1[12], d1[13], d1[14], d1[15]);
            u2.x = pack4b(d2[0], d2[1], d2[2], d2[3]);
            u2.y = pack4b(d2[4], d2[5], d2[6], d2[7]);
            u2.z = pack4b(d2[8], d2[9], d2[10], d2[11]);
            u2.w = pack4b(d2[12], d2[13], d2[14], d2[15]);
            const size_t o = (size_t)(cc0 + cw) * DMODEL + k0 + kk;
            *(uint4*)(B1 + o) = u1;
            *(uint4*)(B2 + o) = u2;
            __syncthreads();
        }
    }
}

// per-row quant of a [rows,1024] fp32 matrix -> digits + scale
__global__ __launch_bounds__(256)
void rowquant_kernel(const float* __restrict__ src,
                     int8_t* __restrict__ D1, int8_t* __restrict__ D2,
                     float* __restrict__ s)
{
    const int row = blockIdx.x;
    const int tid = threadIdx.x;
    const float4 v = ((const float4*)(src + (size_t)row * DMODEL))[tid];
    float m = fmaxf(fmaxf(fabsf(v.x), fabsf(v.y)), fmaxf(fabsf(v.z), fabsf(v.w)));
    #pragma unroll
    for (int o = 16; o >= 1; o >>= 1)
        m = fmaxf(m, __shfl_xor_sync(0xffffffffu, m, o));
    __shared__ float red[8];
    if ((tid & 31) == 0) red[tid >> 5] = m;
    __syncthreads();
    float mm = red[0];
    #pragma unroll
    for (int i = 1; i < 8; i++) mm = fmaxf(mm, red[i]);
    mm = fmaxf(mm, 1e-30f);
    if (tid == 0) s[row] = mm * (1.f / 127.f);
    const float inv = 127.f / mm;
    int d1, d2;
    char4 c1, c2;
    digits2(v.x * inv, d1, d2); c1.x = (char)d1; c2.x = (char)d2;
    digits2(v.y * inv, d1, d2); c1.y = (char)d1; c2.y = (char)d2;
    digits2(v.z * inv, d1, d2); c1.z = (char)d1; c2.z = (char)d2;
    digits2(v.w * inv, d1, d2); c1.w = (char)d1; c2.w = (char)d2;
    ((char4*)(D1 + (size_t)row * DMODEL))[tid] = c1;
    ((char4*)(D2 + (size_t)row * DMODEL))[tid] = c2;
}

// ======================= int8 dual-digit GEMM cores =======================
#define QBK 64
#define QNCH (DMODEL / QBK)
#define QROWB 80
#define QARR_B (128 * QROWB)
#define QSTAGE_B (4 * QARR_B)
#define QGEMM_SMEM (2 * QSTAGE_B)

// shared mainloop body as a macro-free template via device function
struct GemmAcc { int a1[2][8][4]; int a2[2][8][4]; };

__device__ __forceinline__ void gemm_mainloop(
    const int8_t* A1p, const int8_t* A2p, const int8_t* B1p, const int8_t* B2p,
    char* sm, uint32_t sbase, int tid, int lane, int mw0, int nw0, GemmAcc& acc)
{
    #pragma unroll
    for (int i = 0; i < 2; i++)
        #pragma unroll
        for (int j = 0; j < 8; j++)
            #pragma unroll
            for (int q = 0; q < 4; q++) { acc.a1[i][j][q] = 0; acc.a2[i][j][q] = 0; }

    const int8_t* srcs[4] = { A1p, A2p, B1p, B2p };
    const int a_row = lane & 15;
    const int a_kb  = (lane >> 4) * 16;
    const int b_row = ((lane >> 4) << 3) + (lane & 7);
    const int b_kb  = ((lane >> 3) & 1) * 16;

    auto issue_loads = [&](int c, int stage) {
        const int k0 = c * QBK;
        const uint32_t sb = sbase + stage * QSTAGE_B;
        #pragma unroll
        for (int t = 0; t < 4; t++) {
            #pragma unroll
            for (int jj = 0; jj < 2; jj++) {
                const int slot = tid + jj * 256;
                const int row = slot >> 2, col = slot & 3;
                cp16(sb + t * QARR_B + row * QROWB + col * 16,
                     srcs[t] + (size_t)row * DMODEL + k0 + col * 16);
            }
        }
    };

    issue_loads(0, 0);
    cp_commit();

    for (int c = 0; c < QNCH; ++c) {
        const int stage = c & 1;
        const bool hasNext = (c + 1 < QNCH);
        if (hasNext) { issue_loads(c + 1, stage ^ 1); cp_commit(); }
        if (hasNext) cp_wait1(); else cp_wait0();
        __syncthreads();

        const uint32_t sb = sbase + stage * QSTAGE_B;
        #pragma unroll
        for (int ks = 0; ks < 2; ++ks) {
            const int kb = ks * 32;
            uint32_t fa1[2][4], fa2[2][4];
            #pragma unroll
            for (int mi = 0; mi < 2; ++mi) {
                const uint32_t aoff = (uint32_t)(mw0 + mi * 16 + a_row) * QROWB + kb + a_kb;
                ldsm_x4(fa1[mi], sb + 0 * QARR_B + aoff);
                ldsm_x4(fa2[mi], sb + 1 * QARR_B + aoff);
            }
            #pragma unroll
            for (int nt2 = 0; nt2 < 4; ++nt2) {
                const uint32_t boff = (uint32_t)(nw0 + nt2 * 16 + b_row) * QROWB + kb + b_kb;
                uint32_t fb1[4], fb2[4];
                ldsm_x4(fb1, sb + 2 * QARR_B + boff);
                ldsm_x4(fb2, sb + 3 * QARR_B + boff);
                #pragma unroll
                for (int mi = 0; mi < 2; ++mi) {
                    #pragma unroll
                    for (int half = 0; half < 2; ++half) {
                        mma_s8(acc.a1[mi][nt2 * 2 + half], fa1[mi], fb1 + half * 2);
                        mma_s8(acc.a2[mi][nt2 * 2 + half], fa1[mi], fb2 + half * 2);
                        mma_s8(acc.a2[mi][nt2 * 2 + half], fa2[mi], fb1 + half * 2);
                    }
                }
            }
        }
        __syncthreads();
    }
}

// fused Q/K/V projection: grid (8, 32, 3)
__global__ __launch_bounds__(256, 1)
void gemm_qkv_kernel(const float* __restrict__ bq,
                     const float* __restrict__ bk,
                     const float* __restrict__ bv)
{
    extern __shared__ char sm[];
    const uint32_t sbase = smem_u32(sm);
    const int tid  = threadIdx.x;
    const int lane = tid & 31;
    const int wid  = tid >> 5;
    const int mw0  = (wid & 3) * 32;
    const int nw0  = (wid >> 2) * 64;
    const int bm   = blockIdx.y * 128;
    const int bn   = blockIdx.x * 128;
    const int z    = blockIdx.z;

    const int8_t* B1 = (z == 0) ? g_wq1 : (z == 1) ? g_wk1 : g_wv1;
    const int8_t* B2 = (z == 0) ? g_wq2 : (z == 1) ? g_wk2 : g_wv2;
    const float* bias = (z == 0) ? bq : (z == 1) ? bk : bv;
    const unsigned* sBbits = g_wbits + z * DMODEL;

    GemmAcc acc;
    gemm_mainloop(g_x1 + (size_t)bm * DMODEL, g_x2 + (size_t)bm * DMODEL,
                  B1 + (size_t)bn * DMODEL, B2 + (size_t)bn * DMODEL,
                  sm, sbase, tid, lane, mw0, nw0, acc);

    const int erow = lane >> 2;
    const int ecol = (lane & 3) * 2;
    const float* sA = g_sx;

    if (z == 2) {
        // V: bf16 hi/lo natural layout
        #pragma unroll
        for (int mi = 0; mi < 2; ++mi) {
            const int m0 = bm + mw0 + mi * 16 + erow;
            const float sa0 = sA[m0], sa8 = sA[m0 + 8];
            #pragma unroll
            for (int ni = 0; ni < 8; ++ni) {
                const int n = bn + nw0 + ni * 8 + ecol;
                const float sb0 = __uint_as_float(sBbits[n])     * (1.f / 127.f);
                const float sb1 = __uint_as_float(sBbits[n + 1]) * (1.f / 127.f);
                const float b0 = bias[n], b1 = bias[n + 1];
                const float c00 = ((float)acc.a1[mi][ni][0] + (float)acc.a2[mi][ni][0] * (1.f / 254.f)) * (sa0 * sb0) + b0;
                const float c01 = ((float)acc.a1[mi][ni][1] + (float)acc.a2[mi][ni][1] * (1.f / 254.f)) * (sa0 * sb1) + b1;
                const float c10 = ((float)acc.a1[mi][ni][2] + (float)acc.a2[mi][ni][2] * (1.f / 254.f)) * (sa8 * sb0) + b0;
                const float c11 = ((float)acc.a1[mi][ni][3] + (float)acc.a2[mi][ni][3] * (1.f / 254.f)) * (sa8 * sb1) + b1;
                uint32_t H, L;
                pack2(c00, c01, H, L);
                *(uint32_t*)(g_vh + (size_t)m0 * DMODEL + n) = H;
                *(uint32_t*)(g_vl + (size_t)m0 * DMODEL + n) = L;
                pack2(c10, c11, H, L);
                *(uint32_t*)(g_vh + (size_t)(m0 + 8) * DMODEL + n) = H;
                *(uint32_t*)(g_vl + (size_t)(m0 + 8) * DMODEL + n) = L;
            }
        }
    } else {
        int8_t* D1 = z ? g_k1 : g_q1;
        int8_t* D2 = z ? g_k2 : g_q2;
        float* sOut = z ? g_sk : g_sq;
        const float smul = z ? 1.0f : 0.125f * 1.44269504f;  // Q: fold 1/sqrt(dk) * log2(e)
        const int head = (bn + nw0) >> 6;
        #pragma unroll
        for (int mi = 0; mi < 2; ++mi) {
            const int m0 = bm + mw0 + mi * 16 + erow;
            const float sa0 = sA[m0], sa8 = sA[m0 + 8];
            float v0[16], v1[16];
            #pragma unroll
            for (int ni = 0; ni < 8; ++ni) {
                const int n = bn + nw0 + ni * 8 + ecol;
                const float sb0 = __uint_as_float(sBbits[n])     * (1.f / 127.f);
                const float sb1 = __uint_as_float(sBbits[n + 1]) * (1.f / 127.f);
                const float b0 = bias[n], b1 = bias[n + 1];
                v0[ni * 2 + 0] = ((float)acc.a1[mi][ni][0] + (float)acc.a2[mi][ni][0] * (1.f / 254.f)) * (sa0 * sb0) + b0;
                v0[ni * 2 + 1] = ((float)acc.a1[mi][ni][1] + (float)acc.a2[mi][ni][1] * (1.f / 254.f)) * (sa0 * sb1) + b1;
                v1[ni * 2 + 0] = ((float)acc.a1[mi][ni][2] + (float)acc.a2[mi][ni][2] * (1.f / 254.f)) * (sa8 * sb0) + b0;
                v1[ni * 2 + 1] = ((float)acc.a1[mi][ni][3] + (float)acc.a2[mi][ni][3] * (1.f / 254.f)) * (sa8 * sb1) + b1;
            }
            float mx0 = 0.f, mx1 = 0.f;
            #pragma unroll
            for (int i = 0; i < 16; i++) {
                mx0 = fmaxf(mx0, fabsf(v0[i]));
                mx1 = fmaxf(mx1, fabsf(v1[i]));
            }
            mx0 = fmaxf(mx0, __shfl_xor_sync(0xffffffffu, mx0, 1));
            mx0 = fmaxf(mx0, __shfl_xor_sync(0xffffffffu, mx0, 2));
            mx1 = fmaxf(mx1, __shfl_xor_sync(0xffffffffu, mx1, 1));
            mx1 = fmaxf(mx1, __shfl_xor_sync(0xffffffffu, mx1, 2));
            mx0 = fmaxf(mx0, 1e-20f);
            mx1 = fmaxf(mx1, 1e-20f);
            if ((lane & 3) == 0) {
                sOut[head * S_LEN + m0]     = mx0 * (smul / 127.f);
                sOut[head * S_LEN + m0 + 8] = mx1 * (smul / 127.f);
            }
            const float i0 = 127.f / mx0, i1 = 127.f / mx1;
            #pragma unroll
            for (int ni = 0; ni < 8; ++ni) {
                const int n = bn + nw0 + ni * 8 + ecol;
                uint32_t w2;
                uint32_t w1 = pack_dig(v0[ni * 2] * i0, v0[ni * 2 + 1] * i0, w2);
                *(uint16_t*)(D1 + (size_t)m0 * DMODEL + n) = (uint16_t)w1;
                *(uint16_t*)(D2 + (size_t)m0 * DMODEL + n) = (uint16_t)w2;
                w1 = pack_dig(v1[ni * 2] * i1, v1[ni * 2 + 1] * i1, w2);
                *(uint16_t*)(D1 + (size_t)(m0 + 8) * DMODEL + n) = (uint16_t)w1;
                *(uint16_t*)(D2 + (size_t)(m0 + 8) * DMODEL + n) = (uint16_t)w2;
            }
        }
    }
}

// O projection: fp32 out + bias
__global__ __launch_bounds__(256, 1)
void gemm_o_kernel(const float* __restrict__ bias, float* __restrict__ C)
{
    extern __shared__ char sm[];
    const uint32_t sbase = smem_u32(sm);
    const int tid  = threadIdx.x;
    const int lane = tid & 31;
    const int wid  = tid >> 5;
    const int mw0  = (wid & 3) * 32;
    const int nw0  = (wid >> 2) * 64;
    const int bm   = blockIdx.y * 128;
    const int bn   = blockIdx.x * 128;

    GemmAcc acc;
    gemm_mainloop(g_c1 + (size_t)bm * DMODEL, g_c2 + (size_t)bm * DMODEL,
                  g_wo1 + (size_t)bn * DMODEL, g_wo2 + (size_t)bn * DMODEL,
                  sm, sbase, tid, lane, mw0, nw0, acc);

    const unsigned* sBbits = g_wbits + 3 * DMODEL;
    const int erow = lane >> 2;
    const int ecol = (lane & 3) * 2;
    #pragma unroll
    for (int mi = 0; mi < 2; ++mi) {
        const int m0 = bm + mw0 + mi * 16 + erow;
        const float sa0 = g_sc[m0], sa8 = g_sc[m0 + 8];
        #pragma unroll
        for (int ni = 0; ni < 8; ++ni) {
            const int n = bn + nw0 + ni * 8 + ecol;
            const float sb0 = __uint_as_float(sBbits[n])     * (1.f / 127.f);
            const float sb1 = __uint_as_float(sBbits[n + 1]) * (1.f / 127.f);
            const float b0 = bias[n], b1 = bias[n + 1];
            float2 v0, v1;
            v0.x = ((float)acc.a1[mi][ni][0] + (float)acc.a2[mi][ni][0] * (1.f / 254.f)) * (sa0 * sb0) + b0;
            v0.y = ((float)acc.a1[mi][ni][1] + (float)acc.a2[mi][ni][1] * (1.f / 254.f)) * (sa0 * sb1) + b1;
            v1.x = ((float)acc.a1[mi][ni][2] + (float)acc.a2[mi][ni][2] * (1.f / 254.f)) * (sa8 * sb0) + b0;
            v1.y = ((float)acc.a1[mi][ni][3] + (float)acc.a2[mi][ni][3] * (1.f / 254.f)) * (sa8 * sb1) + b1;
            *(float2*)(C + (size_t)m0 * DMODEL + n)       = v0;
            *(float2*)(C + (size_t)(m0 + 8) * DMODEL + n) = v1;
        }
    }
}

// ======================= hybrid flash attention =======================
// QK: int8 dual-digit.  PV: bf16 hi/lo x3 (P register-direct, V trans-ldmatrix).
#define AK_ROWB 80
#define AK_B (128 * AK_ROWB)            // 10240 per K digit
#define AV_ROWB 144
#define AV_B (128 * AV_ROWB)            // 18432 per V half
#define ASK_OFF (2 * AK_B + 2 * AV_B)   // 57344
#define ABUF_B (ASK_OFF + 512)          // 57856
#define ATT_SMEM (2 * ABUF_B)           // 115712

__global__ __launch_bounds__(256, 1)
void attn_kernel()
{
    extern __shared__ char sm[];
    const uint32_t sbase = smem_u32(sm);

    const int tid  = threadIdx.x;
    const int lane = tid & 31;
    const int w    = tid >> 5;
    const int h    = blockIdx.y;
    const int qt   = (int)gridDim.x - 1 - (int)blockIdx.x;
    const int q0   = qt * 128;
    const int hoff = h * DK;
    const int q0w  = q0 + w * 16;

    const int r  = lane >> 2;
    const int kc = (lane & 3) * 2;

    // Q A-fragments (int8 digits)
    uint32_t q1f[2][4], q2f[2][4];
    {
        const int qb = (lane & 3) * 4;
        #pragma unroll
        for (int g = 0; g < 2; ++g) {
            const size_t bA = (size_t)(q0w + r) * DMODEL + hoff + g * 32 + qb;
            const size_t bB = (size_t)(q0w + r + 8) * DMODEL + hoff + g * 32 + qb;
            q1f[g][0] = *(const uint32_t*)(g_q1 + bA);
            q1f[g][1] = *(const uint32_t*)(g_q1 + bB);
            q1f[g][2] = *(const uint32_t*)(g_q1 + bA + 16);
            q1f[g][3] = *(const uint32_t*)(g_q1 + bB + 16);
            q2f[g][0] = *(const uint32_t*)(g_q2 + bA);
            q2f[g][1] = *(const uint32_t*)(g_q2 + bB);
            q2f[g][2] = *(const uint32_t*)(g_q2 + bA + 16);
            q2f[g][3] = *(const uint32_t*)(g_q2 + bB + 16);
        }
    }
    const float sq0f = g_sq[h * S_LEN + q0w + r]     * (1.f / 254.f);
    const float sq1f = g_sq[h * S_LEN + q0w + r + 8] * (1.f / 254.f);

    auto issue_kv = [&](int kt, int buf) {
        const int k0 = kt * 128;
        const uint32_t sb = sbase + buf * ABUF_B;
        // K digits
        #pragma unroll
        for (int d = 0; d < 2; ++d) {
            const int8_t* src = (d ? g_k2 : g_k1) + (size_t)k0 * DMODEL + hoff;
            #pragma unroll
            for (int j = 0; j < 2; ++j) {
                const int slot = tid + j * 256;
                const int row = slot >> 2, col = slot & 3;
                cp16(sb + d * AK_B + row * AK_ROWB + col * 16,
                     src + (size_t)row * DMODEL + col * 16);
            }
        }
        // V bf16 hi/lo natural [token][d]
        #pragma unroll
        for (int d = 0; d < 2; ++d) {
            const __nv_bfloat16* src = (d ? g_vl : g_vh) + (size_t)k0 * DMODEL + hoff;
            #pragma unroll
            for (int j = 0; j < 4; ++j) {
                const int slot = tid + j * 256;
                const int row = slot >> 3, col = slot & 7;
                cp16(sb + 2 * AK_B + d * AV_B + row * AV_ROWB + col * 16,
                     src + (size_t)row * DMODEL + col * 8);
            }
        }
        if (tid < 32)
            cp16(sb + ASK_OFF + tid * 16, g_sk + h * S_LEN + k0 + tid * 4);
    };

    float m_[2] = { -1e30f, -1e30f }, l_[2] = { 0.f, 0.f };
    float oacc[8][4];
    #pragma unroll
    for (int i = 0; i < 8; i++)
        #pragma unroll
        for (int j = 0; j < 4; j++) oacc[i][j] = 0.f;

    issue_kv(0, 0);
    cp_commit();

    const uint32_t b_off  = (uint32_t)(((lane >> 4) << 3) + (lane & 7));
    const uint32_t kb_off = ((lane >> 3) & 1) * 16;
    const uint32_t vrow   = lane & 15;
    const uint32_t vcol   = (lane >> 4) * 8;

    for (int kt = 0; kt <= qt; ++kt) {
        const int buf = kt & 1;
        const bool hasNext = kt < qt;
        if (hasNext) { issue_kv(kt + 1, buf ^ 1); cp_commit(); }
        if (hasNext) cp_wait1(); else cp_wait0();
        __syncthreads();

        const uint32_t k1b = sbase + buf * ABUF_B;
        const uint32_t k2b = k1b + AK_B;
        const uint32_t vh_b = k1b + 2 * AK_B;
        const uint32_t vl_b = vh_b + AV_B;
        const float* sks = (const float*)(sm + buf * ABUF_B + ASK_OFF);

        // ---- S = Q @ K^T (dual-digit int8); scores in log2 units ----
        float s[16][4];
        #pragma unroll
        for (int nt2 = 0; nt2 < 8; ++nt2) {
            int a1[2][4] = { {0,0,0,0}, {0,0,0,0} };
            int a2[2][4] = { {0,0,0,0}, {0,0,0,0} };
            #pragma unroll
            for (int g = 0; g < 2; ++g) {
                const uint32_t addr = (uint32_t)(nt2 * 16 + b_off) * AK_ROWB + g * 32 + kb_off;
                uint32_t fb1[4], fb2[4];
                ldsm_x4(fb1, k1b + addr);
                ldsm_x4(fb2, k2b + addr);
                #pragma unroll
                for (int hf = 0; hf < 2; ++hf) {
                    mma_s8(a1[hf], q1f[g], fb1 + hf * 2);
                    mma_s8(a2[hf], q1f[g], fb2 + hf * 2);
                    mma_s8(a2[hf], q2f[g], fb1 + hf * 2);
                }
            }
            #pragma unroll
            for (int hf = 0; hf < 2; ++hf) {
                const float2 sk2 = *(const float2*)(sks + (nt2 * 2 + hf) * 8 + kc);
                s[nt2 * 2 + hf][0] = (float)(a1[hf][0] * 254 + a2[hf][0]) * (sq0f * sk2.x);
                s[nt2 * 2 + hf][1] = (float)(a1[hf][1] * 254 + a2[hf][1]) * (sq0f * sk2.y);
                s[nt2 * 2 + hf][2] = (float)(a1[hf][2] * 254 + a2[hf][2]) * (sq1f * sk2.x);
                s[nt2 * 2 + hf][3] = (float)(a1[hf][3] * 254 + a2[hf][3]) * (sq1f * sk2.y);
            }
        }

        // causal mask on diagonal tile
        if (kt == qt) {
            #pragma unroll
            for (int nt = 0; nt < 16; ++nt) {
                #pragma unroll
                for (int c = 0; c < 4; ++c) {
                    const int key = nt * 8 + kc + (c & 1);
                    const int qq  = w * 16 + r + (c >> 1) * 8;
                    if (key > qq) s[nt][c] = -1e30f;
                }
            }
        }

        // ---- online softmax (base-2) ----
        float mx0 = -1e30f, mx1 = -1e30f;
        #pragma unroll
        for (int nt = 0; nt < 16; ++nt) {
            mx0 = fmaxf(mx0, fmaxf(s[nt][0], s[nt][1]));
            mx1 = fmaxf(mx1, fmaxf(s[nt][2], s[nt][3]));
        }
        mx0 = fmaxf(mx0, __shfl_xor_sync(0xffffffffu, mx0, 1));
        mx0 = fmaxf(mx0, __shfl_xor_sync(0xffffffffu, mx0, 2));
        mx1 = fmaxf(mx1, __shfl_xor_sync(0xffffffffu, mx1, 1));
        mx1 = fmaxf(mx1, __shfl_xor_sync(0xffffffffu, mx1, 2));

        const float nm0 = fmaxf(m_[0], mx0), nm1 = fmaxf(m_[1], mx1);
        const float al0 = ex2f(m_[0] - nm0), al1 = ex2f(m_[1] - nm1);
        float rs0 = 0.f, rs1 = 0.f;
        #pragma unroll
        for (int nt = 0; nt < 16; ++nt) {
            s[nt][0] = ex2f(s[nt][0] - nm0);
            s[nt][1] = ex2f(s[nt][1] - nm0);
            s[nt][2] = ex2f(s[nt][2] - nm1);
            s[nt][3] = ex2f(s[nt][3] - nm1);
            rs0 += s[nt][0] + s[nt][1];
            rs1 += s[nt][2] + s[nt][3];
        }
        rs0 += __shfl_xor_sync(0xffffffffu, rs0, 1);
        rs0 += __shfl_xor_sync(0xffffffffu, rs0, 2);
        rs1 += __shfl_xor_sync(0xffffffffu, rs1, 1);
        rs1 += __shfl_xor_sync(0xffffffffu, rs1, 2);

        l_[0] = l_[0] * al0 + rs0;  m_[0] = nm0;
        l_[1] = l_[1] * al1 + rs1;  m_[1] = nm1;
        #pragma unroll
        for (int dt = 0; dt < 8; ++dt) {
            oacc[dt][0] *= al0; oacc[dt][1] *= al0;
            oacc[dt][2] *= al1; oacc[dt][3] *= al1;
        }

        // ---- O += P @ V (P packed hi/lo in regs; V via trans-ldmatrix) ----
        #pragma unroll
        for (int j = 0; j < 8; ++j) {
            uint32_t pah[4], pal[4];
            pack2(s[2*j][0],   s[2*j][1],   pah[0], pal[0]);
            pack2(s[2*j][2],   s[2*j][3],   pah[1], pal[1]);
            pack2(s[2*j+1][0], s[2*j+1][1], pah[2], pal[2]);
            pack2(s[2*j+1][2], s[2*j+1][3], pah[3], pal[3]);

            const uint32_t abase = (j * 16 + vrow) * AV_ROWB + vcol * 2;
            #pragma unroll
            for (int dg = 0; dg < 4; ++dg) {
                const uint32_t a2 = abase + dg * 32;
                uint32_t bh[4], bl[4];
                ldsm_x4_t(bh, vh_b + a2);
                ldsm_x4_t(bl, vl_b + a2);
                #pragma unroll
                for (int hf = 0; hf < 2; ++hf) {
                    float* cc = oacc[dg * 2 + hf];
                    mma16816(cc, pah, bh + hf * 2);
                    mma16816(cc, pah, bl + hf * 2);
                    mma16816(cc, pal, bh + hf * 2);
                }
            }
        }
        __syncthreads();
    }

    // epilogue: normalize, write fp32 ctx
    const float inv0 = 1.f / l_[0], inv1 = 1.f / l_[1];
    #pragma unroll
    for (int dt = 0; dt < 8; ++dt) {
        const size_t d = (size_t)hoff + dt * 8 + kc;
        const size_t rowA = (size_t)(q0w + r) * DMODEL + d;
        const size_t rowB = (size_t)(q0w + r + 8) * DMODEL + d;
        float2 a0 = { oacc[dt][0] * inv0, oacc[dt][1] * inv0 };
        float2 a1 = { oacc[dt][2] * inv1, oacc[dt][3] * inv1 };
        *(float2*)(g_ctx + rowA) = a0;
        *(float2*)(g_ctx + rowB) = a1;
    }
}

// ======================= host launcher =======================
extern "C" void kernel_launch(void* const* d_in, const int* in_sizes, int n_in,
                              void* d_out, int out_size)
{
    (void)in_sizes; (void)n_in; (void)out_size;
    const float* x  = (const float*)d_in[0];
    const float* Wq = (const float*)d_in[2];
    const float* bq = (const float*)d_in[3];
    const float* Wk = (const float*)d_in[4];
    const float* bk = (const float*)d_in[5];
    const float* Wv = (const float*)d_in[6];
    const float* bv = (const float*)d_in[7];
    const float* Wo = (const float*)d_in[8];
    const float* bo = (const float*)d_in[9];
    float* out = (float*)d_out;

    int8_t *x1, *x2, *c1, *c2;
    float *sx, *sc, *ctx;
    cudaGetSymbolAddress((void**)&x1, g_x1);
    cudaGetSymbolAddress((void**)&x2, g_x2);
    cudaGetSymbolAddress((void**)&sx, g_sx);
    cudaGetSymbolAddress((void**)&c1, g_c1);
    cudaGetSymbolAddress((void**)&c2, g_c2);
    cudaGetSymbolAddress((void**)&sc, g_sc);
    cudaGetSymbolAddress((void**)&ctx, g_ctx);

    cudaFuncSetAttribute(gemm_qkv_kernel,
                         cudaFuncAttributeMaxDynamicSharedMemorySize, QGEMM_SMEM);
    cudaFuncSetAttribute(gemm_o_kernel,
                         cudaFuncAttributeMaxDynamicSharedMemorySize, QGEMM_SMEM);
    cudaFuncSetAttribute(attn_kernel,
                         cudaFuncAttributeMaxDynamicSharedMemorySize, ATT_SMEM);

    // 1: fused weight colmax + transpose-quant
    wprep_kernel<<<dim3(8, 4), 256>>>(Wq, Wk, Wv, Wo);
    // 2: input row-quant
    rowquant_kernel<<<S_LEN, 256>>>(x, x1, x2, sx);
    // 3: fused Q/K/V projections
    gemm_qkv_kernel<<<dim3(8, 32, 3), 256, QGEMM_SMEM>>>(bq, bk, bv);
    // 4: attention  (profiled slot)
    attn_kernel<<<dim3(S_LEN / 128, NHEADS), 256, ATT_SMEM>>>();
    // 5: ctx row-quant
    rowquant_kernel<<<S_LEN, 256>>>(ctx, c1, c2, sc);
    // 6: O projection
    gemm_o_kernel<<<dim3(8, 32), 256, QGEMM_SMEM>>>(bo, out);
}

// round 9
// speedup vs baseline: 4.0513x; 1.1925x over previous
#include <cuda_runtime.h>
#include <cuda_bf16.h>
#include <cuda_fp16.h>
#include <cstdint>
#include <math.h>

#define S_LEN  4096
#define DMODEL 1024
#define NHEADS 16
#define DK     64

// ======================= scratch (device globals) =======================
__device__ int8_t g_x1[(size_t)S_LEN * DMODEL];
__device__ int8_t g_x2[(size_t)S_LEN * DMODEL];
__device__ float  g_sx[S_LEN];

__device__ int8_t g_wq1[(size_t)DMODEL * DMODEL];
__device__ int8_t g_wq2[(size_t)DMODEL * DMODEL];
__device__ int8_t g_wk1[(size_t)DMODEL * DMODEL];
__device__ int8_t g_wk2[(size_t)DMODEL * DMODEL];
__device__ int8_t g_wv1[(size_t)DMODEL * DMODEL];
__device__ int8_t g_wv2[(size_t)DMODEL * DMODEL];
__device__ int8_t g_wo1[(size_t)DMODEL * DMODEL];
__device__ int8_t g_wo2[(size_t)DMODEL * DMODEL];
__device__ unsigned g_wbits[4 * DMODEL];

// attention operands
__device__ int8_t g_q1[(size_t)S_LEN * DMODEL];
__device__ int8_t g_q2[(size_t)S_LEN * DMODEL];
__device__ int8_t g_k1[(size_t)S_LEN * DMODEL];
__device__ int8_t g_k2[(size_t)S_LEN * DMODEL];
__device__ float  g_sq[NHEADS * S_LEN];
__device__ float  g_sk[NHEADS * S_LEN];
__device__ __half g_v16[(size_t)S_LEN * DMODEL];

__device__ float  g_ctx[(size_t)S_LEN * DMODEL];
__device__ int8_t g_c1[(size_t)S_LEN * DMODEL];
__device__ int8_t g_c2[(size_t)S_LEN * DMODEL];
__device__ float  g_sc[S_LEN];

// ======================= helpers =======================
__device__ __forceinline__ uint32_t smem_u32(const void* p) {
    uint32_t a;
    asm("{ .reg .u64 t; cvta.to.shared.u64 t, %1; cvt.u32.u64 %0, t; }" : "=r"(a) : "l"(p));
    return a;
}
__device__ __forceinline__ void cp16(uint32_t saddr, const void* g) {
    asm volatile("cp.async.ca.shared.global [%0], [%1], 16;" :: "r"(saddr), "l"(g));
}
__device__ __forceinline__ void cp_commit() { asm volatile("cp.async.commit_group;"); }
__device__ __forceinline__ void cp_wait1()  { asm volatile("cp.async.wait_group 1;"); }
__device__ __forceinline__ void cp_wait0()  { asm volatile("cp.async.wait_group 0;"); }

__device__ __forceinline__ void ldsm_x4(uint32_t* r, uint32_t addr) {
    asm volatile("ldmatrix.sync.aligned.m8n8.x4.shared.b16 {%0,%1,%2,%3}, [%4];"
                 : "=r"(r[0]), "=r"(r[1]), "=r"(r[2]), "=r"(r[3]) : "r"(addr));
}
__device__ __forceinline__ void ldsm_x4_t(uint32_t* r, uint32_t addr) {
    asm volatile("ldmatrix.sync.aligned.m8n8.x4.trans.shared.b16 {%0,%1,%2,%3}, [%4];"
                 : "=r"(r[0]), "=r"(r[1]), "=r"(r[2]), "=r"(r[3]) : "r"(addr));
}
__device__ __forceinline__ void mma_s8(int* c, const uint32_t* a, const uint32_t* b) {
    asm volatile(
        "mma.sync.aligned.m16n8k32.row.col.s32.s8.s8.s32 "
        "{%0,%1,%2,%3}, {%4,%5,%6,%7}, {%8,%9}, {%0,%1,%2,%3};"
        : "+r"(c[0]), "+r"(c[1]), "+r"(c[2]), "+r"(c[3])
        : "r"(a[0]), "r"(a[1]), "r"(a[2]), "r"(a[3]), "r"(b[0]), "r"(b[1]));
}
__device__ __forceinline__ void mma_f16(float* c, const uint32_t* a, const uint32_t* b) {
    asm volatile(
        "mma.sync.aligned.m16n8k16.row.col.f32.f16.f16.f32 "
        "{%0,%1,%2,%3}, {%4,%5,%6,%7}, {%8,%9}, {%0,%1,%2,%3};"
        : "+f"(c[0]), "+f"(c[1]), "+f"(c[2]), "+f"(c[3])
        : "r"(a[0]), "r"(a[1]), "r"(a[2]), "r"(a[3]), "r"(b[0]), "r"(b[1]));
}
__device__ __forceinline__ float ex2f(float x) {
    float y;
    asm("ex2.approx.f32 %0, %1;" : "=f"(y) : "f"(x));
    return y;
}
__device__ __forceinline__ uint32_t h2u(float x, float y) {
    __half2 h = __floats2half2_rn(x, y);
    return *(uint32_t*)&h;
}
__device__ __forceinline__ void digits2(float alpha, int& d1, int& d2) {
    d1 = __float2int_rn(alpha);
    d2 = __float2int_rn((alpha - (float)d1) * 254.f);
}
__device__ __forceinline__ uint32_t pack_dig(float a, float b, uint32_t& w2) {
    int a1, a2, b1, b2;
    digits2(a, a1, a2);
    digits2(b, b1, b2);
    w2 = (uint32_t)(a2 & 0xff) | (((uint32_t)(b2 & 0xff)) << 8);
    return (uint32_t)(a1 & 0xff) | (((uint32_t)(b1 & 0xff)) << 8);
}
__device__ __forceinline__ uint32_t pack4b(int a, int b, int c, int d) {
    return (uint32_t)(a & 0xff) | (((uint32_t)(b & 0xff)) << 8) |
           (((uint32_t)(c & 0xff)) << 16) | (((uint32_t)(d & 0xff)) << 24);
}

// ======================= fused weight prep =======================
__global__ __launch_bounds__(256)
void wprep_kernel(const float* __restrict__ Wq, const float* __restrict__ Wk,
                  const float* __restrict__ Wv, const float* __restrict__ Wo)
{
    const int z = blockIdx.y;
    const float* W = (z == 0) ? Wq : (z == 1) ? Wk : (z == 2) ? Wv : Wo;
    int8_t* B1 = (z == 0) ? g_wq1 : (z == 1) ? g_wk1 : (z == 2) ? g_wv1 : g_wo1;
    int8_t* B2 = (z == 0) ? g_wq2 : (z == 1) ? g_wk2 : (z == 2) ? g_wv2 : g_wo2;
    unsigned* bits = g_wbits + z * DMODEL;

    const int tid = threadIdx.x;
    const int c0 = blockIdx.x * 128;

    __shared__ float pm[2][128];
    __shared__ float sinv[128];
    __shared__ float tile[128][33];

    {
        const int col = c0 + (tid & 127);
        const int half = tid >> 7;
        float m = 0.f;
        for (int r = half; r < DMODEL; r += 2)
            m = fmaxf(m, fabsf(W[(size_t)r * DMODEL + col]));
        pm[half][tid & 127] = m;
    }
    __syncthreads();
    if (tid < 128) {
        const float mx = fmaxf(fmaxf(pm[0][tid], pm[1][tid]), 1e-30f);
        bits[c0 + tid] = __float_as_uint(mx);
        sinv[tid] = 127.f / mx;
    }
    __syncthreads();

    for (int kg = 0; kg < 8; ++kg) {
        const int k0 = kg * 128;
        for (int cg = 0; cg < 4; ++cg) {
            const int cc0 = c0 + cg * 32;
            #pragma unroll
            for (int i = 0; i < 16; ++i) {
                const int idx = tid + i * 256;
                const int kr = idx >> 5, cc = idx & 31;
                tile[kr][cc] = W[(size_t)(k0 + kr) * DMODEL + cc0 + cc];
            }
            __syncthreads();
            const int cw = tid >> 3;
            const int kk = (tid & 7) * 16;
            const float inv = sinv[cg * 32 + cw];
            int d1[16], d2[16];
            #pragma unroll
            for (int i = 0; i < 16; ++i)
                digits2(tile[kk + i][cw] * inv, d1[i], d2[i]);
            uint4 u1, u2;
            u1.x = pack4b(d1[0], d1[1], d1[2], d1[3]);
            u1.y = pack4b(d1[4], d1[5], d1[6], d1[7]);
            u1.z = pack4b(d1[8], d1[9], d1[10], d1[11]);
            u1.w = pack4b(d1[12], d1[13], d1[14], d1[15]);
            u2.x = pack4b(d2[0], d2[1], d2[2], d2[3]);
            u2.y = pack4b(d2[4], d2[5], d2[6], d2[7]);
            u2.z = pack4b(d2[8], d2[9], d2[10], d2[11]);
            u2.w = pack4b(d2[12], d2[13], d2[14], d2[15]);
            const size_t o = (size_t)(cc0 + cw) * DMODEL + k0 + kk;
            *(uint4*)(B1 + o) = u1;
            *(uint4*)(B2 + o) = u2;
            __syncthreads();
        }
    }
}

// per-row quant of a [rows,1024] fp32 matrix -> digits + scale
__global__ __launch_bounds__(256)
void rowquant_kernel(const float* __restrict__ src,
                     int8_t* __restrict__ D1, int8_t* __restrict__ D2,
                     float* __restrict__ s)
{
    const int row = blockIdx.x;
    const int tid = threadIdx.x;
    const float4 v = ((const float4*)(src + (size_t)row * DMODEL))[tid];
    float m = fmaxf(fmaxf(fabsf(v.x), fabsf(v.y)), fmaxf(fabsf(v.z), fabsf(v.w)));
    #pragma unroll
    for (int o = 16; o >= 1; o >>= 1)
        m = fmaxf(m, __shfl_xor_sync(0xffffffffu, m, o));
    __shared__ float red[8];
    if ((tid & 31) == 0) red[tid >> 5] = m;
    __syncthreads();
    float mm = red[0];
    #pragma unroll
    for (int i = 1; i < 8; i++) mm = fmaxf(mm, red[i]);
    mm = fmaxf(mm, 1e-30f);
    if (tid == 0) s[row] = mm * (1.f / 127.f);
    const float inv = 127.f / mm;
    int d1, d2;
    char4 c1, c2;
    digits2(v.x * inv, d1, d2); c1.x = (char)d1; c2.x = (char)d2;
    digits2(v.y * inv, d1, d2); c1.y = (char)d1; c2.y = (char)d2;
    digits2(v.z * inv, d1, d2); c1.z = (char)d1; c2.z = (char)d2;
    digits2(v.w * inv, d1, d2); c1.w = (char)d1; c2.w = (char)d2;
    ((char4*)(D1 + (size_t)row * DMODEL))[tid] = c1;
    ((char4*)(D2 + (size_t)row * DMODEL))[tid] = c2;
}

// ======================= int8 dual-digit GEMM cores =======================
#define QBK 64
#define QNCH (DMODEL / QBK)
#define QROWB 80
#define QARR_B (128 * QROWB)
#define QSTAGE_B (4 * QARR_B)
#define QGEMM_SMEM (2 * QSTAGE_B)

struct GemmAcc { int a1[2][8][4]; int a2[2][8][4]; };

__device__ __forceinline__ void gemm_mainloop(
    const int8_t* A1p, const int8_t* A2p, const int8_t* B1p, const int8_t* B2p,
    char* sm, uint32_t sbase, int tid, int lane, int mw0, int nw0, GemmAcc& acc)
{
    #pragma unroll
    for (int i = 0; i < 2; i++)
        #pragma unroll
        for (int j = 0; j < 8; j++)
            #pragma unroll
            for (int q = 0; q < 4; q++) { acc.a1[i][j][q] = 0; acc.a2[i][j][q] = 0; }

    const int8_t* srcs[4] = { A1p, A2p, B1p, B2p };
    const int a_row = lane & 15;
    const int a_kb  = (lane >> 4) * 16;
    const int b_row = ((lane >> 4) << 3) + (lane & 7);
    const int b_kb  = ((lane >> 3) & 1) * 16;

    auto issue_loads = [&](int c, int stage) {
        const int k0 = c * QBK;
        const uint32_t sb = sbase + stage * QSTAGE_B;
        #pragma unroll
        for (int t = 0; t < 4; t++) {
            #pragma unroll
            for (int jj = 0; jj < 2; jj++) {
                const int slot = tid + jj * 256;
                const int row = slot >> 2, col = slot & 3;
                cp16(sb + t * QARR_B + row * QROWB + col * 16,
                     srcs[t] + (size_t)row * DMODEL + k0 + col * 16);
            }
        }
    };

    issue_loads(0, 0);
    cp_commit();

    for (int c = 0; c < QNCH; ++c) {
        const int stage = c & 1;
        const bool hasNext = (c + 1 < QNCH);
        if (hasNext) { issue_loads(c + 1, stage ^ 1); cp_commit(); }
        if (hasNext) cp_wait1(); else cp_wait0();
        __syncthreads();

        const uint32_t sb = sbase + stage * QSTAGE_B;
        #pragma unroll
        for (int ks = 0; ks < 2; ++ks) {
            const int kb = ks * 32;
            uint32_t fa1[2][4], fa2[2][4];
            #pragma unroll
            for (int mi = 0; mi < 2; ++mi) {
                const uint32_t aoff = (uint32_t)(mw0 + mi * 16 + a_row) * QROWB + kb + a_kb;
                ldsm_x4(fa1[mi], sb + 0 * QARR_B + aoff);
                ldsm_x4(fa2[mi], sb + 1 * QARR_B + aoff);
            }
            #pragma unroll
            for (int nt2 = 0; nt2 < 4; ++nt2) {
                const uint32_t boff = (uint32_t)(nw0 + nt2 * 16 + b_row) * QROWB + kb + b_kb;
                uint32_t fb1[4], fb2[4];
                ldsm_x4(fb1, sb + 2 * QARR_B + boff);
                ldsm_x4(fb2, sb + 3 * QARR_B + boff);
                #pragma unroll
                for (int mi = 0; mi < 2; ++mi) {
                    #pragma unroll
                    for (int half = 0; half < 2; ++half) {
                        mma_s8(acc.a1[mi][nt2 * 2 + half], fa1[mi], fb1 + half * 2);
                        mma_s8(acc.a2[mi][nt2 * 2 + half], fa1[mi], fb2 + half * 2);
                        mma_s8(acc.a2[mi][nt2 * 2 + half], fa2[mi], fb1 + half * 2);
                    }
                }
            }
        }
        __syncthreads();
    }
}

// fused Q/K/V projection: grid (8, 32, 3)
__global__ __launch_bounds__(256, 1)
void gemm_qkv_kernel(const float* __restrict__ bq,
                     const float* __restrict__ bk,
                     const float* __restrict__ bv)
{
    extern __shared__ char sm[];
    const uint32_t sbase = smem_u32(sm);
    const int tid  = threadIdx.x;
    const int lane = tid & 31;
    const int wid  = tid >> 5;
    const int mw0  = (wid & 3) * 32;
    const int nw0  = (wid >> 2) * 64;
    const int bm   = blockIdx.y * 128;
    const int bn   = blockIdx.x * 128;
    const int z    = blockIdx.z;

    const int8_t* B1 = (z == 0) ? g_wq1 : (z == 1) ? g_wk1 : g_wv1;
    const int8_t* B2 = (z == 0) ? g_wq2 : (z == 1) ? g_wk2 : g_wv2;
    const float* bias = (z == 0) ? bq : (z == 1) ? bk : bv;
    const unsigned* sBbits = g_wbits + z * DMODEL;

    GemmAcc acc;
    gemm_mainloop(g_x1 + (size_t)bm * DMODEL, g_x2 + (size_t)bm * DMODEL,
                  B1 + (size_t)bn * DMODEL, B2 + (size_t)bn * DMODEL,
                  sm, sbase, tid, lane, mw0, nw0, acc);

    const int erow = lane >> 2;
    const int ecol = (lane & 3) * 2;
    const float* sA = g_sx;

    if (z == 2) {
        // V: single fp16 natural layout
        #pragma unroll
        for (int mi = 0; mi < 2; ++mi) {
            const int m0 = bm + mw0 + mi * 16 + erow;
            const float sa0 = sA[m0], sa8 = sA[m0 + 8];
            #pragma unroll
            for (int ni = 0; ni < 8; ++ni) {
                const int n = bn + nw0 + ni * 8 + ecol;
                const float sb0 = __uint_as_float(sBbits[n])     * (1.f / 127.f);
                const float sb1 = __uint_as_float(sBbits[n + 1]) * (1.f / 127.f);
                const float b0 = bias[n], b1 = bias[n + 1];
                const float c00 = ((float)acc.a1[mi][ni][0] + (float)acc.a2[mi][ni][0] * (1.f / 254.f)) * (sa0 * sb0) + b0;
                const float c01 = ((float)acc.a1[mi][ni][1] + (float)acc.a2[mi][ni][1] * (1.f / 254.f)) * (sa0 * sb1) + b1;
                const float c10 = ((float)acc.a1[mi][ni][2] + (float)acc.a2[mi][ni][2] * (1.f / 254.f)) * (sa8 * sb0) + b0;
                const float c11 = ((float)acc.a1[mi][ni][3] + (float)acc.a2[mi][ni][3] * (1.f / 254.f)) * (sa8 * sb1) + b1;
                *(uint32_t*)(g_v16 + (size_t)m0 * DMODEL + n)       = h2u(c00, c01);
                *(uint32_t*)(g_v16 + (size_t)(m0 + 8) * DMODEL + n) = h2u(c10, c11);
            }
        }
    } else {
        int8_t* D1 = z ? g_k1 : g_q1;
        int8_t* D2 = z ? g_k2 : g_q2;
        float* sOut = z ? g_sk : g_sq;
        const float smul = z ? 1.0f : 0.125f * 1.44269504f;  // Q: fold 1/sqrt(dk) * log2(e)
        const int head = (bn + nw0) >> 6;
        #pragma unroll
        for (int mi = 0; mi < 2; ++mi) {
            const int m0 = bm + mw0 + mi * 16 + erow;
            const float sa0 = sA[m0], sa8 = sA[m0 + 8];
            float v0[16], v1[16];
            #pragma unroll
            for (int ni = 0; ni < 8; ++ni) {
                const int n = bn + nw0 + ni * 8 + ecol;
                const float sb0 = __uint_as_float(sBbits[n])     * (1.f / 127.f);
                const float sb1 = __uint_as_float(sBbits[n + 1]) * (1.f / 127.f);
                const float b0 = bias[n], b1 = bias[n + 1];
                v0[ni * 2 + 0] = ((float)acc.a1[mi][ni][0] + (float)acc.a2[mi][ni][0] * (1.f / 254.f)) * (sa0 * sb0) + b0;
                v0[ni * 2 + 1] = ((float)acc.a1[mi][ni][1] + (float)acc.a2[mi][ni][1] * (1.f / 254.f)) * (sa0 * sb1) + b1;
                v1[ni * 2 + 0] = ((float)acc.a1[mi][ni][2] + (float)acc.a2[mi][ni][2] * (1.f / 254.f)) * (sa8 * sb0) + b0;
                v1[ni * 2 + 1] = ((float)acc.a1[mi][ni][3] + (float)acc.a2[mi][ni][3] * (1.f / 254.f)) * (sa8 * sb1) + b1;
            }
            float mx0 = 0.f, mx1 = 0.f;
            #pragma unroll
            for (int i = 0; i < 16; i++) {
                mx0 = fmaxf(mx0, fabsf(v0[i]));
                mx1 = fmaxf(mx1, fabsf(v1[i]));
            }
            mx0 = fmaxf(mx0, __shfl_xor_sync(0xffffffffu, mx0, 1));
            mx0 = fmaxf(mx0, __shfl_xor_sync(0xffffffffu, mx0, 2));
            mx1 = fmaxf(mx1, __shfl_xor_sync(0xffffffffu, mx1, 1));
            mx1 = fmaxf(mx1, __shfl_xor_sync(0xffffffffu, mx1, 2));
            mx0 = fmaxf(mx0, 1e-20f);
            mx1 = fmaxf(mx1, 1e-20f);
            if ((lane & 3) == 0) {
                sOut[head * S_LEN + m0]     = mx0 * (smul / 127.f);
                sOut[head * S_LEN + m0 + 8] = mx1 * (smul / 127.f);
            }
            const float i0 = 127.f / mx0, i1 = 127.f / mx1;
            #pragma unroll
            for (int ni = 0; ni < 8; ++ni) {
                const int n = bn + nw0 + ni * 8 + ecol;
                uint32_t w2;
                uint32_t w1 = pack_dig(v0[ni * 2] * i0, v0[ni * 2 + 1] * i0, w2);
                *(uint16_t*)(D1 + (size_t)m0 * DMODEL + n) = (uint16_t)w1;
                *(uint16_t*)(D2 + (size_t)m0 * DMODEL + n) = (uint16_t)w2;
                w1 = pack_dig(v1[ni * 2] * i1, v1[ni * 2 + 1] * i1, w2);
                *(uint16_t*)(D1 + (size_t)(m0 + 8) * DMODEL + n) = (uint16_t)w1;
                *(uint16_t*)(D2 + (size_t)(m0 + 8) * DMODEL + n) = (uint16_t)w2;
            }
        }
    }
}

// O projection: fp32 out + bias
__global__ __launch_bounds__(256, 1)
void gemm_o_kernel(const float* __restrict__ bias, float* __restrict__ C)
{
    extern __shared__ char sm[];
    const uint32_t sbase = smem_u32(sm);
    const int tid  = threadIdx.x;
    const int lane = tid & 31;
    const int wid  = tid >> 5;
    const int mw0  = (wid & 3) * 32;
    const int nw0  = (wid >> 2) * 64;
    const int bm   = blockIdx.y * 128;
    const int bn   = blockIdx.x * 128;

    GemmAcc acc;
    gemm_mainloop(g_c1 + (size_t)bm * DMODEL, g_c2 + (size_t)bm * DMODEL,
                  g_wo1 + (size_t)bn * DMODEL, g_wo2 + (size_t)bn * DMODEL,
                  sm, sbase, tid, lane, mw0, nw0, acc);

    const unsigned* sBbits = g_wbits + 3 * DMODEL;
    const int erow = lane >> 2;
    const int ecol = (lane & 3) * 2;
    #pragma unroll
    for (int mi = 0; mi < 2; ++mi) {
        const int m0 = bm + mw0 + mi * 16 + erow;
        const float sa0 = g_sc[m0], sa8 = g_sc[m0 + 8];
        #pragma unroll
        for (int ni = 0; ni < 8; ++ni) {
            const int n = bn + nw0 + ni * 8 + ecol;
            const float sb0 = __uint_as_float(sBbits[n])     * (1.f / 127.f);
            const float sb1 = __uint_as_float(sBbits[n + 1]) * (1.f / 127.f);
            const float b0 = bias[n], b1 = bias[n + 1];
            float2 v0, v1;
            v0.x = ((float)acc.a1[mi][ni][0] + (float)acc.a2[mi][ni][0] * (1.f / 254.f)) * (sa0 * sb0) + b0;
            v0.y = ((float)acc.a1[mi][ni][1] + (float)acc.a2[mi][ni][1] * (1.f / 254.f)) * (sa0 * sb1) + b1;
            v1.x = ((float)acc.a1[mi][ni][2] + (float)acc.a2[mi][ni][2] * (1.f / 254.f)) * (sa8 * sb0) + b0;
            v1.y = ((float)acc.a1[mi][ni][3] + (float)acc.a2[mi][ni][3] * (1.f / 254.f)) * (sa8 * sb1) + b1;
            *(float2*)(C + (size_t)m0 * DMODEL + n)       = v0;
            *(float2*)(C + (size_t)(m0 + 8) * DMODEL + n) = v1;
        }
    }
}

// ======================= hybrid flash attention =======================
// QK: int8 dual-digit.  PV: fp16 single x single (P regs direct, V trans-ldmatrix).
#define AK_ROWB 80
#define AK_B (128 * AK_ROWB)            // 10240 per K digit
#define AV_ROWB 144
#define AV_B (128 * AV_ROWB)            // 18432 (single fp16 V)
#define ASK_OFF (2 * AK_B + AV_B)       // 38912
#define ABUF_B (ASK_OFF + 512)          // 39424
#define ATT_SMEM (2 * ABUF_B)           // 78848

__global__ __launch_bounds__(256, 1)
void attn_kernel()
{
    extern __shared__ char sm[];
    const uint32_t sbase = smem_u32(sm);

    const int tid  = threadIdx.x;
    const int lane = tid & 31;
    const int w    = tid >> 5;
    const int h    = blockIdx.y;
    const int qt   = (int)gridDim.x - 1 - (int)blockIdx.x;
    const int q0   = qt * 128;
    const int hoff = h * DK;
    const int q0w  = q0 + w * 16;

    const int r  = lane >> 2;
    const int kc = (lane & 3) * 2;

    // Q A-fragments (int8 digits)
    uint32_t q1f[2][4], q2f[2][4];
    {
        const int qb = (lane & 3) * 4;
        #pragma unroll
        for (int g = 0; g < 2; ++g) {
            const size_t bA = (size_t)(q0w + r) * DMODEL + hoff + g * 32 + qb;
            const size_t bB = (size_t)(q0w + r + 8) * DMODEL + hoff + g * 32 + qb;
            q1f[g][0] = *(const uint32_t*)(g_q1 + bA);
            q1f[g][1] = *(const uint32_t*)(g_q1 + bB);
            q1f[g][2] = *(const uint32_t*)(g_q1 + bA + 16);
            q1f[g][3] = *(const uint32_t*)(g_q1 + bB + 16);
            q2f[g][0] = *(const uint32_t*)(g_q2 + bA);
            q2f[g][1] = *(const uint32_t*)(g_q2 + bB);
            q2f[g][2] = *(const uint32_t*)(g_q2 + bA + 16);
            q2f[g][3] = *(const uint32_t*)(g_q2 + bB + 16);
        }
    }
    const float sq0f = g_sq[h * S_LEN + q0w + r]     * (1.f / 254.f);
    const float sq1f = g_sq[h * S_LEN + q0w + r + 8] * (1.f / 254.f);

    auto issue_kv = [&](int kt, int buf) {
        const int k0 = kt * 128;
        const uint32_t sb = sbase + buf * ABUF_B;
        // K digits
        #pragma unroll
        for (int d = 0; d < 2; ++d) {
            const int8_t* src = (d ? g_k2 : g_k1) + (size_t)k0 * DMODEL + hoff;
            #pragma unroll
            for (int j = 0; j < 2; ++j) {
                const int slot = tid + j * 256;
                const int row = slot >> 2, col = slot & 3;
                cp16(sb + d * AK_B + row * AK_ROWB + col * 16,
                     src + (size_t)row * DMODEL + col * 16);
            }
        }
        // V fp16 natural [token][d]
        {
            const __half* src = g_v16 + (size_t)k0 * DMODEL + hoff;
            #pragma unroll
            for (int j = 0; j < 4; ++j) {
                const int slot = tid + j * 256;
                const int row = slot >> 3, col = slot & 7;
                cp16(sb + 2 * AK_B + row * AV_ROWB + col * 16,
                     src + (size_t)row * DMODEL + col * 8);
            }
        }
        if (tid < 32)
            cp16(sb + ASK_OFF + tid * 16, g_sk + h * S_LEN + k0 + tid * 4);
    };

    float m_[2] = { -1e30f, -1e30f }, l_[2] = { 0.f, 0.f };
    float oacc[8][4];
    #pragma unroll
    for (int i = 0; i < 8; i++)
        #pragma unroll
        for (int j = 0; j < 4; j++) oacc[i][j] = 0.f;

    issue_kv(0, 0);
    cp_commit();

    const uint32_t b_off  = (uint32_t)(((lane >> 4) << 3) + (lane & 7));
    const uint32_t kb_off = ((lane >> 3) & 1) * 16;
    const uint32_t vrow   = lane & 15;
    const uint32_t vcol   = (lane >> 4) * 8;

    for (int kt = 0; kt <= qt; ++kt) {
        const int buf = kt & 1;
        const bool hasNext = kt < qt;
        if (hasNext) { issue_kv(kt + 1, buf ^ 1); cp_commit(); }
        if (hasNext) cp_wait1(); else cp_wait0();
        __syncthreads();

        const uint32_t k1b = sbase + buf * ABUF_B;
        const uint32_t k2b = k1b + AK_B;
        const uint32_t v_b = k1b + 2 * AK_B;
        const float* sks = (const float*)(sm + buf * ABUF_B + ASK_OFF);

        // ---- S = Q @ K^T (dual-digit int8); scores in log2 units ----
        float s[16][4];
        #pragma unroll
        for (int nt2 = 0; nt2 < 8; ++nt2) {
            int a1[2][4] = { {0,0,0,0}, {0,0,0,0} };
            int a2[2][4] = { {0,0,0,0}, {0,0,0,0} };
            #pragma unroll
            for (int g = 0; g < 2; ++g) {
                const uint32_t addr = (uint32_t)(nt2 * 16 + b_off) * AK_ROWB + g * 32 + kb_off;
                uint32_t fb1[4], fb2[4];
                ldsm_x4(fb1, k1b + addr);
                ldsm_x4(fb2, k2b + addr);
                #pragma unroll
                for (int hf = 0; hf < 2; ++hf) {
                    mma_s8(a1[hf], q1f[g], fb1 + hf * 2);
                    mma_s8(a2[hf], q1f[g], fb2 + hf * 2);
                    mma_s8(a2[hf], q2f[g], fb1 + hf * 2);
                }
            }
            #pragma unroll
            for (int hf = 0; hf < 2; ++hf) {
                const float2 sk2 = *(const float2*)(sks + (nt2 * 2 + hf) * 8 + kc);
                s[nt2 * 2 + hf][0] = (float)(a1[hf][0] * 254 + a2[hf][0]) * (sq0f * sk2.x);
                s[nt2 * 2 + hf][1] = (float)(a1[hf][1] * 254 + a2[hf][1]) * (sq0f * sk2.y);
                s[nt2 * 2 + hf][2] = (float)(a1[hf][2] * 254 + a2[hf][2]) * (sq1f * sk2.x);
                s[nt2 * 2 + hf][3] = (float)(a1[hf][3] * 254 + a2[hf][3]) * (sq1f * sk2.y);
            }
        }

        // causal mask on diagonal tile
        if (kt == qt) {
            #pragma unroll
            for (int nt = 0; nt < 16; ++nt) {
                #pragma unroll
                for (int c = 0; c < 4; ++c) {
                    const int key = nt * 8 + kc + (c & 1);
                    const int qq  = w * 16 + r + (c >> 1) * 8;
                    if (key > qq) s[nt][c] = -1e30f;
                }
            }
        }

        // ---- online softmax (base-2) ----
        float mx0 = -1e30f, mx1 = -1e30f;
        #pragma unroll
        for (int nt = 0; nt < 16; ++nt) {
            mx0 = fmaxf(mx0, fmaxf(s[nt][0], s[nt][1]));
            mx1 = fmaxf(mx1, fmaxf(s[nt][2], s[nt][3]));
        }
        mx0 = fmaxf(mx0, __shfl_xor_sync(0xffffffffu, mx0, 1));
        mx0 = fmaxf(mx0, __shfl_xor_sync(0xffffffffu, mx0, 2));
        mx1 = fmaxf(mx1, __shfl_xor_sync(0xffffffffu, mx1, 1));
        mx1 = fmaxf(mx1, __shfl_xor_sync(0xffffffffu, mx1, 2));

        const float nm0 = fmaxf(m_[0], mx0), nm1 = fmaxf(m_[1], mx1);
        const float al0 = ex2f(m_[0] - nm0), al1 = ex2f(m_[1] - nm1);
        float rs0 = 0.f, rs1 = 0.f;
        #pragma unroll
        for (int nt = 0; nt < 16; ++nt) {
            s[nt][0] = ex2f(s[nt][0] - nm0);
            s[nt][1] = ex2f(s[nt][1] - nm0);
            s[nt][2] = ex2f(s[nt][2] - nm1);
            s[nt][3] = ex2f(s[nt][3] - nm1);
            rs0 += s[nt][0] + s[nt][1];
            rs1 += s[nt][2] + s[nt][3];
        }
        rs0 += __shfl_xor_sync(0xffffffffu, rs0, 1);
        rs0 += __shfl_xor_sync(0xffffffffu, rs0, 2);
        rs1 += __shfl_xor_sync(0xffffffffu, rs1, 1);
        rs1 += __shfl_xor_sync(0xffffffffu, rs1, 2);

        l_[0] = l_[0] * al0 + rs0;  m_[0] = nm0;
        l_[1] = l_[1] * al1 + rs1;  m_[1] = nm1;
        #pragma unroll
        for (int dt = 0; dt < 8; ++dt) {
            oacc[dt][0] *= al0; oacc[dt][1] *= al0;
            oacc[dt][2] *= al1; oacc[dt][3] *= al1;
        }

        // ---- O += P @ V (P fp16 in regs; V fp16 via trans-ldmatrix) ----
        #pragma unroll
        for (int j = 0; j < 8; ++j) {
            uint32_t pa[4];
            pa[0] = h2u(s[2*j][0],   s[2*j][1]);
            pa[1] = h2u(s[2*j][2],   s[2*j][3]);
            pa[2] = h2u(s[2*j+1][0], s[2*j+1][1]);
            pa[3] = h2u(s[2*j+1][2], s[2*j+1][3]);

            const uint32_t abase = (j * 16 + vrow) * AV_ROWB + vcol * 2;
            #pragma unroll
            for (int dg = 0; dg < 4; ++dg) {
                uint32_t bv[4];
                ldsm_x4_t(bv, v_b + abase + dg * 32);
                mma_f16(oacc[dg * 2 + 0], pa, bv + 0);
                mma_f16(oacc[dg * 2 + 1], pa, bv + 2);
            }
        }
        __syncthreads();
    }

    // epilogue: normalize, write fp32 ctx
    const float inv0 = 1.f / l_[0], inv1 = 1.f / l_[1];
    #pragma unroll
    for (int dt = 0; dt < 8; ++dt) {
        const size_t d = (size_t)hoff + dt * 8 + kc;
        const size_t rowA = (size_t)(q0w + r) * DMODEL + d;
        const size_t rowB = (size_t)(q0w + r + 8) * DMODEL + d;
        float2 a0 = { oacc[dt][0] * inv0, oacc[dt][1] * inv0 };
        float2 a1 = { oacc[dt][2] * inv1, oacc[dt][3] * inv1 };
        *(float2*)(g_ctx + rowA) = a0;
        *(float2*)(g_ctx + rowB) = a1;
    }
}

// ======================= host launcher =======================
extern "C" void kernel_launch(void* const* d_in, const int* in_sizes, int n_in,
                              void* d_out, int out_size)
{
    (void)in_sizes; (void)n_in; (void)out_size;
    const float* x  = (const float*)d_in[0];
    const float* Wq = (const float*)d_in[2];
    const float* bq = (const float*)d_in[3];
    const float* Wk = (const float*)d_in[4];
    const float* bk = (const float*)d_in[5];
    const float* Wv = (const float*)d_in[6];
    const float* bv = (const float*)d_in[7];
    const float* Wo = (const float*)d_in[8];
    const float* bo = (const float*)d_in[9];
    float* out = (float*)d_out;

    int8_t *x1, *x2, *c1, *c2;
    float *sx, *sc, *ctx;
    cudaGetSymbolAddress((void**)&x1, g_x1);
    cudaGetSymbolAddress((void**)&x2, g_x2);
    cudaGetSymbolAddress((void**)&sx, g_sx);
    cudaGetSymbolAddress((void**)&c1, g_c1);
    cudaGetSymbolAddress((void**)&c2, g_c2);
    cudaGetSymbolAddress((void**)&sc, g_sc);
    cudaGetSymbolAddress((void**)&ctx, g_ctx);

    cudaFuncSetAttribute(gemm_qkv_kernel,
                         cudaFuncAttributeMaxDynamicSharedMemorySize, QGEMM_SMEM);
    cudaFuncSetAttribute(gemm_o_kernel,
                         cudaFuncAttributeMaxDynamicSharedMemorySize, QGEMM_SMEM);
    cudaFuncSetAttribute(attn_kernel,
                         cudaFuncAttributeMaxDynamicSharedMemorySize, ATT_SMEM);

    // 1: fused weight colmax + transpose-quant
    wprep_kernel<<<dim3(8, 4), 256>>>(Wq, Wk, Wv, Wo);
    // 2: input row-quant
    rowquant_kernel<<<S_LEN, 256>>>(x, x1, x2, sx);
    // 3: fused Q/K/V projections
    gemm_qkv_kernel<<<dim3(8, 32, 3), 256, QGEMM_SMEM>>>(bq, bk, bv);
    // 4: attention  (profiled slot)
    attn_kernel<<<dim3(S_LEN / 128, NHEADS), 256, ATT_SMEM>>>();
    // 5: ctx row-quant
    rowquant_kernel<<<S_LEN, 256>>>(ctx, c1, c2, sc);
    // 6: O projection
    gemm_o_kernel<<<dim3(8, 32), 256, QGEMM_SMEM>>>(bo, out);
}

// round 10
// speedup vs baseline: 4.0876x; 1.0090x over previous
#include <cuda_runtime.h>
#include <cuda_bf16.h>
#include <cuda_fp16.h>
#include <cstdint>
#include <math.h>

#define S_LEN  4096
#define DMODEL 1024
#define NHEADS 16
#define DK     64

// ======================= scratch (device globals) =======================
__device__ int8_t g_x1[(size_t)S_LEN * DMODEL];
__device__ int8_t g_x2[(size_t)S_LEN * DMODEL];
__device__ float  g_sx[S_LEN];

__device__ int8_t g_wq1[(size_t)DMODEL * DMODEL];
__device__ int8_t g_wq2[(size_t)DMODEL * DMODEL];
__device__ int8_t g_wk1[(size_t)DMODEL * DMODEL];
__device__ int8_t g_wk2[(size_t)DMODEL * DMODEL];
__device__ int8_t g_wv1[(size_t)DMODEL * DMODEL];
__device__ int8_t g_wv2[(size_t)DMODEL * DMODEL];
__device__ int8_t g_wo1[(size_t)DMODEL * DMODEL];
__device__ int8_t g_wo2[(size_t)DMODEL * DMODEL];
__device__ unsigned g_wbits[4 * DMODEL];

// attention operands
__device__ int8_t g_q1[(size_t)S_LEN * DMODEL];
__device__ int8_t g_q2[(size_t)S_LEN * DMODEL];
__device__ int8_t g_k1[(size_t)S_LEN * DMODEL];
__device__ int8_t g_k2[(size_t)S_LEN * DMODEL];
__device__ float  g_sq[NHEADS * S_LEN];
__device__ float  g_sk[NHEADS * S_LEN];
__device__ __half g_v16[(size_t)S_LEN * DMODEL];

__device__ float  g_ctx[(size_t)S_LEN * DMODEL];
__device__ int8_t g_c1[(size_t)S_LEN * DMODEL];
__device__ int8_t g_c2[(size_t)S_LEN * DMODEL];
__device__ float  g_sc[S_LEN];

// ======================= helpers =======================
__device__ __forceinline__ uint32_t smem_u32(const void* p) {
    uint32_t a;
    asm("{ .reg .u64 t; cvta.to.shared.u64 t, %1; cvt.u32.u64 %0, t; }" : "=r"(a) : "l"(p));
    return a;
}
__device__ __forceinline__ void cp16(uint32_t saddr, const void* g) {
    asm volatile("cp.async.ca.shared.global [%0], [%1], 16;" :: "r"(saddr), "l"(g));
}
__device__ __forceinline__ void cp_commit() { asm volatile("cp.async.commit_group;"); }
__device__ __forceinline__ void cp_wait1()  { asm volatile("cp.async.wait_group 1;"); }
__device__ __forceinline__ void cp_wait0()  { asm volatile("cp.async.wait_group 0;"); }

__device__ __forceinline__ void ldsm_x4(uint32_t* r, uint32_t addr) {
    asm volatile("ldmatrix.sync.aligned.m8n8.x4.shared.b16 {%0,%1,%2,%3}, [%4];"
                 : "=r"(r[0]), "=r"(r[1]), "=r"(r[2]), "=r"(r[3]) : "r"(addr));
}
__device__ __forceinline__ void ldsm_x4_t(uint32_t* r, uint32_t addr) {
    asm volatile("ldmatrix.sync.aligned.m8n8.x4.trans.shared.b16 {%0,%1,%2,%3}, [%4];"
                 : "=r"(r[0]), "=r"(r[1]), "=r"(r[2]), "=r"(r[3]) : "r"(addr));
}
__device__ __forceinline__ void mma_s8(int* c, const uint32_t* a, const uint32_t* b) {
    asm volatile(
        "mma.sync.aligned.m16n8k32.row.col.s32.s8.s8.s32 "
        "{%0,%1,%2,%3}, {%4,%5,%6,%7}, {%8,%9}, {%0,%1,%2,%3};"
        : "+r"(c[0]), "+r"(c[1]), "+r"(c[2]), "+r"(c[3])
        : "r"(a[0]), "r"(a[1]), "r"(a[2]), "r"(a[3]), "r"(b[0]), "r"(b[1]));
}
__device__ __forceinline__ void mma_f16(float* c, const uint32_t* a, const uint32_t* b) {
    asm volatile(
        "mma.sync.aligned.m16n8k16.row.col.f32.f16.f16.f32 "
        "{%0,%1,%2,%3}, {%4,%5,%6,%7}, {%8,%9}, {%0,%1,%2,%3};"
        : "+f"(c[0]), "+f"(c[1]), "+f"(c[2]), "+f"(c[3])
        : "r"(a[0]), "r"(a[1]), "r"(a[2]), "r"(a[3]), "r"(b[0]), "r"(b[1]));
}
__device__ __forceinline__ float ex2f(float x) {
    float y;
    asm("ex2.approx.f32 %0, %1;" : "=f"(y) : "f"(x));
    return y;
}
__device__ __forceinline__ uint32_t h2u(float x, float y) {
    __half2 h = __floats2half2_rn(x, y);
    return *(uint32_t*)&h;
}
__device__ __forceinline__ void digits2(float alpha, int& d1, int& d2) {
    d1 = __float2int_rn(alpha);
    d2 = __float2int_rn((alpha - (float)d1) * 254.f);
}
__device__ __forceinline__ uint32_t pack_dig(float a, float b, uint32_t& w2) {
    int a1, a2, b1, b2;
    digits2(a, a1, a2);
    digits2(b, b1, b2);
    w2 = (uint32_t)(a2 & 0xff) | (((uint32_t)(b2 & 0xff)) << 8);
    return (uint32_t)(a1 & 0xff) | (((uint32_t)(b1 & 0xff)) << 8);
}
__device__ __forceinline__ uint32_t pack4b(int a, int b, int c, int d) {
    return (uint32_t)(a & 0xff) | (((uint32_t)(b & 0xff)) << 8) |
           (((uint32_t)(c & 0xff)) << 16) | (((uint32_t)(d & 0xff)) << 24);
}

// ======================= fused weight prep =======================
__global__ __launch_bounds__(256)
void wprep_kernel(const float* __restrict__ Wq, const float* __restrict__ Wk,
                  const float* __restrict__ Wv, const float* __restrict__ Wo)
{
    const int z = blockIdx.y;
    const float* W = (z == 0) ? Wq : (z == 1) ? Wk : (z == 2) ? Wv : Wo;
    int8_t* B1 = (z == 0) ? g_wq1 : (z == 1) ? g_wk1 : (z == 2) ? g_wv1 : g_wo1;
    int8_t* B2 = (z == 0) ? g_wq2 : (z == 1) ? g_wk2 : (z == 2) ? g_wv2 : g_wo2;
    unsigned* bits = g_wbits + z * DMODEL;

    const int tid = threadIdx.x;
    const int c0 = blockIdx.x * 128;

    __shared__ float pm[2][128];
    __shared__ float sinv[128];
    __shared__ float tile[128][33];

    {
        const int col = c0 + (tid & 127);
        const int half = tid >> 7;
        float m = 0.f;
        for (int r = half; r < DMODEL; r += 2)
            m = fmaxf(m, fabsf(W[(size_t)r * DMODEL + col]));
        pm[half][tid & 127] = m;
    }
    __syncthreads();
    if (tid < 128) {
        const float mx = fmaxf(fmaxf(pm[0][tid], pm[1][tid]), 1e-30f);
        bits[c0 + tid] = __float_as_uint(mx);
        sinv[tid] = 127.f / mx;
    }
    __syncthreads();

    for (int kg = 0; kg < 8; ++kg) {
        const int k0 = kg * 128;
        for (int cg = 0; cg < 4; ++cg) {
            const int cc0 = c0 + cg * 32;
            #pragma unroll
            for (int i = 0; i < 16; ++i) {
                const int idx = tid + i * 256;
                const int kr = idx >> 5, cc = idx & 31;
                tile[kr][cc] = W[(size_t)(k0 + kr) * DMODEL + cc0 + cc];
            }
            __syncthreads();
            const int cw = tid >> 3;
            const int kk = (tid & 7) * 16;
            const float inv = sinv[cg * 32 + cw];
            int d1[16], d2[16];
            #pragma unroll
            for (int i = 0; i < 16; ++i)
                digits2(tile[kk + i][cw] * inv, d1[i], d2[i]);
            uint4 u1, u2;
            u1.x = pack4b(d1[0], d1[1], d1[2], d1[3]);
            u1.y = pack4b(d1[4], d1[5], d1[6], d1[7]);
            u1.z = pack4b(d1[8], d1[9], d1[10], d1[11]);
            u1.w = pack4b(d1[12], d1[13], d1[14], d1[15]);
            u2.x = pack4b(d2[0], d2[1], d2[2], d2[3]);
            u2.y = pack4b(d2[4], d2[5], d2[6], d2[7]);
            u2.z = pack4b(d2[8], d2[9], d2[10], d2[11]);
            u2.w = pack4b(d2[12], d2[13], d2[14], d2[15]);
            const size_t o = (size_t)(cc0 + cw) * DMODEL + k0 + kk;
            *(uint4*)(B1 + o) = u1;
            *(uint4*)(B2 + o) = u2;
            __syncthreads();
        }
    }
}

// per-row quant of a [rows,1024] fp32 matrix -> digits + scale
__global__ __launch_bounds__(256)
void rowquant_kernel(const float* __restrict__ src,
                     int8_t* __restrict__ D1, int8_t* __restrict__ D2,
                     float* __restrict__ s)
{
    const int row = blockIdx.x;
    const int tid = threadIdx.x;
    const float4 v = ((const float4*)(src + (size_t)row * DMODEL))[tid];
    float m = fmaxf(fmaxf(fabsf(v.x), fabsf(v.y)), fmaxf(fabsf(v.z), fabsf(v.w)));
    #pragma unroll
    for (int o = 16; o >= 1; o >>= 1)
        m = fmaxf(m, __shfl_xor_sync(0xffffffffu, m, o));
    __shared__ float red[8];
    if ((tid & 31) == 0) red[tid >> 5] = m;
    __syncthreads();
    float mm = red[0];
    #pragma unroll
    for (int i = 1; i < 8; i++) mm = fmaxf(mm, red[i]);
    mm = fmaxf(mm, 1e-30f);
    if (tid == 0) s[row] = mm * (1.f / 127.f);
    const float inv = 127.f / mm;
    int d1, d2;
    char4 c1, c2;
    digits2(v.x * inv, d1, d2); c1.x = (char)d1; c2.x = (char)d2;
    digits2(v.y * inv, d1, d2); c1.y = (char)d1; c2.y = (char)d2;
    digits2(v.z * inv, d1, d2); c1.z = (char)d1; c2.z = (char)d2;
    digits2(v.w * inv, d1, d2); c1.w = (char)d1; c2.w = (char)d2;
    ((char4*)(D1 + (size_t)row * DMODEL))[tid] = c1;
    ((char4*)(D2 + (size_t)row * DMODEL))[tid] = c2;
}

// ======================= int8 dual-digit GEMM cores =======================
#define QBK 64
#define QNCH (DMODEL / QBK)
#define QROWB 80
#define QARR_B (128 * QROWB)
#define QSTAGE_B (4 * QARR_B)
#define QGEMM_SMEM (2 * QSTAGE_B)

struct GemmAcc { int a1[2][8][4]; int a2[2][8][4]; };

__device__ __forceinline__ void gemm_mainloop(
    const int8_t* A1p, const int8_t* A2p, const int8_t* B1p, const int8_t* B2p,
    char* sm, uint32_t sbase, int tid, int lane, int mw0, int nw0, GemmAcc& acc)
{
    #pragma unroll
    for (int i = 0; i < 2; i++)
        #pragma unroll
        for (int j = 0; j < 8; j++)
            #pragma unroll
            for (int q = 0; q < 4; q++) { acc.a1[i][j][q] = 0; acc.a2[i][j][q] = 0; }

    const int8_t* srcs[4] = { A1p, A2p, B1p, B2p };
    const int a_row = lane & 15;
    const int a_kb  = (lane >> 4) * 16;
    const int b_row = ((lane >> 4) << 3) + (lane & 7);
    const int b_kb  = ((lane >> 3) & 1) * 16;

    auto issue_loads = [&](int c, int stage) {
        const int k0 = c * QBK;
        const uint32_t sb = sbase + stage * QSTAGE_B;
        #pragma unroll
        for (int t = 0; t < 4; t++) {
            #pragma unroll
            for (int jj = 0; jj < 2; jj++) {
                const int slot = tid + jj * 256;
                const int row = slot >> 2, col = slot & 3;
                cp16(sb + t * QARR_B + row * QROWB + col * 16,
                     srcs[t] + (size_t)row * DMODEL + k0 + col * 16);
            }
        }
    };

    issue_loads(0, 0);
    cp_commit();

    for (int c = 0; c < QNCH; ++c) {
        const int stage = c & 1;
        const bool hasNext = (c + 1 < QNCH);
        if (hasNext) { issue_loads(c + 1, stage ^ 1); cp_commit(); }
        if (hasNext) cp_wait1(); else cp_wait0();
        __syncthreads();

        const uint32_t sb = sbase + stage * QSTAGE_B;
        #pragma unroll
        for (int ks = 0; ks < 2; ++ks) {
            const int kb = ks * 32;
            uint32_t fa1[2][4], fa2[2][4];
            #pragma unroll
            for (int mi = 0; mi < 2; ++mi) {
                const uint32_t aoff = (uint32_t)(mw0 + mi * 16 + a_row) * QROWB + kb + a_kb;
                ldsm_x4(fa1[mi], sb + 0 * QARR_B + aoff);
                ldsm_x4(fa2[mi], sb + 1 * QARR_B + aoff);
            }
            #pragma unroll
            for (int nt2 = 0; nt2 < 4; ++nt2) {
                const uint32_t boff = (uint32_t)(nw0 + nt2 * 16 + b_row) * QROWB + kb + b_kb;
                uint32_t fb1[4], fb2[4];
                ldsm_x4(fb1, sb + 2 * QARR_B + boff);
                ldsm_x4(fb2, sb + 3 * QARR_B + boff);
                #pragma unroll
                for (int mi = 0; mi < 2; ++mi) {
                    #pragma unroll
                    for (int half = 0; half < 2; ++half) {
                        mma_s8(acc.a1[mi][nt2 * 2 + half], fa1[mi], fb1 + half * 2);
                        mma_s8(acc.a2[mi][nt2 * 2 + half], fa1[mi], fb2 + half * 2);
                        mma_s8(acc.a2[mi][nt2 * 2 + half], fa2[mi], fb1 + half * 2);
                    }
                }
            }
        }
        __syncthreads();
    }
}

// fused Q/K/V projection: grid (8, 32, 3)
__global__ __launch_bounds__(256, 1)
void gemm_qkv_kernel(const float* __restrict__ bq,
                     const float* __restrict__ bk,
                     const float* __restrict__ bv)
{
    extern __shared__ char sm[];
    const uint32_t sbase = smem_u32(sm);
    const int tid  = threadIdx.x;
    const int lane = tid & 31;
    const int wid  = tid >> 5;
    const int mw0  = (wid & 3) * 32;
    const int nw0  = (wid >> 2) * 64;
    const int bm   = blockIdx.y * 128;
    const int bn   = blockIdx.x * 128;
    const int z    = blockIdx.z;

    const int8_t* B1 = (z == 0) ? g_wq1 : (z == 1) ? g_wk1 : g_wv1;
    const int8_t* B2 = (z == 0) ? g_wq2 : (z == 1) ? g_wk2 : g_wv2;
    const float* bias = (z == 0) ? bq : (z == 1) ? bk : bv;
    const unsigned* sBbits = g_wbits + z * DMODEL;

    GemmAcc acc;
    gemm_mainloop(g_x1 + (size_t)bm * DMODEL, g_x2 + (size_t)bm * DMODEL,
                  B1 + (size_t)bn * DMODEL, B2 + (size_t)bn * DMODEL,
                  sm, sbase, tid, lane, mw0, nw0, acc);

    const int erow = lane >> 2;
    const int ecol = (lane & 3) * 2;
    const float* sA = g_sx;

    if (z == 2) {
        // V: single fp16 natural layout
        #pragma unroll
        for (int mi = 0; mi < 2; ++mi) {
            const int m0 = bm + mw0 + mi * 16 + erow;
            const float sa0 = sA[m0], sa8 = sA[m0 + 8];
            #pragma unroll
            for (int ni = 0; ni < 8; ++ni) {
                const int n = bn + nw0 + ni * 8 + ecol;
                const float sb0 = __uint_as_float(sBbits[n])     * (1.f / 127.f);
                const float sb1 = __uint_as_float(sBbits[n + 1]) * (1.f / 127.f);
                const float b0 = bias[n], b1 = bias[n + 1];
                const float c00 = ((float)acc.a1[mi][ni][0] + (float)acc.a2[mi][ni][0] * (1.f / 254.f)) * (sa0 * sb0) + b0;
                const float c01 = ((float)acc.a1[mi][ni][1] + (float)acc.a2[mi][ni][1] * (1.f / 254.f)) * (sa0 * sb1) + b1;
                const float c10 = ((float)acc.a1[mi][ni][2] + (float)acc.a2[mi][ni][2] * (1.f / 254.f)) * (sa8 * sb0) + b0;
                const float c11 = ((float)acc.a1[mi][ni][3] + (float)acc.a2[mi][ni][3] * (1.f / 254.f)) * (sa8 * sb1) + b1;
                *(uint32_t*)(g_v16 + (size_t)m0 * DMODEL + n)       = h2u(c00, c01);
                *(uint32_t*)(g_v16 + (size_t)(m0 + 8) * DMODEL + n) = h2u(c10, c11);
            }
        }
    } else {
        int8_t* D1 = z ? g_k1 : g_q1;
        int8_t* D2 = z ? g_k2 : g_q2;
        float* sOut = z ? g_sk : g_sq;
        const float smul = z ? 1.0f : 0.125f * 1.44269504f;  // Q: fold 1/sqrt(dk) * log2(e)
        const int head = (bn + nw0) >> 6;
        #pragma unroll
        for (int mi = 0; mi < 2; ++mi) {
            const int m0 = bm + mw0 + mi * 16 + erow;
            const float sa0 = sA[m0], sa8 = sA[m0 + 8];
            float v0[16], v1[16];
            #pragma unroll
            for (int ni = 0; ni < 8; ++ni) {
                const int n = bn + nw0 + ni * 8 + ecol;
                const float sb0 = __uint_as_float(sBbits[n])     * (1.f / 127.f);
                const float sb1 = __uint_as_float(sBbits[n + 1]) * (1.f / 127.f);
                const float b0 = bias[n], b1 = bias[n + 1];
                v0[ni * 2 + 0] = ((float)acc.a1[mi][ni][0] + (float)acc.a2[mi][ni][0] * (1.f / 254.f)) * (sa0 * sb0) + b0;
                v0[ni * 2 + 1] = ((float)acc.a1[mi][ni][1] + (float)acc.a2[mi][ni][1] * (1.f / 254.f)) * (sa0 * sb1) + b1;
                v1[ni * 2 + 0] = ((float)acc.a1[mi][ni][2] + (float)acc.a2[mi][ni][2] * (1.f / 254.f)) * (sa8 * sb0) + b0;
                v1[ni * 2 + 1] = ((float)acc.a1[mi][ni][3] + (float)acc.a2[mi][ni][3] * (1.f / 254.f)) * (sa8 * sb1) + b1;
            }
            float mx0 = 0.f, mx1 = 0.f;
            #pragma unroll
            for (int i = 0; i < 16; i++) {
                mx0 = fmaxf(mx0, fabsf(v0[i]));
                mx1 = fmaxf(mx1, fabsf(v1[i]));
            }
            mx0 = fmaxf(mx0, __shfl_xor_sync(0xffffffffu, mx0, 1));
            mx0 = fmaxf(mx0, __shfl_xor_sync(0xffffffffu, mx0, 2));
            mx1 = fmaxf(mx1, __shfl_xor_sync(0xffffffffu, mx1, 1));
            mx1 = fmaxf(mx1, __shfl_xor_sync(0xffffffffu, mx1, 2));
            mx0 = fmaxf(mx0, 1e-20f);
            mx1 = fmaxf(mx1, 1e-20f);
            if ((lane & 3) == 0) {
                sOut[head * S_LEN + m0]     = mx0 * (smul / 127.f);
                sOut[head * S_LEN + m0 + 8] = mx1 * (smul / 127.f);
            }
            const float i0 = 127.f / mx0, i1 = 127.f / mx1;
            #pragma unroll
            for (int ni = 0; ni < 8; ++ni) {
                const int n = bn + nw0 + ni * 8 + ecol;
                uint32_t w2;
                uint32_t w1 = pack_dig(v0[ni * 2] * i0, v0[ni * 2 + 1] * i0, w2);
                *(uint16_t*)(D1 + (size_t)m0 * DMODEL + n) = (uint16_t)w1;
                *(uint16_t*)(D2 + (size_t)m0 * DMODEL + n) = (uint16_t)w2;
                w1 = pack_dig(v1[ni * 2] * i1, v1[ni * 2 + 1] * i1, w2);
                *(uint16_t*)(D1 + (size_t)(m0 + 8) * DMODEL + n) = (uint16_t)w1;
                *(uint16_t*)(D2 + (size_t)(m0 + 8) * DMODEL + n) = (uint16_t)w2;
            }
        }
    }
}

// O projection: fp32 out + bias
__global__ __launch_bounds__(256, 1)
void gemm_o_kernel(const float* __restrict__ bias, float* __restrict__ C)
{
    extern __shared__ char sm[];
    const uint32_t sbase = smem_u32(sm);
    const int tid  = threadIdx.x;
    const int lane = tid & 31;
    const int wid  = tid >> 5;
    const int mw0  = (wid & 3) * 32;
    const int nw0  = (wid >> 2) * 64;
    const int bm   = blockIdx.y * 128;
    const int bn   = blockIdx.x * 128;

    GemmAcc acc;
    gemm_mainloop(g_c1 + (size_t)bm * DMODEL, g_c2 + (size_t)bm * DMODEL,
                  g_wo1 + (size_t)bn * DMODEL, g_wo2 + (size_t)bn * DMODEL,
                  sm, sbase, tid, lane, mw0, nw0, acc);

    const unsigned* sBbits = g_wbits + 3 * DMODEL;
    const int erow = lane >> 2;
    const int ecol = (lane & 3) * 2;
    #pragma unroll
    for (int mi = 0; mi < 2; ++mi) {
        const int m0 = bm + mw0 + mi * 16 + erow;
        const float sa0 = g_sc[m0], sa8 = g_sc[m0 + 8];
        #pragma unroll
        for (int ni = 0; ni < 8; ++ni) {
            const int n = bn + nw0 + ni * 8 + ecol;
            const float sb0 = __uint_as_float(sBbits[n])     * (1.f / 127.f);
            const float sb1 = __uint_as_float(sBbits[n + 1]) * (1.f / 127.f);
            const float b0 = bias[n], b1 = bias[n + 1];
            float2 v0, v1;
            v0.x = ((float)acc.a1[mi][ni][0] + (float)acc.a2[mi][ni][0] * (1.f / 254.f)) * (sa0 * sb0) + b0;
            v0.y = ((float)acc.a1[mi][ni][1] + (float)acc.a2[mi][ni][1] * (1.f / 254.f)) * (sa0 * sb1) + b1;
            v1.x = ((float)acc.a1[mi][ni][2] + (float)acc.a2[mi][ni][2] * (1.f / 254.f)) * (sa8 * sb0) + b0;
            v1.y = ((float)acc.a1[mi][ni][3] + (float)acc.a2[mi][ni][3] * (1.f / 254.f)) * (sa8 * sb1) + b1;
            *(float2*)(C + (size_t)m0 * DMODEL + n)       = v0;
            *(float2*)(C + (size_t)(m0 + 8) * DMODEL + n) = v1;
        }
    }
}

// ======================= hybrid flash attention =======================
// QK: int8 dual-digit.  PV: fp16.  Tile processed in two 64-key halves to
// shrink the live score set (s[8][4]); __launch_bounds__(256,2) -> 2 CTAs/SM.
#define AK_ROWB 80
#define AK_B (128 * AK_ROWB)            // 10240 per K digit
#define AV_ROWB 144
#define AV_B (128 * AV_ROWB)            // 18432 (single fp16 V)
#define ASK_OFF (2 * AK_B + AV_B)       // 38912
#define ABUF_B (ASK_OFF + 512)          // 39424
#define ATT_SMEM (2 * ABUF_B)           // 78848

__global__ __launch_bounds__(256, 2)
void attn_kernel()
{
    extern __shared__ char sm[];
    const uint32_t sbase = smem_u32(sm);

    const int tid  = threadIdx.x;
    const int lane = tid & 31;
    const int w    = tid >> 5;
    const int h    = blockIdx.y;
    const int qt   = (int)gridDim.x - 1 - (int)blockIdx.x;
    const int q0   = qt * 128;
    const int hoff = h * DK;
    const int q0w  = q0 + w * 16;

    const int r  = lane >> 2;
    const int kc = (lane & 3) * 2;

    // Q A-fragments (int8 digits)
    uint32_t q1f[2][4], q2f[2][4];
    {
        const int qb = (lane & 3) * 4;
        #pragma unroll
        for (int g = 0; g < 2; ++g) {
            const size_t bA = (size_t)(q0w + r) * DMODEL + hoff + g * 32 + qb;
            const size_t bB = (size_t)(q0w + r + 8) * DMODEL + hoff + g * 32 + qb;
            q1f[g][0] = *(const uint32_t*)(g_q1 + bA);
            q1f[g][1] = *(const uint32_t*)(g_q1 + bB);
            q1f[g][2] = *(const uint32_t*)(g_q1 + bA + 16);
            q1f[g][3] = *(const uint32_t*)(g_q1 + bB + 16);
            q2f[g][0] = *(const uint32_t*)(g_q2 + bA);
            q2f[g][1] = *(const uint32_t*)(g_q2 + bB);
            q2f[g][2] = *(const uint32_t*)(g_q2 + bA + 16);
            q2f[g][3] = *(const uint32_t*)(g_q2 + bB + 16);
        }
    }
    const float sq0f = g_sq[h * S_LEN + q0w + r]     * (1.f / 254.f);
    const float sq1f = g_sq[h * S_LEN + q0w + r + 8] * (1.f / 254.f);

    auto issue_kv = [&](int kt, int buf) {
        const int k0 = kt * 128;
        const uint32_t sb = sbase + buf * ABUF_B;
        #pragma unroll
        for (int d = 0; d < 2; ++d) {
            const int8_t* src = (d ? g_k2 : g_k1) + (size_t)k0 * DMODEL + hoff;
            #pragma unroll
            for (int j = 0; j < 2; ++j) {
                const int slot = tid + j * 256;
                const int row = slot >> 2, col = slot & 3;
                cp16(sb + d * AK_B + row * AK_ROWB + col * 16,
                     src + (size_t)row * DMODEL + col * 16);
            }
        }
        {
            const __half* src = g_v16 + (size_t)k0 * DMODEL + hoff;
            #pragma unroll
            for (int j = 0; j < 4; ++j) {
                const int slot = tid + j * 256;
                const int row = slot >> 3, col = slot & 7;
                cp16(sb + 2 * AK_B + row * AV_ROWB + col * 16,
                     src + (size_t)row * DMODEL + col * 8);
            }
        }
        if (tid < 32)
            cp16(sb + ASK_OFF + tid * 16, g_sk + h * S_LEN + k0 + tid * 4);
    };

    float m_[2] = { -1e30f, -1e30f }, l_[2] = { 0.f, 0.f };
    float oacc[8][4];
    #pragma unroll
    for (int i = 0; i < 8; i++)
        #pragma unroll
        for (int j = 0; j < 4; j++) oacc[i][j] = 0.f;

    issue_kv(0, 0);
    cp_commit();

    const uint32_t b_off  = (uint32_t)(((lane >> 4) << 3) + (lane & 7));
    const uint32_t kb_off = ((lane >> 3) & 1) * 16;
    const uint32_t vrow   = lane & 15;
    const uint32_t vcol   = (lane >> 4) * 8;

    for (int kt = 0; kt <= qt; ++kt) {
        const int buf = kt & 1;
        const bool hasNext = kt < qt;
        if (hasNext) { issue_kv(kt + 1, buf ^ 1); cp_commit(); }
        if (hasNext) cp_wait1(); else cp_wait0();
        __syncthreads();

        const uint32_t k1b = sbase + buf * ABUF_B;
        const uint32_t k2b = k1b + AK_B;
        const uint32_t v_b = k1b + 2 * AK_B;
        const float* sks = (const float*)(sm + buf * ABUF_B + ASK_OFF);

        #pragma unroll
        for (int half = 0; half < 2; ++half) {
            // diagonal tile, upper half: warps whose rows are all < 64 are fully masked
            if (kt == qt && half == 1 && (w * 16 + 15) < 64) break;

            const int kbase = half * 64;

            // ---- S = Q @ K^T over 64 keys (dual-digit int8) ----
            float s[8][4];
            #pragma unroll
            for (int nt2 = 0; nt2 < 4; ++nt2) {
                int a1[2][4] = { {0,0,0,0}, {0,0,0,0} };
                int a2[2][4] = { {0,0,0,0}, {0,0,0,0} };
                #pragma unroll
                for (int g = 0; g < 2; ++g) {
                    const uint32_t addr = (uint32_t)(kbase + nt2 * 16 + b_off) * AK_ROWB + g * 32 + kb_off;
                    uint32_t fb1[4], fb2[4];
                    ldsm_x4(fb1, k1b + addr);
                    ldsm_x4(fb2, k2b + addr);
                    #pragma unroll
                    for (int hf = 0; hf < 2; ++hf) {
                        mma_s8(a1[hf], q1f[g], fb1 + hf * 2);
                        mma_s8(a2[hf], q1f[g], fb2 + hf * 2);
                        mma_s8(a2[hf], q2f[g], fb1 + hf * 2);
                    }
                }
                #pragma unroll
                for (int hf = 0; hf < 2; ++hf) {
                    const float2 sk2 = *(const float2*)(sks + (kbase + (nt2 * 2 + hf) * 8) + kc);
                    s[nt2 * 2 + hf][0] = (float)(a1[hf][0] * 254 + a2[hf][0]) * (sq0f * sk2.x);
                    s[nt2 * 2 + hf][1] = (float)(a1[hf][1] * 254 + a2[hf][1]) * (sq0f * sk2.y);
                    s[nt2 * 2 + hf][2] = (float)(a1[hf][2] * 254 + a2[hf][2]) * (sq1f * sk2.x);
                    s[nt2 * 2 + hf][3] = (float)(a1[hf][3] * 254 + a2[hf][3]) * (sq1f * sk2.y);
                }
            }

            // causal mask on diagonal tile
            if (kt == qt) {
                #pragma unroll
                for (int nt = 0; nt < 8; ++nt) {
                    #pragma unroll
                    for (int c = 0; c < 4; ++c) {
                        const int key = kbase + nt * 8 + kc + (c & 1);
                        const int qq  = w * 16 + r + (c >> 1) * 8;
                        if (key > qq) s[nt][c] = -1e30f;
                    }
                }
            }

            // ---- online softmax (base-2) over 64 keys ----
            float mx0 = -1e30f, mx1 = -1e30f;
            #pragma unroll
            for (int nt = 0; nt < 8; ++nt) {
                mx0 = fmaxf(mx0, fmaxf(s[nt][0], s[nt][1]));
                mx1 = fmaxf(mx1, fmaxf(s[nt][2], s[nt][3]));
            }
            mx0 = fmaxf(mx0, __shfl_xor_sync(0xffffffffu, mx0, 1));
            mx0 = fmaxf(mx0, __shfl_xor_sync(0xffffffffu, mx0, 2));
            mx1 = fmaxf(mx1, __shfl_xor_sync(0xffffffffu, mx1, 1));
            mx1 = fmaxf(mx1, __shfl_xor_sync(0xffffffffu, mx1, 2));

            const float nm0 = fmaxf(m_[0], mx0), nm1 = fmaxf(m_[1], mx1);
            const float al0 = ex2f(m_[0] - nm0), al1 = ex2f(m_[1] - nm1);
            float rs0 = 0.f, rs1 = 0.f;
            #pragma unroll
            for (int nt = 0; nt < 8; ++nt) {
                s[nt][0] = ex2f(s[nt][0] - nm0);
                s[nt][1] = ex2f(s[nt][1] - nm0);
                s[nt][2] = ex2f(s[nt][2] - nm1);
                s[nt][3] = ex2f(s[nt][3] - nm1);
                rs0 += s[nt][0] + s[nt][1];
                rs1 += s[nt][2] + s[nt][3];
            }
            rs0 += __shfl_xor_sync(0xffffffffu, rs0, 1);
            rs0 += __shfl_xor_sync(0xffffffffu, rs0, 2);
            rs1 += __shfl_xor_sync(0xffffffffu, rs1, 1);
            rs1 += __shfl_xor_sync(0xffffffffu, rs1, 2);

            l_[0] = l_[0] * al0 + rs0;  m_[0] = nm0;
            l_[1] = l_[1] * al1 + rs1;  m_[1] = nm1;
            #pragma unroll
            for (int dt = 0; dt < 8; ++dt) {
                oacc[dt][0] *= al0; oacc[dt][1] *= al0;
                oacc[dt][2] *= al1; oacc[dt][3] *= al1;
            }

            // ---- O += P @ V over 64 keys (P fp16 in regs; V via trans-ldmatrix) ----
            #pragma unroll
            for (int j = 0; j < 4; ++j) {
                uint32_t pa[4];
                pa[0] = h2u(s[2*j][0],   s[2*j][1]);
                pa[1] = h2u(s[2*j][2],   s[2*j][3]);
                pa[2] = h2u(s[2*j+1][0], s[2*j+1][1]);
                pa[3] = h2u(s[2*j+1][2], s[2*j+1][3]);

                const uint32_t abase = (kbase + j * 16 + vrow) * AV_ROWB + vcol * 2;
                #pragma unroll
                for (int dg = 0; dg < 4; ++dg) {
                    uint32_t bv[4];
                    ldsm_x4_t(bv, v_b + abase + dg * 32);
                    mma_f16(oacc[dg * 2 + 0], pa, bv + 0);
                    mma_f16(oacc[dg * 2 + 1], pa, bv + 2);
                }
            }
        }
        __syncthreads();
    }

    // epilogue: normalize, write fp32 ctx
    const float inv0 = 1.f / l_[0], inv1 = 1.f / l_[1];
    #pragma unroll
    for (int dt = 0; dt < 8; ++dt) {
        const size_t d = (size_t)hoff + dt * 8 + kc;
        const size_t rowA = (size_t)(q0w + r) * DMODEL + d;
        const size_t rowB = (size_t)(q0w + r + 8) * DMODEL + d;
        float2 a0 = { oacc[dt][0] * inv0, oacc[dt][1] * inv0 };
        float2 a1 = { oacc[dt][2] * inv1, oacc[dt][3] * inv1 };
        *(float2*)(g_ctx + rowA) = a0;
        *(float2*)(g_ctx + rowB) = a1;
    }
}

// ======================= host launcher =======================
extern "C" void kernel_launch(void* const* d_in, const int* in_sizes, int n_in,
                              void* d_out, int out_size)
{
    (void)in_sizes; (void)n_in; (void)out_size;
    const float* x  = (const float*)d_in[0];
    const float* Wq = (const float*)d_in[2];
    const float* bq = (const float*)d_in[3];
    const float* Wk = (const float*)d_in[4];
    const float* bk = (const float*)d_in[5];
    const float* Wv = (const float*)d_in[6];
    const float* bv = (const float*)d_in[7];
    const float* Wo = (const float*)d_in[8];
    const float* bo = (const float*)d_in[9];
    float* out = (float*)d_out;

    int8_t *x1, *x2, *c1, *c2;
    float *sx, *sc, *ctx;
    cudaGetSymbolAddress((void**)&x1, g_x1);
    cudaGetSymbolAddress((void**)&x2, g_x2);
    cudaGetSymbolAddress((void**)&sx, g_sx);
    cudaGetSymbolAddress((void**)&c1, g_c1);
    cudaGetSymbolAddress((void**)&c2, g_c2);
    cudaGetSymbolAddress((void**)&sc, g_sc);
    cudaGetSymbolAddress((void**)&ctx, g_ctx);

    cudaFuncSetAttribute(gemm_qkv_kernel,
                         cudaFuncAttributeMaxDynamicSharedMemorySize, QGEMM_SMEM);
    cudaFuncSetAttribute(gemm_o_kernel,
                         cudaFuncAttributeMaxDynamicSharedMemorySize, QGEMM_SMEM);
    cudaFuncSetAttribute(attn_kernel,
                         cudaFuncAttributeMaxDynamicSharedMemorySize, ATT_SMEM);

    // 1: fused weight colmax + transpose-quant
    wprep_kernel<<<dim3(8, 4), 256>>>(Wq, Wk, Wv, Wo);
    // 2: input row-quant
    rowquant_kernel<<<S_LEN, 256>>>(x, x1, x2, sx);
    // 3: fused Q/K/V projections
    gemm_qkv_kernel<<<dim3(8, 32, 3), 256, QGEMM_SMEM>>>(bq, bk, bv);
    // 4: attention  (profiled slot)
    attn_kernel<<<dim3(S_LEN / 128, NHEADS), 256, ATT_SMEM>>>();
    // 5: ctx row-quant
    rowquant_kernel<<<S_LEN, 256>>>(ctx, c1, c2, sc);
    // 6: O projection
    gemm_o_kernel<<<dim3(8, 32), 256, QGEMM_SMEM>>>(bo, out);
}

// round 11
// speedup vs baseline: 4.3631x; 1.0674x over previous
#include <cuda_runtime.h>
#include <cuda_bf16.h>
#include <cuda_fp16.h>
#include <cstdint>
#include <math.h>

#define S_LEN  4096
#define DMODEL 1024
#define NHEADS 16
#define DK     64

// ======================= scratch (device globals) =======================
__device__ int8_t g_x1[(size_t)S_LEN * DMODEL];
__device__ int8_t g_x2[(size_t)S_LEN * DMODEL];
__device__ float  g_sx[S_LEN];

__device__ int8_t g_wq1[(size_t)DMODEL * DMODEL];
__device__ int8_t g_wq2[(size_t)DMODEL * DMODEL];
__device__ int8_t g_wk1[(size_t)DMODEL * DMODEL];
__device__ int8_t g_wk2[(size_t)DMODEL * DMODEL];
__device__ int8_t g_wv1[(size_t)DMODEL * DMODEL];
__device__ int8_t g_wv2[(size_t)DMODEL * DMODEL];
__device__ int8_t g_wo1[(size_t)DMODEL * DMODEL];
__device__ int8_t g_wo2[(size_t)DMODEL * DMODEL];
__device__ unsigned g_wbits[4 * DMODEL];

// attention operands
__device__ int8_t g_q1[(size_t)S_LEN * DMODEL];
__device__ int8_t g_q2[(size_t)S_LEN * DMODEL];
__device__ int8_t g_k1[(size_t)S_LEN * DMODEL];
__device__ int8_t g_k2[(size_t)S_LEN * DMODEL];
__device__ float  g_sq[NHEADS * S_LEN];
__device__ float  g_sk[NHEADS * S_LEN];
__device__ __half g_v16[(size_t)S_LEN * DMODEL];

__device__ float  g_ctx[(size_t)S_LEN * DMODEL];
__device__ int8_t g_c1[(size_t)S_LEN * DMODEL];
__device__ int8_t g_c2[(size_t)S_LEN * DMODEL];
__device__ float  g_sc[S_LEN];

// ======================= helpers =======================
__device__ __forceinline__ uint32_t smem_u32(const void* p) {
    uint32_t a;
    asm("{ .reg .u64 t; cvta.to.shared.u64 t, %1; cvt.u32.u64 %0, t; }" : "=r"(a) : "l"(p));
    return a;
}
__device__ __forceinline__ void cp16(uint32_t saddr, const void* g) {
    asm volatile("cp.async.ca.shared.global [%0], [%1], 16;" :: "r"(saddr), "l"(g));
}
__device__ __forceinline__ void cp_commit() { asm volatile("cp.async.commit_group;"); }
__device__ __forceinline__ void cp_wait1()  { asm volatile("cp.async.wait_group 1;"); }
__device__ __forceinline__ void cp_wait0()  { asm volatile("cp.async.wait_group 0;"); }

__device__ __forceinline__ void ldsm_x4(uint32_t* r, uint32_t addr) {
    asm volatile("ldmatrix.sync.aligned.m8n8.x4.shared.b16 {%0,%1,%2,%3}, [%4];"
                 : "=r"(r[0]), "=r"(r[1]), "=r"(r[2]), "=r"(r[3]) : "r"(addr));
}
__device__ __forceinline__ void ldsm_x4_t(uint32_t* r, uint32_t addr) {
    asm volatile("ldmatrix.sync.aligned.m8n8.x4.trans.shared.b16 {%0,%1,%2,%3}, [%4];"
                 : "=r"(r[0]), "=r"(r[1]), "=r"(r[2]), "=r"(r[3]) : "r"(addr));
}
__device__ __forceinline__ void mma_s8(int* c, const uint32_t* a, const uint32_t* b) {
    asm volatile(
        "mma.sync.aligned.m16n8k32.row.col.s32.s8.s8.s32 "
        "{%0,%1,%2,%3}, {%4,%5,%6,%7}, {%8,%9}, {%0,%1,%2,%3};"
        : "+r"(c[0]), "+r"(c[1]), "+r"(c[2]), "+r"(c[3])
        : "r"(a[0]), "r"(a[1]), "r"(a[2]), "r"(a[3]), "r"(b[0]), "r"(b[1]));
}
__device__ __forceinline__ void mma_f16(float* c, const uint32_t* a, const uint32_t* b) {
    asm volatile(
        "mma.sync.aligned.m16n8k16.row.col.f32.f16.f16.f32 "
        "{%0,%1,%2,%3}, {%4,%5,%6,%7}, {%8,%9}, {%0,%1,%2,%3};"
        : "+f"(c[0]), "+f"(c[1]), "+f"(c[2]), "+f"(c[3])
        : "r"(a[0]), "r"(a[1]), "r"(a[2]), "r"(a[3]), "r"(b[0]), "r"(b[1]));
}
__device__ __forceinline__ float ex2f(float x) {
    float y;
    asm("ex2.approx.f32 %0, %1;" : "=f"(y) : "f"(x));
    return y;
}
__device__ __forceinline__ uint32_t h2u(float x, float y) {
    __half2 h = __floats2half2_rn(x, y);
    return *(uint32_t*)&h;
}
__device__ __forceinline__ void digits2(float alpha, int& d1, int& d2) {
    d1 = __float2int_rn(alpha);
    d2 = __float2int_rn((alpha - (float)d1) * 254.f);
}
__device__ __forceinline__ uint32_t pack_dig(float a, float b, uint32_t& w2) {
    int a1, a2, b1, b2;
    digits2(a, a1, a2);
    digits2(b, b1, b2);
    w2 = (uint32_t)(a2 & 0xff) | (((uint32_t)(b2 & 0xff)) << 8);
    return (uint32_t)(a1 & 0xff) | (((uint32_t)(b1 & 0xff)) << 8);
}
__device__ __forceinline__ uint32_t pack4b(int a, int b, int c, int d) {
    return (uint32_t)(a & 0xff) | (((uint32_t)(b & 0xff)) << 8) |
           (((uint32_t)(c & 0xff)) << 16) | (((uint32_t)(d & 0xff)) << 24);
}

// ======================= weight prep (parallelized) =======================
// column max for all 4 weights: grid (8, 4), 1024 threads, 8-way row split.
__global__ __launch_bounds__(1024)
void colmax4_kernel(const float* __restrict__ Wq, const float* __restrict__ Wk,
                    const float* __restrict__ Wv, const float* __restrict__ Wo)
{
    const int z = blockIdx.y;
    const float* W = (z == 0) ? Wq : (z == 1) ? Wk : (z == 2) ? Wv : Wo;
    unsigned* bits = g_wbits + z * DMODEL;

    const int tid  = threadIdx.x;
    const int col  = blockIdx.x * 128 + (tid & 127);
    const int part = tid >> 7;                 // 0..7

    float m = 0.f;
    #pragma unroll 8
    for (int r = part; r < DMODEL; r += 8)
        m = fmaxf(m, fabsf(W[(size_t)r * DMODEL + col]));

    __shared__ float red[8][128];
    red[part][tid & 127] = m;
    __syncthreads();
    if (tid < 128) {
        float mm = red[0][tid];
        #pragma unroll
        for (int i = 1; i < 8; ++i) mm = fmaxf(mm, red[i][tid]);
        bits[blockIdx.x * 128 + tid] = __float_as_uint(fmaxf(mm, 1e-30f));
    }
}

// batched transpose+quant: W [K,N] -> [N,K] digits. grid (32,32,4)
__global__ __launch_bounds__(256)
void transpose_quant4_kernel(const float* __restrict__ W0, const float* __restrict__ W1,
                             const float* __restrict__ W2, const float* __restrict__ W3)
{
    const int z = blockIdx.z;
    const float* W = (z == 0) ? W0 : (z == 1) ? W1 : (z == 2) ? W2 : W3;
    int8_t* B1 = (z == 0) ? g_wq1 : (z == 1) ? g_wk1 : (z == 2) ? g_wv1 : g_wo1;
    int8_t* B2 = (z == 0) ? g_wq2 : (z == 1) ? g_wk2 : (z == 2) ? g_wv2 : g_wo2;
    const unsigned* b = g_wbits + z * DMODEL;

    __shared__ float t[32][33];
    const int n0 = blockIdx.x * 32, k0 = blockIdx.y * 32;
    const int lx = threadIdx.x & 31, ly = threadIdx.x >> 5;
    #pragma unroll
    for (int i = 0; i < 32; i += 8)
        t[ly + i][lx] = W[(size_t)(k0 + ly + i) * DMODEL + n0 + lx];
    __syncthreads();
    #pragma unroll
    for (int i = 0; i < 32; i += 8) {
        const int n = n0 + ly + i;
        const float inv = 127.f / __uint_as_float(b[n]);
        int d1, d2;
        digits2(t[lx][ly + i] * inv, d1, d2);
        const size_t o = (size_t)n * DMODEL + k0 + lx;
        B1[o] = (int8_t)d1;
        B2[o] = (int8_t)d2;
    }
}

// per-row quant of a [rows,1024] fp32 matrix -> digits + scale
__global__ __launch_bounds__(256)
void rowquant_kernel(const float* __restrict__ src,
                     int8_t* __restrict__ D1, int8_t* __restrict__ D2,
                     float* __restrict__ s)
{
    const int row = blockIdx.x;
    const int tid = threadIdx.x;
    const float4 v = ((const float4*)(src + (size_t)row * DMODEL))[tid];
    float m = fmaxf(fmaxf(fabsf(v.x), fabsf(v.y)), fmaxf(fabsf(v.z), fabsf(v.w)));
    #pragma unroll
    for (int o = 16; o >= 1; o >>= 1)
        m = fmaxf(m, __shfl_xor_sync(0xffffffffu, m, o));
    __shared__ float red[8];
    if ((tid & 31) == 0) red[tid >> 5] = m;
    __syncthreads();
    float mm = red[0];
    #pragma unroll
    for (int i = 1; i < 8; i++) mm = fmaxf(mm, red[i]);
    mm = fmaxf(mm, 1e-30f);
    if (tid == 0) s[row] = mm * (1.f / 127.f);
    const float inv = 127.f / mm;
    int d1, d2;
    char4 c1, c2;
    digits2(v.x * inv, d1, d2); c1.x = (char)d1; c2.x = (char)d2;
    digits2(v.y * inv, d1, d2); c1.y = (char)d1; c2.y = (char)d2;
    digits2(v.z * inv, d1, d2); c1.z = (char)d1; c2.z = (char)d2;
    digits2(v.w * inv, d1, d2); c1.w = (char)d1; c2.w = (char)d2;
    ((char4*)(D1 + (size_t)row * DMODEL))[tid] = c1;
    ((char4*)(D2 + (size_t)row * DMODEL))[tid] = c2;
}

// ======================= int8 dual-digit GEMM cores =======================
#define QBK 64
#define QNCH (DMODEL / QBK)
#define QROWB 80
#define QARR_B (128 * QROWB)
#define QSTAGE_B (4 * QARR_B)
#define QGEMM_SMEM (2 * QSTAGE_B)

struct GemmAcc { int a1[2][8][4]; int a2[2][8][4]; };

__device__ __forceinline__ void gemm_mainloop(
    const int8_t* A1p, const int8_t* A2p, const int8_t* B1p, const int8_t* B2p,
    char* sm, uint32_t sbase, int tid, int lane, int mw0, int nw0, GemmAcc& acc)
{
    #pragma unroll
    for (int i = 0; i < 2; i++)
        #pragma unroll
        for (int j = 0; j < 8; j++)
            #pragma unroll
            for (int q = 0; q < 4; q++) { acc.a1[i][j][q] = 0; acc.a2[i][j][q] = 0; }

    const int8_t* srcs[4] = { A1p, A2p, B1p, B2p };
    const int a_row = lane & 15;
    const int a_kb  = (lane >> 4) * 16;
    const int b_row = ((lane >> 4) << 3) + (lane & 7);
    const int b_kb  = ((lane >> 3) & 1) * 16;

    auto issue_loads = [&](int c, int stage) {
        const int k0 = c * QBK;
        const uint32_t sb = sbase + stage * QSTAGE_B;
        #pragma unroll
        for (int t = 0; t < 4; t++) {
            #pragma unroll
            for (int jj = 0; jj < 2; jj++) {
                const int slot = tid + jj * 256;
                const int row = slot >> 2, col = slot & 3;
                cp16(sb + t * QARR_B + row * QROWB + col * 16,
                     srcs[t] + (size_t)row * DMODEL + k0 + col * 16);
            }
        }
    };

    issue_loads(0, 0);
    cp_commit();

    for (int c = 0; c < QNCH; ++c) {
        const int stage = c & 1;
        const bool hasNext = (c + 1 < QNCH);
        if (hasNext) { issue_loads(c + 1, stage ^ 1); cp_commit(); }
        if (hasNext) cp_wait1(); else cp_wait0();
        __syncthreads();

        const uint32_t sb = sbase + stage * QSTAGE_B;
        #pragma unroll
        for (int ks = 0; ks < 2; ++ks) {
            const int kb = ks * 32;
            uint32_t fa1[2][4], fa2[2][4];
            #pragma unroll
            for (int mi = 0; mi < 2; ++mi) {
                const uint32_t aoff = (uint32_t)(mw0 + mi * 16 + a_row) * QROWB + kb + a_kb;
                ldsm_x4(fa1[mi], sb + 0 * QARR_B + aoff);
                ldsm_x4(fa2[mi], sb + 1 * QARR_B + aoff);
            }
            #pragma unroll
            for (int nt2 = 0; nt2 < 4; ++nt2) {
                const uint32_t boff = (uint32_t)(nw0 + nt2 * 16 + b_row) * QROWB + kb + b_kb;
                uint32_t fb1[4], fb2[4];
                ldsm_x4(fb1, sb + 2 * QARR_B + boff);
                ldsm_x4(fb2, sb + 3 * QARR_B + boff);
                #pragma unroll
                for (int mi = 0; mi < 2; ++mi) {
                    #pragma unroll
                    for (int half = 0; half < 2; ++half) {
                        mma_s8(acc.a1[mi][nt2 * 2 + half], fa1[mi], fb1 + half * 2);
                        mma_s8(acc.a2[mi][nt2 * 2 + half], fa1[mi], fb2 + half * 2);
                        mma_s8(acc.a2[mi][nt2 * 2 + half], fa2[mi], fb1 + half * 2);
                    }
                }
            }
        }
        __syncthreads();
    }
}

// fused Q/K/V projection: grid (8, 32, 3)
__global__ __launch_bounds__(256, 1)
void gemm_qkv_kernel(const float* __restrict__ bq,
                     const float* __restrict__ bk,
                     const float* __restrict__ bv)
{
    extern __shared__ char sm[];
    const uint32_t sbase = smem_u32(sm);
    const int tid  = threadIdx.x;
    const int lane = tid & 31;
    const int wid  = tid >> 5;
    const int mw0  = (wid & 3) * 32;
    const int nw0  = (wid >> 2) * 64;
    const int bm   = blockIdx.y * 128;
    const int bn   = blockIdx.x * 128;
    const int z    = blockIdx.z;

    const int8_t* B1 = (z == 0) ? g_wq1 : (z == 1) ? g_wk1 : g_wv1;
    const int8_t* B2 = (z == 0) ? g_wq2 : (z == 1) ? g_wk2 : g_wv2;
    const float* bias = (z == 0) ? bq : (z == 1) ? bk : bv;
    const unsigned* sBbits = g_wbits + z * DMODEL;

    GemmAcc acc;
    gemm_mainloop(g_x1 + (size_t)bm * DMODEL, g_x2 + (size_t)bm * DMODEL,
                  B1 + (size_t)bn * DMODEL, B2 + (size_t)bn * DMODEL,
                  sm, sbase, tid, lane, mw0, nw0, acc);

    const int erow = lane >> 2;
    const int ecol = (lane & 3) * 2;
    const float* sA = g_sx;

    if (z == 2) {
        #pragma unroll
        for (int mi = 0; mi < 2; ++mi) {
            const int m0 = bm + mw0 + mi * 16 + erow;
            const float sa0 = sA[m0], sa8 = sA[m0 + 8];
            #pragma unroll
            for (int ni = 0; ni < 8; ++ni) {
                const int n = bn + nw0 + ni * 8 + ecol;
                const float sb0 = __uint_as_float(sBbits[n])     * (1.f / 127.f);
                const float sb1 = __uint_as_float(sBbits[n + 1]) * (1.f / 127.f);
                const float b0 = bias[n], b1 = bias[n + 1];
                const float c00 = ((float)acc.a1[mi][ni][0] + (float)acc.a2[mi][ni][0] * (1.f / 254.f)) * (sa0 * sb0) + b0;
                const float c01 = ((float)acc.a1[mi][ni][1] + (float)acc.a2[mi][ni][1] * (1.f / 254.f)) * (sa0 * sb1) + b1;
                const float c10 = ((float)acc.a1[mi][ni][2] + (float)acc.a2[mi][ni][2] * (1.f / 254.f)) * (sa8 * sb0) + b0;
                const float c11 = ((float)acc.a1[mi][ni][3] + (float)acc.a2[mi][ni][3] * (1.f / 254.f)) * (sa8 * sb1) + b1;
                *(uint32_t*)(g_v16 + (size_t)m0 * DMODEL + n)       = h2u(c00, c01);
                *(uint32_t*)(g_v16 + (size_t)(m0 + 8) * DMODEL + n) = h2u(c10, c11);
            }
        }
    } else {
        int8_t* D1 = z ? g_k1 : g_q1;
        int8_t* D2 = z ? g_k2 : g_q2;
        float* sOut = z ? g_sk : g_sq;
        const float smul = z ? 1.0f : 0.125f * 1.44269504f;
        const int head = (bn + nw0) >> 6;
        #pragma unroll
        for (int mi = 0; mi < 2; ++mi) {
            const int m0 = bm + mw0 + mi * 16 + erow;
            const float sa0 = sA[m0], sa8 = sA[m0 + 8];
            float v0[16], v1[16];
            #pragma unroll
            for (int ni = 0; ni < 8; ++ni) {
                const int n = bn + nw0 + ni * 8 + ecol;
                const float sb0 = __uint_as_float(sBbits[n])     * (1.f / 127.f);
                const float sb1 = __uint_as_float(sBbits[n + 1]) * (1.f / 127.f);
                const float b0 = bias[n], b1 = bias[n + 1];
                v0[ni * 2 + 0] = ((float)acc.a1[mi][ni][0] + (float)acc.a2[mi][ni][0] * (1.f / 254.f)) * (sa0 * sb0) + b0;
                v0[ni * 2 + 1] = ((float)acc.a1[mi][ni][1] + (float)acc.a2[mi][ni][1] * (1.f / 254.f)) * (sa0 * sb1) + b1;
                v1[ni * 2 + 0] = ((float)acc.a1[mi][ni][2] + (float)acc.a2[mi][ni][2] * (1.f / 254.f)) * (sa8 * sb0) + b0;
                v1[ni * 2 + 1] = ((float)acc.a1[mi][ni][3] + (float)acc.a2[mi][ni][3] * (1.f / 254.f)) * (sa8 * sb1) + b1;
            }
            float mx0 = 0.f, mx1 = 0.f;
            #pragma unroll
            for (int i = 0; i < 16; i++) {
                mx0 = fmaxf(mx0, fabsf(v0[i]));
                mx1 = fmaxf(mx1, fabsf(v1[i]));
            }
            mx0 = fmaxf(mx0, __shfl_xor_sync(0xffffffffu, mx0, 1));
            mx0 = fmaxf(mx0, __shfl_xor_sync(0xffffffffu, mx0, 2));
            mx1 = fmaxf(mx1, __shfl_xor_sync(0xffffffffu, mx1, 1));
            mx1 = fmaxf(mx1, __shfl_xor_sync(0xffffffffu, mx1, 2));
            mx0 = fmaxf(mx0, 1e-20f);
            mx1 = fmaxf(mx1, 1e-20f);
            if ((lane & 3) == 0) {
                sOut[head * S_LEN + m0]     = mx0 * (smul / 127.f);
                sOut[head * S_LEN + m0 + 8] = mx1 * (smul / 127.f);
            }
            const float i0 = 127.f / mx0, i1 = 127.f / mx1;
            #pragma unroll
            for (int ni = 0; ni < 8; ++ni) {
                const int n = bn + nw0 + ni * 8 + ecol;
                uint32_t w2;
                uint32_t w1 = pack_dig(v0[ni * 2] * i0, v0[ni * 2 + 1] * i0, w2);
                *(uint16_t*)(D1 + (size_t)m0 * DMODEL + n) = (uint16_t)w1;
                *(uint16_t*)(D2 + (size_t)m0 * DMODEL + n) = (uint16_t)w2;
                w1 = pack_dig(v1[ni * 2] * i1, v1[ni * 2 + 1] * i1, w2);
                *(uint16_t*)(D1 + (size_t)(m0 + 8) * DMODEL + n) = (uint16_t)w1;
                *(uint16_t*)(D2 + (size_t)(m0 + 8) * DMODEL + n) = (uint16_t)w2;
            }
        }
    }
}

// O projection: fp32 out + bias
__global__ __launch_bounds__(256, 1)
void gemm_o_kernel(const float* __restrict__ bias, float* __restrict__ C)
{
    extern __shared__ char sm[];
    const uint32_t sbase = smem_u32(sm);
    const int tid  = threadIdx.x;
    const int lane = tid & 31;
    const int wid  = tid >> 5;
    const int mw0  = (wid & 3) * 32;
    const int nw0  = (wid >> 2) * 64;
    const int bm   = blockIdx.y * 128;
    const int bn   = blockIdx.x * 128;

    GemmAcc acc;
    gemm_mainloop(g_c1 + (size_t)bm * DMODEL, g_c2 + (size_t)bm * DMODEL,
                  g_wo1 + (size_t)bn * DMODEL, g_wo2 + (size_t)bn * DMODEL,
                  sm, sbase, tid, lane, mw0, nw0, acc);

    const unsigned* sBbits = g_wbits + 3 * DMODEL;
    const int erow = lane >> 2;
    const int ecol = (lane & 3) * 2;
    #pragma unroll
    for (int mi = 0; mi < 2; ++mi) {
        const int m0 = bm + mw0 + mi * 16 + erow;
        const float sa0 = g_sc[m0], sa8 = g_sc[m0 + 8];
        #pragma unroll
        for (int ni = 0; ni < 8; ++ni) {
            const int n = bn + nw0 + ni * 8 + ecol;
            const float sb0 = __uint_as_float(sBbits[n])     * (1.f / 127.f);
            const float sb1 = __uint_as_float(sBbits[n + 1]) * (1.f / 127.f);
            const float b0 = bias[n], b1 = bias[n + 1];
            float2 v0, v1;
            v0.x = ((float)acc.a1[mi][ni][0] + (float)acc.a2[mi][ni][0] * (1.f / 254.f)) * (sa0 * sb0) + b0;
            v0.y = ((float)acc.a1[mi][ni][1] + (float)acc.a2[mi][ni][1] * (1.f / 254.f)) * (sa0 * sb1) + b1;
            v1.x = ((float)acc.a1[mi][ni][2] + (float)acc.a2[mi][ni][2] * (1.f / 254.f)) * (sa8 * sb0) + b0;
            v1.y = ((float)acc.a1[mi][ni][3] + (float)acc.a2[mi][ni][3] * (1.f / 254.f)) * (sa8 * sb1) + b1;
            *(float2*)(C + (size_t)m0 * DMODEL + n)       = v0;
            *(float2*)(C + (size_t)(m0 + 8) * DMODEL + n) = v1;
        }
    }
}

// ======================= hybrid flash attention =======================
#define AK_ROWB 80
#define AK_B (128 * AK_ROWB)
#define AV_ROWB 144
#define AV_B (128 * AV_ROWB)
#define ASK_OFF (2 * AK_B + AV_B)
#define ABUF_B (ASK_OFF + 512)
#define ATT_SMEM (2 * ABUF_B)

__global__ __launch_bounds__(256, 2)
void attn_kernel()
{
    extern __shared__ char sm[];
    const uint32_t sbase = smem_u32(sm);

    const int tid  = threadIdx.x;
    const int lane = tid & 31;
    const int w    = tid >> 5;
    const int h    = blockIdx.y;
    const int qt   = (int)gridDim.x - 1 - (int)blockIdx.x;
    const int q0   = qt * 128;
    const int hoff = h * DK;
    const int q0w  = q0 + w * 16;

    const int r  = lane >> 2;
    const int kc = (lane & 3) * 2;

    // Q A-fragments (int8 digits)
    uint32_t q1f[2][4], q2f[2][4];
    {
        const int qb = (lane & 3) * 4;
        #pragma unroll
        for (int g = 0; g < 2; ++g) {
            const size_t bA = (size_t)(q0w + r) * DMODEL + hoff + g * 32 + qb;
            const size_t bB = (size_t)(q0w + r + 8) * DMODEL + hoff + g * 32 + qb;
            q1f[g][0] = *(const uint32_t*)(g_q1 + bA);
            q1f[g][1] = *(const uint32_t*)(g_q1 + bB);
            q1f[g][2] = *(const uint32_t*)(g_q1 + bA + 16);
            q1f[g][3] = *(const uint32_t*)(g_q1 + bB + 16);
            q2f[g][0] = *(const uint32_t*)(g_q2 + bA);
            q2f[g][1] = *(const uint32_t*)(g_q2 + bB);
            q2f[g][2] = *(const uint32_t*)(g_q2 + bA + 16);
            q2f[g][3] = *(const uint32_t*)(g_q2 + bB + 16);
        }
    }
    const float sq0f = g_sq[h * S_LEN + q0w + r]     * (1.f / 254.f);
    const float sq1f = g_sq[h * S_LEN + q0w + r + 8] * (1.f / 254.f);

    auto issue_kv = [&](int kt, int buf) {
        const int k0 = kt * 128;
        const uint32_t sb = sbase + buf * ABUF_B;
        #pragma unroll
        for (int d = 0; d < 2; ++d) {
            const int8_t* src = (d ? g_k2 : g_k1) + (size_t)k0 * DMODEL + hoff;
            #pragma unroll
            for (int j = 0; j < 2; ++j) {
                const int slot = tid + j * 256;
                const int row = slot >> 2, col = slot & 3;
                cp16(sb + d * AK_B + row * AK_ROWB + col * 16,
                     src + (size_t)row * DMODEL + col * 16);
            }
        }
        {
            const __half* src = g_v16 + (size_t)k0 * DMODEL + hoff;
            #pragma unroll
            for (int j = 0; j < 4; ++j) {
                const int slot = tid + j * 256;
                const int row = slot >> 3, col = slot & 7;
                cp16(sb + 2 * AK_B + row * AV_ROWB + col * 16,
                     src + (size_t)row * DMODEL + col * 8);
            }
        }
        if (tid < 32)
            cp16(sb + ASK_OFF + tid * 16, g_sk + h * S_LEN + k0 + tid * 4);
    };

    float m_[2] = { -1e30f, -1e30f }, l_[2] = { 0.f, 0.f };
    float oacc[8][4];
    #pragma unroll
    for (int i = 0; i < 8; i++)
        #pragma unroll
        for (int j = 0; j < 4; j++) oacc[i][j] = 0.f;

    issue_kv(0, 0);
    cp_commit();

    const uint32_t b_off  = (uint32_t)(((lane >> 4) << 3) + (lane & 7));
    const uint32_t kb_off = ((lane >> 3) & 1) * 16;
    const uint32_t vrow   = lane & 15;
    const uint32_t vcol   = (lane >> 4) * 8;

    for (int kt = 0; kt <= qt; ++kt) {
        const int buf = kt & 1;
        const bool hasNext = kt < qt;
        if (hasNext) { issue_kv(kt + 1, buf ^ 1); cp_commit(); }
        if (hasNext) cp_wait1(); else cp_wait0();
        __syncthreads();

        const uint32_t k1b = sbase + buf * ABUF_B;
        const uint32_t k2b = k1b + AK_B;
        const uint32_t v_b = k1b + 2 * AK_B;
        const float* sks = (const float*)(sm + buf * ABUF_B + ASK_OFF);

        #pragma unroll
        for (int half = 0; half < 2; ++half) {
            if (kt == qt && half == 1 && (w * 16 + 15) < 64) break;

            const int kbase = half * 64;

            // ---- S = Q @ K^T over 64 keys (dual-digit int8) ----
            float s[8][4];
            #pragma unroll
            for (int nt2 = 0; nt2 < 4; ++nt2) {
                int a1[2][4] = { {0,0,0,0}, {0,0,0,0} };
                int a2[2][4] = { {0,0,0,0}, {0,0,0,0} };
                #pragma unroll
                for (int g = 0; g < 2; ++g) {
                    const uint32_t addr = (uint32_t)(kbase + nt2 * 16 + b_off) * AK_ROWB + g * 32 + kb_off;
                    uint32_t fb1[4], fb2[4];
                    ldsm_x4(fb1, k1b + addr);
                    ldsm_x4(fb2, k2b + addr);
                    #pragma unroll
                    for (int hf = 0; hf < 2; ++hf) {
                        mma_s8(a1[hf], q1f[g], fb1 + hf * 2);
                        mma_s8(a2[hf], q1f[g], fb2 + hf * 2);
                        mma_s8(a2[hf], q2f[g], fb1 + hf * 2);
                    }
                }
                #pragma unroll
                for (int hf = 0; hf < 2; ++hf) {
                    const float2 sk2 = *(const float2*)(sks + (kbase + (nt2 * 2 + hf) * 8) + kc);
                    s[nt2 * 2 + hf][0] = (float)(a1[hf][0] * 254 + a2[hf][0]) * (sq0f * sk2.x);
                    s[nt2 * 2 + hf][1] = (float)(a1[hf][1] * 254 + a2[hf][1]) * (sq0f * sk2.y);
                    s[nt2 * 2 + hf][2] = (float)(a1[hf][2] * 254 + a2[hf][2]) * (sq1f * sk2.x);
                    s[nt2 * 2 + hf][3] = (float)(a1[hf][3] * 254 + a2[hf][3]) * (sq1f * sk2.y);
                }
            }

            // causal mask on diagonal tile
            if (kt == qt) {
                #pragma unroll
                for (int nt = 0; nt < 8; ++nt) {
                    #pragma unroll
                    for (int c = 0; c < 4; ++c) {
                        const int key = kbase + nt * 8 + kc + (c & 1);
                        const int qq  = w * 16 + r + (c >> 1) * 8;
                        if (key > qq) s[nt][c] = -1e30f;
                    }
                }
            }

            // ---- online softmax (base-2), conditional rescale ----
            float mx0 = -1e30f, mx1 = -1e30f;
            #pragma unroll
            for (int nt = 0; nt < 8; ++nt) {
                mx0 = fmaxf(mx0, fmaxf(s[nt][0], s[nt][1]));
                mx1 = fmaxf(mx1, fmaxf(s[nt][2], s[nt][3]));
            }
            mx0 = fmaxf(mx0, __shfl_xor_sync(0xffffffffu, mx0, 1));
            mx0 = fmaxf(mx0, __shfl_xor_sync(0xffffffffu, mx0, 2));
            mx1 = fmaxf(mx1, __shfl_xor_sync(0xffffffffu, mx1, 1));
            mx1 = fmaxf(mx1, __shfl_xor_sync(0xffffffffu, mx1, 2));

            const bool upd = (mx0 > m_[0]) || (mx1 > m_[1]);
            if (__any_sync(0xffffffffu, upd)) {
                const float nm0 = fmaxf(m_[0], mx0), nm1 = fmaxf(m_[1], mx1);
                const float al0 = ex2f(m_[0] - nm0), al1 = ex2f(m_[1] - nm1);
                l_[0] *= al0;  l_[1] *= al1;
                m_[0] = nm0;   m_[1] = nm1;
                #pragma unroll
                for (int dt = 0; dt < 8; ++dt) {
                    oacc[dt][0] *= al0; oacc[dt][1] *= al0;
                    oacc[dt][2] *= al1; oacc[dt][3] *= al1;
                }
            }

            float rs0 = 0.f, rs1 = 0.f;
            #pragma unroll
            for (int nt = 0; nt < 8; ++nt) {
                s[nt][0] = ex2f(s[nt][0] - m_[0]);
                s[nt][1] = ex2f(s[nt][1] - m_[0]);
                s[nt][2] = ex2f(s[nt][2] - m_[1]);
                s[nt][3] = ex2f(s[nt][3] - m_[1]);
                rs0 += s[nt][0] + s[nt][1];
                rs1 += s[nt][2] + s[nt][3];
            }
            rs0 += __shfl_xor_sync(0xffffffffu, rs0, 1);
            rs0 += __shfl_xor_sync(0xffffffffu, rs0, 2);
            rs1 += __shfl_xor_sync(0xffffffffu, rs1, 1);
            rs1 += __shfl_xor_sync(0xffffffffu, rs1, 2);
            l_[0] += rs0;
            l_[1] += rs1;

            // ---- O += P @ V over 64 keys ----
            #pragma unroll
            for (int j = 0; j < 4; ++j) {
                uint32_t pa[4];
                pa[0] = h2u(s[2*j][0],   s[2*j][1]);
                pa[1] = h2u(s[2*j][2],   s[2*j][3]);
                pa[2] = h2u(s[2*j+1][0], s[2*j+1][1]);
                pa[3] = h2u(s[2*j+1][2], s[2*j+1][3]);

                const uint32_t abase = (kbase + j * 16 + vrow) * AV_ROWB + vcol * 2;
                #pragma unroll
                for (int dg = 0; dg < 4; ++dg) {
                    uint32_t bv[4];
                    ldsm_x4_t(bv, v_b + abase + dg * 32);
                    mma_f16(oacc[dg * 2 + 0], pa, bv + 0);
                    mma_f16(oacc[dg * 2 + 1], pa, bv + 2);
                }
            }
        }
        __syncthreads();
    }

    // epilogue: normalize, write fp32 ctx
    const float inv0 = 1.f / l_[0], inv1 = 1.f / l_[1];
    #pragma unroll
    for (int dt = 0; dt < 8; ++dt) {
        const size_t d = (size_t)hoff + dt * 8 + kc;
        const size_t rowA = (size_t)(q0w + r) * DMODEL + d;
        const size_t rowB = (size_t)(q0w + r + 8) * DMODEL + d;
        float2 a0 = { oacc[dt][0] * inv0, oacc[dt][1] * inv0 };
        float2 a1 = { oacc[dt][2] * inv1, oacc[dt][3] * inv1 };
        *(float2*)(g_ctx + rowA) = a0;
        *(float2*)(g_ctx + rowB) = a1;
    }
}

// ======================= host launcher =======================
extern "C" void kernel_launch(void* const* d_in, const int* in_sizes, int n_in,
                              void* d_out, int out_size)
{
    (void)in_sizes; (void)n_in; (void)out_size;
    const float* x  = (const float*)d_in[0];
    const float* Wq = (const float*)d_in[2];
    const float* bq = (const float*)d_in[3];
    const float* Wk = (const float*)d_in[4];
    const float* bk = (const float*)d_in[5];
    const float* Wv = (const float*)d_in[6];
    const float* bv = (const float*)d_in[7];
    const float* Wo = (const float*)d_in[8];
    const float* bo = (const float*)d_in[9];
    float* out = (float*)d_out;

    int8_t *x1, *x2, *c1, *c2;
    float *sx, *sc, *ctx;
    cudaGetSymbolAddress((void**)&x1, g_x1);
    cudaGetSymbolAddress((void**)&x2, g_x2);
    cudaGetSymbolAddress((void**)&sx, g_sx);
    cudaGetSymbolAddress((void**)&c1, g_c1);
    cudaGetSymbolAddress((void**)&c2, g_c2);
    cudaGetSymbolAddress((void**)&sc, g_sc);
    cudaGetSymbolAddress((void**)&ctx, g_ctx);

    cudaFuncSetAttribute(gemm_qkv_kernel,
                         cudaFuncAttributeMaxDynamicSharedMemorySize, QGEMM_SMEM);
    cudaFuncSetAttribute(gemm_o_kernel,
                         cudaFuncAttributeMaxDynamicSharedMemorySize, QGEMM_SMEM);
    cudaFuncSetAttribute(attn_kernel,
                         cudaFuncAttributeMaxDynamicSharedMemorySize, ATT_SMEM);

    // 1: weight column max (parallel, no atomics)
    colmax4_kernel<<<dim3(8, 4), 1024>>>(Wq, Wk, Wv, Wo);
    // 2: weight transpose + quant
    transpose_quant4_kernel<<<dim3(32, 32, 4), 256>>>(Wq, Wk, Wv, Wo);
    // 3: input row-quant
    rowquant_kernel<<<S_LEN, 256>>>(x, x1, x2, sx);
    // 4: fused Q/K/V projections  (profiled slot)
    gemm_qkv_kernel<<<dim3(8, 32, 3), 256, QGEMM_SMEM>>>(bq, bk, bv);
    // 5: attention
    attn_kernel<<<dim3(S_LEN / 128, NHEADS), 256, ATT_SMEM>>>();
    // 6: ctx row-quant
    rowquant_kernel<<<S_LEN, 256>>>(ctx, c1, c2, sc);
    // 7: O projection
    gemm_o_kernel<<<dim3(8, 32), 256, QGEMM_SMEM>>>(bo, out);
}